// round 2
// baseline (speedup 1.0000x reference)
#include <cuda_runtime.h>
#include <math.h>

#define S_LEN  2048
#define B_SZ   4
#define F_DIM  512
#define NHEAD  8
#define NB     32     // B*H
#define HD     64
#define M_ROWS 8192   // S*B

typedef unsigned long long ull;

// scratch (static __device__ arrays: no allocation allowed)
__device__ float g_Q[(size_t)NB * S_LEN * HD];
__device__ float g_K[(size_t)NB * S_LEN * HD];
__device__ float g_V[(size_t)NB * S_LEN * HD];
__device__ float g_Y[(size_t)M_ROWS * F_DIM];
__device__ float g_cos[S_LEN * (HD / 2)];
__device__ float g_sin[S_LEN * (HD / 2)];

// ---------------------------------------------------------------------------
// packed f32x2 helpers (FFMA2 path: 2x fp32 MAC per issue, bit-exact fp32)
// ---------------------------------------------------------------------------
__device__ __forceinline__ void fma2(ull &d, ull a, ull b) {
    asm("fma.rn.f32x2 %0, %1, %2, %3;" : "=l"(d) : "l"(a), "l"(b), "l"(d));
}
__device__ __forceinline__ ull mul2(ull a, ull b) {
    ull d; asm("mul.rn.f32x2 %0, %1, %2;" : "=l"(d) : "l"(a), "l"(b)); return d;
}
__device__ __forceinline__ ull f2u(float lo, float hi) {
    ull u; asm("mov.b64 %0, {%1,%2};" : "=l"(u) : "f"(lo), "f"(hi)); return u;
}
__device__ __forceinline__ float2 u2f(ull u) {
    float2 r; asm("mov.b64 {%0,%1}, %2;" : "=f"(r.x), "=f"(r.y) : "l"(u)); return r;
}

// ---------------------------------------------------------------------------
// RoPE table: double-precision angle generation (s up to 2047 rad)
// ---------------------------------------------------------------------------
__global__ void rope_table_kernel() {
    int idx = blockIdx.x * blockDim.x + threadIdx.x;
    if (idx >= S_LEN * (HD / 2)) return;
    int s = idx >> 5;
    int j = idx & 31;
    double theta = pow(10000.0, -(double)j / 32.0);
    double ang = (double)s * theta;
    g_cos[idx] = (float)cos(ang);
    g_sin[idx] = (float)sin(ang);
}

// ---------------------------------------------------------------------------
// Projection GEMM (FFMA2): C[m,n] = relu(sum_k A[m,k]*W[n,k] + bias[n])
// BM=128, BN=128, BK=16, 256 threads, 8x8 micro-tile, acc pairs along n.
// A stored duplicated in smem ((a,a) pairs); W transposed (natural n-pairs).
// MODE 0: flat out; MODE 1: head layout; MODE 2: head layout + RoPE
// ---------------------------------------------------------------------------
#define APROW 260   // 2*128 + 4
#define WPROW 132   // 128 + 4

template <int MODE>
__global__ __launch_bounds__(256, 2) void proj_kernel(
    const float* __restrict__ A, const float* __restrict__ W,
    const float* __restrict__ bias, float* __restrict__ out)
{
    __shared__ float AsD[16 * APROW];
    __shared__ float WsT[16 * WPROW];

    int tid = threadIdx.x;
    int tx = tid & 15, ty = tid >> 4;
    int m0 = blockIdx.y * 128, n0 = blockIdx.x * 128;

    ull acc[8][4];
#pragma unroll
    for (int i = 0; i < 8; i++)
#pragma unroll
        for (int j = 0; j < 4; j++) acc[i][j] = 0ull;

    int lm = tid & 127;
    int kc = (tid >> 7) * 8;
    const float* Ap = A + (size_t)(m0 + lm) * F_DIM + kc;
    const float* Wp = W + (size_t)(n0 + lm) * F_DIM + kc;

    for (int k0 = 0; k0 < F_DIM; k0 += 16) {
        float4 a0 = *(const float4*)(Ap + k0);
        float4 a1 = *(const float4*)(Ap + k0 + 4);
        float4 w0 = *(const float4*)(Wp + k0);
        float4 w1 = *(const float4*)(Wp + k0 + 4);
        float av[8] = {a0.x, a0.y, a0.z, a0.w, a1.x, a1.y, a1.z, a1.w};
        float wv[8] = {w0.x, w0.y, w0.z, w0.w, w1.x, w1.y, w1.z, w1.w};
#pragma unroll
        for (int i = 0; i < 8; i++) {
            *(ull*)&AsD[(kc + i) * APROW + 2 * lm] = f2u(av[i], av[i]);
            WsT[(kc + i) * WPROW + lm] = wv[i];
        }
        __syncthreads();

#pragma unroll
        for (int k = 0; k < 16; k++) {
            const float* ar = &AsD[k * APROW];
            const float* br = &WsT[k * WPROW];
            ulonglong2 A0 = *(const ulonglong2*)(ar + 8 * ty);
            ulonglong2 A1 = *(const ulonglong2*)(ar + 8 * ty + 4);
            ulonglong2 A2 = *(const ulonglong2*)(ar + 128 + 8 * ty);
            ulonglong2 A3 = *(const ulonglong2*)(ar + 128 + 8 * ty + 4);
            ulonglong2 B0 = *(const ulonglong2*)(br + 4 * tx);
            ulonglong2 B1 = *(const ulonglong2*)(br + 64 + 4 * tx);
            ull ad[8] = {A0.x, A0.y, A1.x, A1.y, A2.x, A2.y, A3.x, A3.y};
            ull bp[4] = {B0.x, B0.y, B1.x, B1.y};
#pragma unroll
            for (int i = 0; i < 8; i++)
#pragma unroll
                for (int j = 0; j < 4; j++)
                    fma2(acc[i][j], ad[i], bp[j]);
        }
        __syncthreads();
    }

    // epilogue
    float4 bs0 = *(const float4*)&bias[n0 + tx * 4];
    float4 bs1 = *(const float4*)&bias[n0 + 64 + tx * 4];
    int d0 = tx * 4;           // (n & 63) — same for both chunks
    int h0 = (n0 + tx * 4) >> 6;

#pragma unroll
    for (int i = 0; i < 8; i++) {
        int m = m0 + (i < 4 ? ty * 4 + i : 64 + ty * 4 + (i - 4));
        int s = m >> 2, b = m & 3;
        float2 c0 = u2f(acc[i][0]), c1 = u2f(acc[i][1]);
        float2 c2 = u2f(acc[i][2]), c3 = u2f(acc[i][3]);
        float v[8];
        v[0] = fmaxf(c0.x + bs0.x, 0.f); v[1] = fmaxf(c0.y + bs0.y, 0.f);
        v[2] = fmaxf(c1.x + bs0.z, 0.f); v[3] = fmaxf(c1.y + bs0.w, 0.f);
        v[4] = fmaxf(c2.x + bs1.x, 0.f); v[5] = fmaxf(c2.y + bs1.y, 0.f);
        v[6] = fmaxf(c3.x + bs1.z, 0.f); v[7] = fmaxf(c3.y + bs1.w, 0.f);

        if (MODE == 2) {
            int p = (s << 5) + (d0 >> 1);
            float cc0 = g_cos[p],     ss0 = g_sin[p];
            float cc1 = g_cos[p + 1], ss1 = g_sin[p + 1];
            float e, o;
            e = v[0]*cc0 - v[1]*ss0; o = v[0]*ss0 + v[1]*cc0; v[0]=e; v[1]=o;
            e = v[2]*cc1 - v[3]*ss1; o = v[2]*ss1 + v[3]*cc1; v[2]=e; v[3]=o;
            e = v[4]*cc0 - v[5]*ss0; o = v[4]*ss0 + v[5]*cc0; v[4]=e; v[5]=o;
            e = v[6]*cc1 - v[7]*ss1; o = v[6]*ss1 + v[7]*cc1; v[6]=e; v[7]=o;
        }

        float4 r0 = make_float4(v[0], v[1], v[2], v[3]);
        float4 r1 = make_float4(v[4], v[5], v[6], v[7]);
        if (MODE == 0) {
            *(float4*)&out[(size_t)m * F_DIM + n0 + tx * 4] = r0;
            *(float4*)&out[(size_t)m * F_DIM + n0 + 64 + tx * 4] = r1;
        } else {
            *(float4*)&out[(((size_t)b * NHEAD + h0) * S_LEN + s) * HD + d0] = r0;
            *(float4*)&out[(((size_t)b * NHEAD + h0 + 1) * S_LEN + s) * HD + d0] = r1;
        }
    }
}

// ---------------------------------------------------------------------------
// Flash attention (FFMA2): BLOCK_M=256, BLOCK_N=64, D=64, 512 threads.
// Micro-tile 8m x 4n (QK) / 8m x 4d (PV); acc pairs along m.
// K,V stored duplicated in smem; P staged m-major (natural m-pairs).
// ---------------------------------------------------------------------------
#define QROW 260   // 256 + 4
#define KROW 128   // 2*64
#define VROW 132   // 2*64 + 4
#define PROW 260   // 256 + 4
#define FL_SMEM_FLOATS (64 * QROW + 64 * KROW + 64 * VROW + 64 * PROW)

__global__ __launch_bounds__(512, 1) void flash_kernel() {
    extern __shared__ float sm[];
    float* Qs = sm;                                      // [d][m] scaled
    float* Ks = sm + 64 * QROW;                          // [d][2n] dup
    float* Vs = sm + 64 * QROW + 64 * KROW;              // [n][2d] dup
    float* Ps = sm + 64 * QROW + 64 * KROW + 64 * VROW;  // [n][m]

    int tid = threadIdx.x;
    int tx = tid & 15, ty = tid >> 4;   // ty 0..31
    int q0 = blockIdx.x * 256;
    size_t hoff = (size_t)blockIdx.y * S_LEN * HD;
    const float* Qh = g_Q + hoff;
    const float* Kh = g_K + hoff;
    const float* Vh = g_V + hoff;

    // load Q tile (256 x 64) transposed + scaled
    {
        int m = tid & 255;
        int dc = (tid >> 8) * 32;
        const float* src = Qh + (size_t)(q0 + m) * HD + dc;
#pragma unroll
        for (int c = 0; c < 8; c++) {
            float4 v = *(const float4*)(src + c * 4);
            int d = dc + c * 4;
            Qs[(d + 0) * QROW + m] = v.x * 0.125f;
            Qs[(d + 1) * QROW + m] = v.y * 0.125f;
            Qs[(d + 2) * QROW + m] = v.z * 0.125f;
            Qs[(d + 3) * QROW + m] = v.w * 0.125f;
        }
    }

    float m_i[8], l_i[8];
    ull o2[4][4];
#pragma unroll
    for (int r = 0; r < 8; r++) { m_i[r] = -3.0e38f; l_i[r] = 0.f; }
#pragma unroll
    for (int i = 0; i < 4; i++)
#pragma unroll
        for (int j = 0; j < 4; j++) o2[i][j] = 0ull;

    int ldn = tid & 63;
    int ldd = (tid >> 6) * 8;

    for (int kt = 0; kt < S_LEN / 64; kt++) {
        __syncthreads();
        // load K,V tiles duplicated
        {
            const float* ks = Kh + (size_t)(kt * 64 + ldn) * HD + ldd;
            const float* vs = Vh + (size_t)(kt * 64 + ldn) * HD + ldd;
            float4 k0 = *(const float4*)(ks), k1 = *(const float4*)(ks + 4);
            float4 v0 = *(const float4*)(vs), v1 = *(const float4*)(vs + 4);
            float kv[8] = {k0.x, k0.y, k0.z, k0.w, k1.x, k1.y, k1.z, k1.w};
            float vv[8] = {v0.x, v0.y, v0.z, v0.w, v1.x, v1.y, v1.z, v1.w};
#pragma unroll
            for (int e = 0; e < 8; e++) {
                *(ull*)&Ks[(ldd + e) * KROW + 2 * ldn] = f2u(kv[e], kv[e]);
                *(ull*)&Vs[ldn * VROW + 2 * (ldd + e)] = f2u(vv[e], vv[e]);
            }
        }
        __syncthreads();

        // S = (Q/8) K^T  — pairs along m, K duplicated along n
        ull sacc[4][4];
#pragma unroll
        for (int i = 0; i < 4; i++)
#pragma unroll
            for (int j = 0; j < 4; j++) sacc[i][j] = 0ull;

#pragma unroll 8
        for (int d = 0; d < 64; d++) {
            const float* qr = &Qs[d * QROW];
            const float* kr = &Ks[d * KROW];
            ulonglong2 qa = *(const ulonglong2*)(qr + 4 * ty);
            ulonglong2 qb = *(const ulonglong2*)(qr + 128 + 4 * ty);
            ulonglong2 ka = *(const ulonglong2*)(kr + 4 * tx);
            ulonglong2 kb = *(const ulonglong2*)(kr + 64 + 4 * tx);
            ull qp[4] = {qa.x, qa.y, qb.x, qb.y};
            ull kd[4] = {ka.x, ka.y, kb.x, kb.y};
#pragma unroll
            for (int i = 0; i < 4; i++)
#pragma unroll
                for (int j = 0; j < 4; j++)
                    fma2(sacc[i][j], qp[i], kd[j]);
        }

        // online softmax; rows r=0..7 -> m = (r<4 ? ty*4+r : 128+ty*4+r-4)
        float alphas[8];
#pragma unroll
        for (int r = 0; r < 8; r++) {
            int mp = r >> 1;
            float sv[4];
#pragma unroll
            for (int j = 0; j < 4; j++) {
                float2 t = u2f(sacc[mp][j]);
                sv[j] = (r & 1) ? t.y : t.x;
            }
            float rmax = fmaxf(fmaxf(sv[0], sv[1]), fmaxf(sv[2], sv[3]));
#pragma unroll
            for (int off = 8; off >= 1; off >>= 1)
                rmax = fmaxf(rmax, __shfl_xor_sync(0xffffffffu, rmax, off));
            float mnew = fmaxf(m_i[r], rmax);
            alphas[r] = __expf(m_i[r] - mnew);
            float p0 = __expf(sv[0] - mnew);
            float p1 = __expf(sv[1] - mnew);
            float p2 = __expf(sv[2] - mnew);
            float p3 = __expf(sv[3] - mnew);
            float rsum = (p0 + p1) + (p2 + p3);
#pragma unroll
            for (int off = 8; off >= 1; off >>= 1)
                rsum += __shfl_xor_sync(0xffffffffu, rsum, off);
            l_i[r] = l_i[r] * alphas[r] + rsum;
            m_i[r] = mnew;
            // store P row-scalar into Ps[n][m]
            int mloc = (r < 4) ? ty * 4 + r : 128 + ty * 4 + (r - 4);
            Ps[(2 * tx) * PROW + mloc] = p0;
            Ps[(2 * tx + 1) * PROW + mloc] = p1;
            Ps[(32 + 2 * tx) * PROW + mloc] = p2;
            Ps[(33 + 2 * tx) * PROW + mloc] = p3;
        }
        // rescale O by alpha (pairs along m)
#pragma unroll
        for (int mp = 0; mp < 4; mp++) {
            ull al2 = f2u(alphas[2 * mp], alphas[2 * mp + 1]);
#pragma unroll
            for (int j = 0; j < 4; j++) o2[mp][j] = mul2(o2[mp][j], al2);
        }
        __syncthreads();

        // O += P @ V  — pairs along m, V duplicated along d
#pragma unroll 8
        for (int n = 0; n < 64; n++) {
            const float* pr = &Ps[n * PROW];
            const float* vr = &Vs[n * VROW];
            ulonglong2 pa = *(const ulonglong2*)(pr + 4 * ty);
            ulonglong2 pb = *(const ulonglong2*)(pr + 128 + 4 * ty);
            ulonglong2 va = *(const ulonglong2*)(vr + 4 * tx);
            ulonglong2 vb = *(const ulonglong2*)(vr + 64 + 4 * tx);
            ull pp[4] = {pa.x, pa.y, pb.x, pb.y};
            ull vd[4] = {va.x, va.y, vb.x, vb.y};
#pragma unroll
            for (int i = 0; i < 4; i++)
#pragma unroll
                for (int j = 0; j < 4; j++)
                    fma2(o2[i][j], pp[i], vd[j]);
        }
    }

    // epilogue: normalize + write (s, b, f) layout
    int bb = blockIdx.y >> 3;
    int hh = blockIdx.y & 7;
#pragma unroll
    for (int r = 0; r < 8; r++) {
        int mp = r >> 1;
        float inv = 1.0f / l_i[r];
        float val[4];
#pragma unroll
        for (int j = 0; j < 4; j++) {
            float2 t = u2f(o2[mp][j]);
            val[j] = ((r & 1) ? t.y : t.x) * inv;
        }
        int srow = q0 + ((r < 4) ? ty * 4 + r : 128 + ty * 4 + (r - 4));
        float* dst = &g_Y[((size_t)srow * B_SZ + bb) * F_DIM + hh * HD];
        *(float2*)&dst[2 * tx] = make_float2(val[0], val[1]);
        *(float2*)&dst[32 + 2 * tx] = make_float2(val[2], val[3]);
    }
}

// ---------------------------------------------------------------------------
// launch
// ---------------------------------------------------------------------------
extern "C" void kernel_launch(void* const* d_in, const int* in_sizes, int n_in,
                              void* d_out, int out_size) {
    const float* q  = (const float*)d_in[0];
    const float* k  = (const float*)d_in[1];
    const float* v  = (const float*)d_in[2];
    const float* Wq = (const float*)d_in[3];
    const float* bq = (const float*)d_in[4];
    const float* Wk = (const float*)d_in[5];
    const float* bk = (const float*)d_in[6];
    const float* Wv = (const float*)d_in[7];
    const float* bv = (const float*)d_in[8];
    const float* Wo = (const float*)d_in[9];
    const float* bo = (const float*)d_in[10];
    float* out = (float*)d_out;

    float *pQ, *pK, *pV, *pY;
    cudaGetSymbolAddress((void**)&pQ, g_Q);
    cudaGetSymbolAddress((void**)&pK, g_K);
    cudaGetSymbolAddress((void**)&pV, g_V);
    cudaGetSymbolAddress((void**)&pY, g_Y);

    const int FLASH_SMEM = FL_SMEM_FLOATS * sizeof(float);  // 199680 B
    cudaFuncSetAttribute(flash_kernel,
                         cudaFuncAttributeMaxDynamicSharedMemorySize, FLASH_SMEM);

    rope_table_kernel<<<256, 256>>>();

    dim3 pg(F_DIM / 128, M_ROWS / 128);  // (4, 64)
    proj_kernel<2><<<pg, 256>>>(q, Wq, bq, pQ);
    proj_kernel<2><<<pg, 256>>>(k, Wk, bk, pK);
    proj_kernel<1><<<pg, 256>>>(v, Wv, bv, pV);

    flash_kernel<<<dim3(S_LEN / 256, NB), 512, FLASH_SMEM>>>();

    proj_kernel<0><<<pg, 256>>>(pY, Wo, bo, out);
}

// round 3
// speedup vs baseline: 1.0553x; 1.0553x over previous
#include <cuda_runtime.h>
#include <math.h>

#define S_LEN  2048
#define B_SZ   4
#define F_DIM  512
#define NHEAD  8
#define NB     32     // B*H
#define HD     64
#define M_ROWS 8192   // S*B

typedef unsigned long long ull;

// scratch (static __device__ arrays: no allocation allowed)
__device__ float g_Q[(size_t)NB * S_LEN * HD];
__device__ float g_K[(size_t)NB * S_LEN * HD];
__device__ float g_V[(size_t)NB * S_LEN * HD];
__device__ float g_Y[(size_t)M_ROWS * F_DIM];
__device__ float g_cos[S_LEN * (HD / 2)];
__device__ float g_sin[S_LEN * (HD / 2)];

// ---------------------------------------------------------------------------
// packed f32x2 helpers (FFMA2 path: 2x fp32 MAC per issue, bit-exact fp32)
// ---------------------------------------------------------------------------
__device__ __forceinline__ void fma2(ull &d, ull a, ull b) {
    asm("fma.rn.f32x2 %0, %1, %2, %3;" : "=l"(d) : "l"(a), "l"(b), "l"(d));
}
__device__ __forceinline__ ull mul2(ull a, ull b) {
    ull d; asm("mul.rn.f32x2 %0, %1, %2;" : "=l"(d) : "l"(a), "l"(b)); return d;
}
__device__ __forceinline__ ull f2u(float lo, float hi) {
    ull u; asm("mov.b64 %0, {%1,%2};" : "=l"(u) : "f"(lo), "f"(hi)); return u;
}
__device__ __forceinline__ float2 u2f(ull u) {
    float2 r; asm("mov.b64 {%0,%1}, %2;" : "=f"(r.x), "=f"(r.y) : "l"(u)); return r;
}

// ---------------------------------------------------------------------------
// RoPE table: double-precision angle generation (s up to 2047 rad)
// ---------------------------------------------------------------------------
__global__ void rope_table_kernel() {
    int idx = blockIdx.x * blockDim.x + threadIdx.x;
    if (idx >= S_LEN * (HD / 2)) return;
    int s = idx >> 5;
    int j = idx & 31;
    double theta = pow(10000.0, -(double)j / 32.0);
    double ang = (double)s * theta;
    g_cos[idx] = (float)cos(ang);
    g_sin[idx] = (float)sin(ang);
}

// ---------------------------------------------------------------------------
// Projection GEMM (FFMA2): C[m,n] = relu(sum_k A[m,k]*W[n,k] + bias[n])
// BM=128, BN=128, BK=16, 256 threads, 8x8 micro-tile, acc pairs along n.
// A stored duplicated in smem ((a,a) pairs); W transposed (natural n-pairs).
// MODE 0: flat out; MODE 1: head layout; MODE 2: head layout + RoPE
// ---------------------------------------------------------------------------
#define APROW 260   // 2*128 + 4
#define WPROW 132   // 128 + 4

template <int MODE>
__global__ __launch_bounds__(256, 2) void proj_kernel(
    const float* __restrict__ A, const float* __restrict__ W,
    const float* __restrict__ bias, float* __restrict__ out)
{
    __shared__ float AsD[16 * APROW];
    __shared__ float WsT[16 * WPROW];

    int tid = threadIdx.x;
    int tx = tid & 15, ty = tid >> 4;
    int m0 = blockIdx.y * 128, n0 = blockIdx.x * 128;

    ull acc[8][4];
#pragma unroll
    for (int i = 0; i < 8; i++)
#pragma unroll
        for (int j = 0; j < 4; j++) acc[i][j] = 0ull;

    int lm = tid & 127;
    int kc = (tid >> 7) * 8;
    const float* Ap = A + (size_t)(m0 + lm) * F_DIM + kc;
    const float* Wp = W + (size_t)(n0 + lm) * F_DIM + kc;

    for (int k0 = 0; k0 < F_DIM; k0 += 16) {
        float4 a0 = *(const float4*)(Ap + k0);
        float4 a1 = *(const float4*)(Ap + k0 + 4);
        float4 w0 = *(const float4*)(Wp + k0);
        float4 w1 = *(const float4*)(Wp + k0 + 4);
        float av[8] = {a0.x, a0.y, a0.z, a0.w, a1.x, a1.y, a1.z, a1.w};
        float wv[8] = {w0.x, w0.y, w0.z, w0.w, w1.x, w1.y, w1.z, w1.w};
#pragma unroll
        for (int i = 0; i < 8; i++) {
            *(ull*)&AsD[(kc + i) * APROW + 2 * lm] = f2u(av[i], av[i]);
            WsT[(kc + i) * WPROW + lm] = wv[i];
        }
        __syncthreads();

#pragma unroll
        for (int k = 0; k < 16; k++) {
            const float* ar = &AsD[k * APROW];
            const float* br = &WsT[k * WPROW];
            ulonglong2 A0 = *(const ulonglong2*)(ar + 8 * ty);
            ulonglong2 A1 = *(const ulonglong2*)(ar + 8 * ty + 4);
            ulonglong2 A2 = *(const ulonglong2*)(ar + 128 + 8 * ty);
            ulonglong2 A3 = *(const ulonglong2*)(ar + 128 + 8 * ty + 4);
            ulonglong2 B0 = *(const ulonglong2*)(br + 4 * tx);
            ulonglong2 B1 = *(const ulonglong2*)(br + 64 + 4 * tx);
            ull ad[8] = {A0.x, A0.y, A1.x, A1.y, A2.x, A2.y, A3.x, A3.y};
            ull bp[4] = {B0.x, B0.y, B1.x, B1.y};
#pragma unroll
            for (int i = 0; i < 8; i++)
#pragma unroll
                for (int j = 0; j < 4; j++)
                    fma2(acc[i][j], ad[i], bp[j]);
        }
        __syncthreads();
    }

    // epilogue
    float4 bs0 = *(const float4*)&bias[n0 + tx * 4];
    float4 bs1 = *(const float4*)&bias[n0 + 64 + tx * 4];
    int d0 = tx * 4;           // (n & 63) — same for both chunks
    int h0 = (n0 + tx * 4) >> 6;

#pragma unroll
    for (int i = 0; i < 8; i++) {
        int m = m0 + (i < 4 ? ty * 4 + i : 64 + ty * 4 + (i - 4));
        int s = m >> 2, b = m & 3;
        float2 c0 = u2f(acc[i][0]), c1 = u2f(acc[i][1]);
        float2 c2 = u2f(acc[i][2]), c3 = u2f(acc[i][3]);
        float v[8];
        v[0] = fmaxf(c0.x + bs0.x, 0.f); v[1] = fmaxf(c0.y + bs0.y, 0.f);
        v[2] = fmaxf(c1.x + bs0.z, 0.f); v[3] = fmaxf(c1.y + bs0.w, 0.f);
        v[4] = fmaxf(c2.x + bs1.x, 0.f); v[5] = fmaxf(c2.y + bs1.y, 0.f);
        v[6] = fmaxf(c3.x + bs1.z, 0.f); v[7] = fmaxf(c3.y + bs1.w, 0.f);

        if (MODE == 2) {
            int p = (s << 5) + (d0 >> 1);
            float cc0 = g_cos[p],     ss0 = g_sin[p];
            float cc1 = g_cos[p + 1], ss1 = g_sin[p + 1];
            float e, o;
            e = v[0]*cc0 - v[1]*ss0; o = v[0]*ss0 + v[1]*cc0; v[0]=e; v[1]=o;
            e = v[2]*cc1 - v[3]*ss1; o = v[2]*ss1 + v[3]*cc1; v[2]=e; v[3]=o;
            e = v[4]*cc0 - v[5]*ss0; o = v[4]*ss0 + v[5]*cc0; v[4]=e; v[5]=o;
            e = v[6]*cc1 - v[7]*ss1; o = v[6]*ss1 + v[7]*cc1; v[6]=e; v[7]=o;
        }

        float4 r0 = make_float4(v[0], v[1], v[2], v[3]);
        float4 r1 = make_float4(v[4], v[5], v[6], v[7]);
        if (MODE == 0) {
            *(float4*)&out[(size_t)m * F_DIM + n0 + tx * 4] = r0;
            *(float4*)&out[(size_t)m * F_DIM + n0 + 64 + tx * 4] = r1;
        } else {
            *(float4*)&out[(((size_t)b * NHEAD + h0) * S_LEN + s) * HD + d0] = r0;
            *(float4*)&out[(((size_t)b * NHEAD + h0 + 1) * S_LEN + s) * HD + d0] = r1;
        }
    }
}

// ---------------------------------------------------------------------------
// Flash attention (FFMA2): BLOCK_M=256, BLOCK_N=64, D=64, 512 threads.
// Micro-tile 8m x 4n (QK) / 8m x 4d (PV); acc pairs along m.
// K,V stored duplicated in smem; P staged m-major (natural m-pairs).
// ---------------------------------------------------------------------------
#define QROW 260   // 256 + 4
#define KROW 128   // 2*64
#define VROW 132   // 2*64 + 4
#define PROW 260   // 256 + 4
#define FL_SMEM_FLOATS (64 * QROW + 64 * KROW + 64 * VROW + 64 * PROW)

__global__ __launch_bounds__(512, 1) void flash_kernel() {
    extern __shared__ float sm[];
    float* Qs = sm;                                      // [d][m] scaled
    float* Ks = sm + 64 * QROW;                          // [d][2n] dup
    float* Vs = sm + 64 * QROW + 64 * KROW;              // [n][2d] dup
    float* Ps = sm + 64 * QROW + 64 * KROW + 64 * VROW;  // [n][m]

    int tid = threadIdx.x;
    int tx = tid & 15, ty = tid >> 4;   // ty 0..31
    int q0 = blockIdx.x * 256;
    size_t hoff = (size_t)blockIdx.y * S_LEN * HD;
    const float* Qh = g_Q + hoff;
    const float* Kh = g_K + hoff;
    const float* Vh = g_V + hoff;

    // load Q tile (256 x 64) transposed + scaled
    {
        int m = tid & 255;
        int dc = (tid >> 8) * 32;
        const float* src = Qh + (size_t)(q0 + m) * HD + dc;
#pragma unroll
        for (int c = 0; c < 8; c++) {
            float4 v = *(const float4*)(src + c * 4);
            int d = dc + c * 4;
            Qs[(d + 0) * QROW + m] = v.x * 0.125f;
            Qs[(d + 1) * QROW + m] = v.y * 0.125f;
            Qs[(d + 2) * QROW + m] = v.z * 0.125f;
            Qs[(d + 3) * QROW + m] = v.w * 0.125f;
        }
    }

    float m_i[8], l_i[8];
    ull o2[4][4];
#pragma unroll
    for (int r = 0; r < 8; r++) { m_i[r] = -3.0e38f; l_i[r] = 0.f; }
#pragma unroll
    for (int i = 0; i < 4; i++)
#pragma unroll
        for (int j = 0; j < 4; j++) o2[i][j] = 0ull;

    int ldn = tid & 63;
    int ldd = (tid >> 6) * 8;

    for (int kt = 0; kt < S_LEN / 64; kt++) {
        __syncthreads();
        // load K,V tiles duplicated
        {
            const float* ks = Kh + (size_t)(kt * 64 + ldn) * HD + ldd;
            const float* vs = Vh + (size_t)(kt * 64 + ldn) * HD + ldd;
            float4 k0 = *(const float4*)(ks), k1 = *(const float4*)(ks + 4);
            float4 v0 = *(const float4*)(vs), v1 = *(const float4*)(vs + 4);
            float kv[8] = {k0.x, k0.y, k0.z, k0.w, k1.x, k1.y, k1.z, k1.w};
            float vv[8] = {v0.x, v0.y, v0.z, v0.w, v1.x, v1.y, v1.z, v1.w};
#pragma unroll
            for (int e = 0; e < 8; e++) {
                *(ull*)&Ks[(ldd + e) * KROW + 2 * ldn] = f2u(kv[e], kv[e]);
                *(ull*)&Vs[ldn * VROW + 2 * (ldd + e)] = f2u(vv[e], vv[e]);
            }
        }
        __syncthreads();

        // S = (Q/8) K^T  — pairs along m, K duplicated along n
        ull sacc[4][4];
#pragma unroll
        for (int i = 0; i < 4; i++)
#pragma unroll
            for (int j = 0; j < 4; j++) sacc[i][j] = 0ull;

#pragma unroll 8
        for (int d = 0; d < 64; d++) {
            const float* qr = &Qs[d * QROW];
            const float* kr = &Ks[d * KROW];
            ulonglong2 qa = *(const ulonglong2*)(qr + 4 * ty);
            ulonglong2 qb = *(const ulonglong2*)(qr + 128 + 4 * ty);
            ulonglong2 ka = *(const ulonglong2*)(kr + 4 * tx);
            ulonglong2 kb = *(const ulonglong2*)(kr + 64 + 4 * tx);
            ull qp[4] = {qa.x, qa.y, qb.x, qb.y};
            ull kd[4] = {ka.x, ka.y, kb.x, kb.y};
#pragma unroll
            for (int i = 0; i < 4; i++)
#pragma unroll
                for (int j = 0; j < 4; j++)
                    fma2(sacc[i][j], qp[i], kd[j]);
        }

        // online softmax; rows r=0..7 -> m = (r<4 ? ty*4+r : 128+ty*4+r-4)
        float alphas[8];
#pragma unroll
        for (int r = 0; r < 8; r++) {
            int mp = r >> 1;
            float sv[4];
#pragma unroll
            for (int j = 0; j < 4; j++) {
                float2 t = u2f(sacc[mp][j]);
                sv[j] = (r & 1) ? t.y : t.x;
            }
            float rmax = fmaxf(fmaxf(sv[0], sv[1]), fmaxf(sv[2], sv[3]));
#pragma unroll
            for (int off = 8; off >= 1; off >>= 1)
                rmax = fmaxf(rmax, __shfl_xor_sync(0xffffffffu, rmax, off));
            float mnew = fmaxf(m_i[r], rmax);
            alphas[r] = __expf(m_i[r] - mnew);
            float p0 = __expf(sv[0] - mnew);
            float p1 = __expf(sv[1] - mnew);
            float p2 = __expf(sv[2] - mnew);
            float p3 = __expf(sv[3] - mnew);
            float rsum = (p0 + p1) + (p2 + p3);
#pragma unroll
            for (int off = 8; off >= 1; off >>= 1)
                rsum += __shfl_xor_sync(0xffffffffu, rsum, off);
            l_i[r] = l_i[r] * alphas[r] + rsum;
            m_i[r] = mnew;
            // store P row-scalar into Ps[n][m]
            int mloc = (r < 4) ? ty * 4 + r : 128 + ty * 4 + (r - 4);
            Ps[(2 * tx) * PROW + mloc] = p0;
            Ps[(2 * tx + 1) * PROW + mloc] = p1;
            Ps[(32 + 2 * tx) * PROW + mloc] = p2;
            Ps[(33 + 2 * tx) * PROW + mloc] = p3;
        }
        // rescale O by alpha (pairs along m)
#pragma unroll
        for (int mp = 0; mp < 4; mp++) {
            ull al2 = f2u(alphas[2 * mp], alphas[2 * mp + 1]);
#pragma unroll
            for (int j = 0; j < 4; j++) o2[mp][j] = mul2(o2[mp][j], al2);
        }
        __syncthreads();

        // O += P @ V  — pairs along m, V duplicated along d
#pragma unroll 8
        for (int n = 0; n < 64; n++) {
            const float* pr = &Ps[n * PROW];
            const float* vr = &Vs[n * VROW];
            ulonglong2 pa = *(const ulonglong2*)(pr + 4 * ty);
            ulonglong2 pb = *(const ulonglong2*)(pr + 128 + 4 * ty);
            ulonglong2 va = *(const ulonglong2*)(vr + 4 * tx);
            ulonglong2 vb = *(const ulonglong2*)(vr + 64 + 4 * tx);
            ull pp[4] = {pa.x, pa.y, pb.x, pb.y};
            ull vd[4] = {va.x, va.y, vb.x, vb.y};
#pragma unroll
            for (int i = 0; i < 4; i++)
#pragma unroll
                for (int j = 0; j < 4; j++)
                    fma2(o2[i][j], pp[i], vd[j]);
        }
    }

    // epilogue: normalize + write (s, b, f) layout
    int bb = blockIdx.y >> 3;
    int hh = blockIdx.y & 7;
#pragma unroll
    for (int r = 0; r < 8; r++) {
        int mp = r >> 1;
        float inv = 1.0f / l_i[r];
        float val[4];
#pragma unroll
        for (int j = 0; j < 4; j++) {
            float2 t = u2f(o2[mp][j]);
            val[j] = ((r & 1) ? t.y : t.x) * inv;
        }
        int srow = q0 + ((r < 4) ? ty * 4 + r : 128 + ty * 4 + (r - 4));
        float* dst = &g_Y[((size_t)srow * B_SZ + bb) * F_DIM + hh * HD];
        *(float2*)&dst[2 * tx] = make_float2(val[0], val[1]);
        *(float2*)&dst[32 + 2 * tx] = make_float2(val[2], val[3]);
    }
}

// ---------------------------------------------------------------------------
// launch
// ---------------------------------------------------------------------------
extern "C" void kernel_launch(void* const* d_in, const int* in_sizes, int n_in,
                              void* d_out, int out_size) {
    const float* q  = (const float*)d_in[0];
    const float* k  = (const float*)d_in[1];
    const float* v  = (const float*)d_in[2];
    const float* Wq = (const float*)d_in[3];
    const float* bq = (const float*)d_in[4];
    const float* Wk = (const float*)d_in[5];
    const float* bk = (const float*)d_in[6];
    const float* Wv = (const float*)d_in[7];
    const float* bv = (const float*)d_in[8];
    const float* Wo = (const float*)d_in[9];
    const float* bo = (const float*)d_in[10];
    float* out = (float*)d_out;

    float *pQ, *pK, *pV, *pY;
    cudaGetSymbolAddress((void**)&pQ, g_Q);
    cudaGetSymbolAddress((void**)&pK, g_K);
    cudaGetSymbolAddress((void**)&pV, g_V);
    cudaGetSymbolAddress((void**)&pY, g_Y);

    const int FLASH_SMEM = FL_SMEM_FLOATS * sizeof(float);  // 199680 B
    cudaFuncSetAttribute(flash_kernel,
                         cudaFuncAttributeMaxDynamicSharedMemorySize, FLASH_SMEM);

    rope_table_kernel<<<256, 256>>>();

    dim3 pg(F_DIM / 128, M_ROWS / 128);  // (4, 64)
    proj_kernel<2><<<pg, 256>>>(q, Wq, bq, pQ);
    proj_kernel<2><<<pg, 256>>>(k, Wk, bk, pK);
    proj_kernel<1><<<pg, 256>>>(v, Wv, bv, pV);

    flash_kernel<<<dim3(S_LEN / 256, NB), 512, FLASH_SMEM>>>();

    proj_kernel<0><<<pg, 256>>>(pY, Wo, bo, out);
}

// round 5
// speedup vs baseline: 1.1973x; 1.1345x over previous
#include <cuda_runtime.h>
#include <cstdint>
#include <math.h>

#define S_LEN  2048
#define B_SZ   4
#define F_DIM  512
#define NHEAD  8
#define NB     32
#define HD     64
#define M_ROWS 8192

__device__ float g_Q[(size_t)NB * S_LEN * HD];   // [bh][s][d]
__device__ float g_K[(size_t)NB * S_LEN * HD];   // [bh][s][d]
__device__ float g_V[(size_t)NB * S_LEN * HD];   // TRANSPOSED [bh][d][s]
__device__ float g_Y[(size_t)M_ROWS * F_DIM];
__device__ float g_cos[S_LEN * 32];
__device__ float g_sin[S_LEN * 32];

// ---------------- helpers ----------------
__device__ __forceinline__ uint32_t s2u(const void* p) {
    uint32_t a;
    asm("{ .reg .u64 t; cvta.to.shared.u64 t, %1; cvt.u32.u64 %0, t; }" : "=r"(a) : "l"(p));
    return a;
}
__device__ __forceinline__ uint16_t f2bf(float f) {
    uint16_t r; asm("cvt.rn.bf16.f32 %0, %1;" : "=h"(r) : "f"(f)); return r;
}
__device__ __forceinline__ float bf2f(uint16_t h) {
    return __uint_as_float(((uint32_t)h) << 16);
}
__device__ __forceinline__ void splitf(float a, uint16_t &h, uint16_t &l) {
    h = f2bf(a);
    l = f2bf(a - bf2f(h));
}

__device__ __forceinline__ void mma16816(float* d, const uint32_t* a, const uint32_t* b) {
    asm volatile(
        "mma.sync.aligned.m16n8k16.row.col.f32.bf16.bf16.f32 "
        "{%0,%1,%2,%3}, {%4,%5,%6,%7}, {%8,%9}, {%0,%1,%2,%3};"
        : "+f"(d[0]), "+f"(d[1]), "+f"(d[2]), "+f"(d[3])
        : "r"(a[0]), "r"(a[1]), "r"(a[2]), "r"(a[3]), "r"(b[0]), "r"(b[1]));
}
__device__ __forceinline__ void ldmx4(uint32_t* r, uint32_t a) {
    asm volatile("ldmatrix.sync.aligned.m8n8.x4.shared.b16 {%0,%1,%2,%3}, [%4];"
                 : "=r"(r[0]), "=r"(r[1]), "=r"(r[2]), "=r"(r[3]) : "r"(a));
}
__device__ __forceinline__ void ldmx2(uint32_t* r, uint32_t a) {
    asm volatile("ldmatrix.sync.aligned.m8n8.x2.shared.b16 {%0,%1}, [%2];"
                 : "=r"(r[0]), "=r"(r[1]) : "r"(a));
}
// A-frag ldmatrix address (m16k16 tile at (m0, k0), row-major, stride bytes)
__device__ __forceinline__ uint32_t addrA(uint32_t base, int stride, int m0, int k0, int lane) {
    int grp = lane >> 3, li = lane & 7;
    return base + (m0 + li + (grp & 1) * 8) * stride + (k0 + (grp >> 1) * 8) * 2;
}
// B-frag ldmatrix address (k16n8 tile, B stored [n][k] row-major)
__device__ __forceinline__ uint32_t addrB(uint32_t base, int stride, int n0, int k0, int lane) {
    int li = lane & 15;
    return base + (n0 + (li & 7)) * stride + (k0 + (li >> 3) * 8) * 2;
}
// triple-split writers: 8 floats -> 24 bf16 (48 bytes)
__device__ __forceinline__ void tripA8(const float* p, char* dst, float scale) {
    __align__(16) uint16_t t[24];
#pragma unroll
    for (int i = 0; i < 8; i++) {
        float a = p[i] * scale;
        uint16_t h, l; splitf(a, h, l);
        t[3*i] = h; t[3*i+1] = l; t[3*i+2] = h;
    }
    const uint4* u = (const uint4*)t;
    *(uint4*)(dst) = u[0]; *(uint4*)(dst + 16) = u[1]; *(uint4*)(dst + 32) = u[2];
}
__device__ __forceinline__ void tripB8(const float* p, char* dst) {
    __align__(16) uint16_t t[24];
#pragma unroll
    for (int i = 0; i < 8; i++) {
        uint16_t h, l; splitf(p[i], h, l);
        t[3*i] = h; t[3*i+1] = h; t[3*i+2] = l;
    }
    const uint4* u = (const uint4*)t;
    *(uint4*)(dst) = u[0]; *(uint4*)(dst + 16) = u[1]; *(uint4*)(dst + 32) = u[2];
}

__global__ void rope_table_kernel() {
    int idx = blockIdx.x * blockDim.x + threadIdx.x;
    if (idx >= S_LEN * 32) return;
    int s = idx >> 5, j = idx & 31;
    double ang = (double)s * pow(10000.0, -(double)j / 32.0);
    g_cos[idx] = (float)cos(ang);
    g_sin[idx] = (float)sin(ang);
}

// ---------------------------------------------------------------------------
// Projection: out = relu(A·W^T + b). BM=128, BN=64, chunks of 16 k (48 k').
// 8 warps = 4m x 2n; warp tile 32m x 32n (2 x m16, 4 x n8 mma tiles).
// MODE 0: flat; MODE 2: [bh][s][d] + RoPE; MODE 3: V transposed [bh][d][s]
// ---------------------------------------------------------------------------
#define SA 112                      // row stride bytes (48 bf16 = 96B + 16 pad)
#define PSTG (128 * SA + 64 * SA)   // 21504 per stage
#define PROJ_SMEM (2 * PSTG)        // 43008

template <int MODE>
__global__ __launch_bounds__(256) void proj_kernel(
    const float* __restrict__ A, const float* __restrict__ W,
    const float* __restrict__ bias, float* __restrict__ out)
{
    extern __shared__ char smem[];
    uint32_t sb = s2u(smem);
    int tid = threadIdx.x, lane = tid & 31, wid = tid >> 5;
    int m0 = blockIdx.y * 128, n0 = blockIdx.x * 64;
    int wm = (wid & 3) * 32, wn = (wid >> 2) * 32;

    int ar = tid >> 1, ac = (tid & 1) * 8;     // A loader: row, float col
    const float* Ap = A + (size_t)(m0 + ar) * F_DIM + ac;
    const float* Wp = W + (size_t)(n0 + (ar & 63)) * F_DIM + ac;

    float acc[2][4][4];
#pragma unroll
    for (int i = 0; i < 2; i++)
#pragma unroll
        for (int j = 0; j < 4; j++)
#pragma unroll
            for (int e = 0; e < 4; e++) acc[i][j][e] = 0.f;

    auto loadStage = [&](int chunk, int stg) {
        char* base = smem + stg * PSTG;
        tripA8(Ap + chunk * 16, base + ar * SA + ac * 6, 1.0f);
        if (tid < 128)
            tripB8(Wp + chunk * 16, base + 128 * SA + (ar & 63) * SA + ac * 6);
    };

    loadStage(0, 0);
    for (int c = 0; c < 32; c++) {
        __syncthreads();
        if (c + 1 < 32) loadStage(c + 1, (c + 1) & 1);
        uint32_t abase = sb + (c & 1) * PSTG;
        uint32_t wbase = abase + 128 * SA;
#pragma unroll
        for (int ks = 0; ks < 3; ks++) {
            uint32_t af[2][4], bf[4][2];
#pragma unroll
            for (int i = 0; i < 2; i++)
                ldmx4(af[i], addrA(abase, SA, wm + i * 16, ks * 16, lane));
#pragma unroll
            for (int j = 0; j < 4; j++)
                ldmx2(bf[j], addrB(wbase, SA, wn + j * 8, ks * 16, lane));
#pragma unroll
            for (int i = 0; i < 2; i++)
#pragma unroll
                for (int j = 0; j < 4; j++)
                    mma16816(acc[i][j], af[i], bf[j]);
        }
    }

    // epilogue
    int rr = lane >> 2, cq = (lane & 3) * 2;
    int head = n0 >> 6;
#pragma unroll
    for (int i = 0; i < 2; i++) {
#pragma unroll
        for (int h2 = 0; h2 < 2; h2++) {
            int m = m0 + wm + i * 16 + rr + h2 * 8;
            int s = m >> 2, b = m & 3;
#pragma unroll
            for (int j = 0; j < 4; j++) {
                int n = wn + j * 8 + cq;   // 0..63 (even)
                float v0 = fmaxf(acc[i][j][h2 * 2]     + bias[n0 + n], 0.f);
                float v1 = fmaxf(acc[i][j][h2 * 2 + 1] + bias[n0 + n + 1], 0.f);
                if (MODE == 2) {
                    int p = (s << 5) + (n >> 1);
                    float cc = g_cos[p], sn = g_sin[p];
                    float e = v0 * cc - v1 * sn;
                    float o = v0 * sn + v1 * cc;
                    v0 = e; v1 = o;
                }
                if (MODE == 0) {
                    *(float2*)&out[(size_t)m * F_DIM + n0 + n] = make_float2(v0, v1);
                } else if (MODE == 3) {
                    size_t o_ = ((size_t)(b * NHEAD + head) * HD + n) * S_LEN + s;
                    out[o_] = v0;
                    out[o_ + S_LEN] = v1;
                } else {
                    *(float2*)&out[((size_t)(b * NHEAD + head) * S_LEN + s) * HD + n] =
                        make_float2(v0, v1);
                }
            }
        }
    }
}

// ---------------------------------------------------------------------------
// Flash attention: CTA = 128 queries x 1 head; key blocks of 64.
// 8 warps; warp = 16 query rows x full width. Q frags in regs (K'=192).
// smem: Q(reused as P) 128x400 | K 64x400 | V 64x400 = 100.0 KB
// ---------------------------------------------------------------------------
#define SQ 400
#define FK_OFF (128 * SQ)
#define FV_OFF (FK_OFF + 64 * SQ)
#define FLASH_SMEM (FV_OFF + 64 * SQ)   // 102400

__global__ __launch_bounds__(256) void flash_kernel() {
    extern __shared__ char smem[];
    uint32_t sb = s2u(smem);
    int tid = threadIdx.x, lane = tid & 31, wid = tid >> 5;
    int q0 = blockIdx.x * 128, bh = blockIdx.y;
    int wm = wid * 16;

    // Q tile -> smem (scaled by 1/8, tripled)
    {
        int r = tid >> 1, c0 = (tid & 1) * 32;
        const float* p = g_Q + ((size_t)bh * S_LEN + q0 + r) * HD + c0;
        char* d = smem + r * SQ + c0 * 6;
#pragma unroll
        for (int g = 0; g < 4; g++)
            tripA8(p + g * 8, d + g * 48, 0.125f);
    }
    __syncthreads();

    // Q fragments (held in regs for whole kernel)
    uint32_t qf[12][4];
#pragma unroll
    for (int ks = 0; ks < 12; ks++)
        ldmx4(qf[ks], addrA(sb, SQ, wm, ks * 16, lane));

    float mi[2] = {-3.0e38f, -3.0e38f}, li[2] = {0.f, 0.f};
    float oacc[8][4];
#pragma unroll
    for (int j = 0; j < 8; j++)
#pragma unroll
        for (int e = 0; e < 4; e++) oacc[j][e] = 0.f;

    int kr = tid >> 2, kc = (tid & 3) * 16;

    for (int kb = 0; kb < 32; kb++) {
        // load K,V blocks (tripled, B-pattern)
        {
            const float* kp = g_K + ((size_t)bh * S_LEN + kb * 64 + kr) * HD + kc;
            const float* vp = g_V + ((size_t)bh * HD + kr) * S_LEN + kb * 64 + kc;
            char* kd = smem + FK_OFF + kr * SQ + kc * 6;
            char* vd = smem + FV_OFF + kr * SQ + kc * 6;
            tripB8(kp, kd);     tripB8(kp + 8, kd + 48);
            tripB8(vp, vd);     tripB8(vp + 8, vd + 48);
        }
        __syncthreads();

        // S = Q K^T
        float sacc[8][4];
#pragma unroll
        for (int j = 0; j < 8; j++)
#pragma unroll
            for (int e = 0; e < 4; e++) sacc[j][e] = 0.f;
#pragma unroll
        for (int ks = 0; ks < 12; ks++) {
#pragma unroll
            for (int j = 0; j < 8; j++) {
                uint32_t bf[2];
                ldmx2(bf, addrB(sb + FK_OFF, SQ, j * 8, ks * 16, lane));
                mma16816(sacc[j], qf[ks], bf);
            }
        }

        // online softmax (rows wm + rr, wm + rr + 8; quad-lane reductions)
        int rr = lane >> 2, cq = (lane & 3) * 2;
#pragma unroll
        for (int h2 = 0; h2 < 2; h2++) {
            float rmax = -3.0e38f;
#pragma unroll
            for (int j = 0; j < 8; j++)
                rmax = fmaxf(rmax, fmaxf(sacc[j][h2 * 2], sacc[j][h2 * 2 + 1]));
            rmax = fmaxf(rmax, __shfl_xor_sync(0xffffffffu, rmax, 1));
            rmax = fmaxf(rmax, __shfl_xor_sync(0xffffffffu, rmax, 2));
            float mnew = fmaxf(mi[h2], rmax);
            float alpha = __expf(mi[h2] - mnew);
            mi[h2] = mnew;
            float rsum = 0.f;
#pragma unroll
            for (int j = 0; j < 8; j++) {
                float p0 = __expf(sacc[j][h2 * 2] - mnew);
                float p1 = __expf(sacc[j][h2 * 2 + 1] - mnew);
                sacc[j][h2 * 2] = p0; sacc[j][h2 * 2 + 1] = p1;
                rsum += p0 + p1;
            }
            rsum += __shfl_xor_sync(0xffffffffu, rsum, 1);
            rsum += __shfl_xor_sync(0xffffffffu, rsum, 2);
            li[h2] = li[h2] * alpha + rsum;
            // O rescale
#pragma unroll
            for (int j = 0; j < 8; j++) {
                oacc[j][h2 * 2] *= alpha; oacc[j][h2 * 2 + 1] *= alpha;
            }
            // store P row (triple-A pattern) into reused Q region
            char* prow = smem + (wm + rr + h2 * 8) * SQ;
#pragma unroll
            for (int j = 0; j < 8; j++) {
                uint16_t h0, l0, h1, l1;
                splitf(sacc[j][h2 * 2], h0, l0);
                splitf(sacc[j][h2 * 2 + 1], h1, l1);
                uint32_t* pw = (uint32_t*)(prow + 6 * (cq + 8 * j));
                pw[0] = (uint32_t)h0 | ((uint32_t)l0 << 16);
                pw[1] = (uint32_t)h0 | ((uint32_t)h1 << 16);
                pw[2] = (uint32_t)l1 | ((uint32_t)h1 << 16);
            }
        }
        __syncwarp();

        // O += P V^T
#pragma unroll
        for (int ks = 0; ks < 12; ks++) {
            uint32_t pf[4];
            ldmx4(pf, addrA(sb, SQ, wm, ks * 16, lane));
#pragma unroll
            for (int j = 0; j < 8; j++) {
                uint32_t bf[2];
                ldmx2(bf, addrB(sb + FV_OFF, SQ, j * 8, ks * 16, lane));
                mma16816(oacc[j], pf, bf);
            }
        }
        __syncthreads();
    }

    // epilogue -> g_Y [s][b][f]
    int b = bh >> 3, h = bh & 7;
    int rr = lane >> 2, cq = (lane & 3) * 2;
#pragma unroll
    for (int h2 = 0; h2 < 2; h2++) {
        int srow = q0 + wm + rr + h2 * 8;
        float inv = 1.0f / li[h2];
        float* dst = &g_Y[((size_t)srow * B_SZ + b) * F_DIM + h * HD];
#pragma unroll
        for (int j = 0; j < 8; j++) {
            int d = j * 8 + cq;
            *(float2*)&dst[d] = make_float2(oacc[j][h2 * 2] * inv,
                                            oacc[j][h2 * 2 + 1] * inv);
        }
    }
}

// ---------------------------------------------------------------------------
extern "C" void kernel_launch(void* const* d_in, const int* in_sizes, int n_in,
                              void* d_out, int out_size) {
    const float* q  = (const float*)d_in[0];
    const float* k  = (const float*)d_in[1];
    const float* v  = (const float*)d_in[2];
    const float* Wq = (const float*)d_in[3];
    const float* bq = (const float*)d_in[4];
    const float* Wk = (const float*)d_in[5];
    const float* bk = (const float*)d_in[6];
    const float* Wv = (const float*)d_in[7];
    const float* bv = (const float*)d_in[8];
    const float* Wo = (const float*)d_in[9];
    const float* bo = (const float*)d_in[10];
    float* out = (float*)d_out;

    float *pQ, *pK, *pV, *pY;
    cudaGetSymbolAddress((void**)&pQ, g_Q);
    cudaGetSymbolAddress((void**)&pK, g_K);
    cudaGetSymbolAddress((void**)&pV, g_V);
    cudaGetSymbolAddress((void**)&pY, g_Y);

    cudaFuncSetAttribute(proj_kernel<0>, cudaFuncAttributeMaxDynamicSharedMemorySize, PROJ_SMEM);
    cudaFuncSetAttribute(proj_kernel<2>, cudaFuncAttributeMaxDynamicSharedMemorySize, PROJ_SMEM);
    cudaFuncSetAttribute(proj_kernel<3>, cudaFuncAttributeMaxDynamicSharedMemorySize, PROJ_SMEM);
    cudaFuncSetAttribute(flash_kernel,   cudaFuncAttributeMaxDynamicSharedMemorySize, FLASH_SMEM);

    rope_table_kernel<<<256, 256>>>();

    dim3 pg(F_DIM / 64, M_ROWS / 128);  // (8, 64)
    proj_kernel<2><<<pg, 256, PROJ_SMEM>>>(q, Wq, bq, pQ);
    proj_kernel<2><<<pg, 256, PROJ_SMEM>>>(k, Wk, bk, pK);
    proj_kernel<3><<<pg, 256, PROJ_SMEM>>>(v, Wv, bv, pV);

    flash_kernel<<<dim3(S_LEN / 128, NB), 256, FLASH_SMEM>>>();

    proj_kernel<0><<<pg, 256, PROJ_SMEM>>>(pY, Wo, bo, out);
}

// round 6
// speedup vs baseline: 1.1979x; 1.0005x over previous
#include <cuda_runtime.h>
#include <cstdint>
#include <math.h>

#define S_LEN  2048
#define B_SZ   4
#define F_DIM  512
#define NHEAD  8
#define NB     32
#define HD     64
#define M_ROWS 8192

__device__ float g_Q[(size_t)NB * S_LEN * HD];   // [bh][s][d]
__device__ float g_K[(size_t)NB * S_LEN * HD];   // [bh][s][d]
__device__ float g_V[(size_t)NB * S_LEN * HD];   // TRANSPOSED [bh][d][s]
__device__ float g_Y[(size_t)M_ROWS * F_DIM];
__device__ float g_cos[S_LEN * 32];
__device__ float g_sin[S_LEN * 32];

// ---------------- helpers ----------------
__device__ __forceinline__ uint32_t s2u(const void* p) {
    uint32_t a;
    asm("{ .reg .u64 t; cvta.to.shared.u64 t, %1; cvt.u32.u64 %0, t; }" : "=r"(a) : "l"(p));
    return a;
}
__device__ __forceinline__ uint16_t f2bf(float f) {
    uint16_t r; asm("cvt.rn.bf16.f32 %0, %1;" : "=h"(r) : "f"(f)); return r;
}
__device__ __forceinline__ float bf2f(uint16_t h) {
    return __uint_as_float(((uint32_t)h) << 16);
}
__device__ __forceinline__ void splitf(float a, uint16_t &h, uint16_t &l) {
    h = f2bf(a);
    l = f2bf(a - bf2f(h));
}

__device__ __forceinline__ void mma16816(float* d, const uint32_t* a, const uint32_t* b) {
    asm volatile(
        "mma.sync.aligned.m16n8k16.row.col.f32.bf16.bf16.f32 "
        "{%0,%1,%2,%3}, {%4,%5,%6,%7}, {%8,%9}, {%0,%1,%2,%3};"
        : "+f"(d[0]), "+f"(d[1]), "+f"(d[2]), "+f"(d[3])
        : "r"(a[0]), "r"(a[1]), "r"(a[2]), "r"(a[3]), "r"(b[0]), "r"(b[1]));
}
__device__ __forceinline__ void ldmx4(uint32_t* r, uint32_t a) {
    asm volatile("ldmatrix.sync.aligned.m8n8.x4.shared.b16 {%0,%1,%2,%3}, [%4];"
                 : "=r"(r[0]), "=r"(r[1]), "=r"(r[2]), "=r"(r[3]) : "r"(a));
}
__device__ __forceinline__ void ldmx2(uint32_t* r, uint32_t a) {
    asm volatile("ldmatrix.sync.aligned.m8n8.x2.shared.b16 {%0,%1}, [%2];"
                 : "=r"(r[0]), "=r"(r[1]) : "r"(a));
}
// A-frag ldmatrix address (m16k16 tile at (m0, k0), row-major, stride bytes)
__device__ __forceinline__ uint32_t addrA(uint32_t base, int stride, int m0, int k0, int lane) {
    int grp = lane >> 3, li = lane & 7;
    return base + (m0 + li + (grp & 1) * 8) * stride + (k0 + (grp >> 1) * 8) * 2;
}
// B-frag ldmatrix address (k16n8 tile, B stored [n][k] row-major)
__device__ __forceinline__ uint32_t addrB(uint32_t base, int stride, int n0, int k0, int lane) {
    int li = lane & 15;
    return base + (n0 + (li & 7)) * stride + (k0 + (li >> 3) * 8) * 2;
}
// triple-split writers: 8 floats -> 24 bf16 (48 bytes)
__device__ __forceinline__ void tripA8(const float* p, char* dst, float scale) {
    __align__(16) uint16_t t[24];
#pragma unroll
    for (int i = 0; i < 8; i++) {
        float a = p[i] * scale;
        uint16_t h, l; splitf(a, h, l);
        t[3*i] = h; t[3*i+1] = l; t[3*i+2] = h;
    }
    const uint4* u = (const uint4*)t;
    *(uint4*)(dst) = u[0]; *(uint4*)(dst + 16) = u[1]; *(uint4*)(dst + 32) = u[2];
}
__device__ __forceinline__ void tripB8(const float* p, char* dst) {
    __align__(16) uint16_t t[24];
#pragma unroll
    for (int i = 0; i < 8; i++) {
        uint16_t h, l; splitf(p[i], h, l);
        t[3*i] = h; t[3*i+1] = h; t[3*i+2] = l;
    }
    const uint4* u = (const uint4*)t;
    *(uint4*)(dst) = u[0]; *(uint4*)(dst + 16) = u[1]; *(uint4*)(dst + 32) = u[2];
}

__global__ void rope_table_kernel() {
    int idx = blockIdx.x * blockDim.x + threadIdx.x;
    if (idx >= S_LEN * 32) return;
    int s = idx >> 5, j = idx & 31;
    double ang = (double)s * pow(10000.0, -(double)j / 32.0);
    g_cos[idx] = (float)cos(ang);
    g_sin[idx] = (float)sin(ang);
}

// ---------------------------------------------------------------------------
// Projection: out = relu(A·W^T + b). BM=128, BN=64, chunks of 16 k (48 k').
// 8 warps = 4m x 2n; warp tile 32m x 32n (2 x m16, 4 x n8 mma tiles).
// MODE 0: flat; MODE 2: [bh][s][d] + RoPE; MODE 3: V transposed [bh][d][s]
// ---------------------------------------------------------------------------
#define SA 112                      // row stride bytes (48 bf16 = 96B + 16 pad)
#define PSTG (128 * SA + 64 * SA)   // 21504 per stage
#define PROJ_SMEM (2 * PSTG)        // 43008

template <int MODE>
__global__ __launch_bounds__(256) void proj_kernel(
    const float* __restrict__ A, const float* __restrict__ W,
    const float* __restrict__ bias, float* __restrict__ out)
{
    extern __shared__ char smem[];
    uint32_t sb = s2u(smem);
    int tid = threadIdx.x, lane = tid & 31, wid = tid >> 5;
    int m0 = blockIdx.y * 128, n0 = blockIdx.x * 64;
    int wm = (wid & 3) * 32, wn = (wid >> 2) * 32;

    int ar = tid >> 1, ac = (tid & 1) * 8;     // A loader: row, float col
    const float* Ap = A + (size_t)(m0 + ar) * F_DIM + ac;
    const float* Wp = W + (size_t)(n0 + (ar & 63)) * F_DIM + ac;

    float acc[2][4][4];
#pragma unroll
    for (int i = 0; i < 2; i++)
#pragma unroll
        for (int j = 0; j < 4; j++)
#pragma unroll
            for (int e = 0; e < 4; e++) acc[i][j][e] = 0.f;

    auto loadStage = [&](int chunk, int stg) {
        char* base = smem + stg * PSTG;
        tripA8(Ap + chunk * 16, base + ar * SA + ac * 6, 1.0f);
        if (tid < 128)
            tripB8(Wp + chunk * 16, base + 128 * SA + (ar & 63) * SA + ac * 6);
    };

    loadStage(0, 0);
    for (int c = 0; c < 32; c++) {
        __syncthreads();
        if (c + 1 < 32) loadStage(c + 1, (c + 1) & 1);
        uint32_t abase = sb + (c & 1) * PSTG;
        uint32_t wbase = abase + 128 * SA;
#pragma unroll
        for (int ks = 0; ks < 3; ks++) {
            uint32_t af[2][4], bf[4][2];
#pragma unroll
            for (int i = 0; i < 2; i++)
                ldmx4(af[i], addrA(abase, SA, wm + i * 16, ks * 16, lane));
#pragma unroll
            for (int j = 0; j < 4; j++)
                ldmx2(bf[j], addrB(wbase, SA, wn + j * 8, ks * 16, lane));
#pragma unroll
            for (int i = 0; i < 2; i++)
#pragma unroll
                for (int j = 0; j < 4; j++)
                    mma16816(acc[i][j], af[i], bf[j]);
        }
    }

    // epilogue
    int rr = lane >> 2, cq = (lane & 3) * 2;
    int head = n0 >> 6;
#pragma unroll
    for (int i = 0; i < 2; i++) {
#pragma unroll
        for (int h2 = 0; h2 < 2; h2++) {
            int m = m0 + wm + i * 16 + rr + h2 * 8;
            int s = m >> 2, b = m & 3;
#pragma unroll
            for (int j = 0; j < 4; j++) {
                int n = wn + j * 8 + cq;   // 0..63 (even)
                float v0 = fmaxf(acc[i][j][h2 * 2]     + bias[n0 + n], 0.f);
                float v1 = fmaxf(acc[i][j][h2 * 2 + 1] + bias[n0 + n + 1], 0.f);
                if (MODE == 2) {
                    int p = (s << 5) + (n >> 1);
                    float cc = g_cos[p], sn = g_sin[p];
                    float e = v0 * cc - v1 * sn;
                    float o = v0 * sn + v1 * cc;
                    v0 = e; v1 = o;
                }
                if (MODE == 0) {
                    *(float2*)&out[(size_t)m * F_DIM + n0 + n] = make_float2(v0, v1);
                } else if (MODE == 3) {
                    size_t o_ = ((size_t)(b * NHEAD + head) * HD + n) * S_LEN + s;
                    out[o_] = v0;
                    out[o_ + S_LEN] = v1;
                } else {
                    *(float2*)&out[((size_t)(b * NHEAD + head) * S_LEN + s) * HD + n] =
                        make_float2(v0, v1);
                }
            }
        }
    }
}

// ---------------------------------------------------------------------------
// Flash attention: CTA = 128 queries x 1 head; key blocks of 64.
// 8 warps; warp = 16 query rows x full width. Q frags in regs (K'=192).
// smem: Q(reused as P) 128x400 | K 64x400 | V 64x400 = 100.0 KB
// ---------------------------------------------------------------------------
#define SQ 400
#define FK_OFF (128 * SQ)
#define FV_OFF (FK_OFF + 64 * SQ)
#define FLASH_SMEM (FV_OFF + 64 * SQ)   // 102400

__global__ __launch_bounds__(256) void flash_kernel() {
    extern __shared__ char smem[];
    uint32_t sb = s2u(smem);
    int tid = threadIdx.x, lane = tid & 31, wid = tid >> 5;
    int q0 = blockIdx.x * 128, bh = blockIdx.y;
    int wm = wid * 16;

    // Q tile -> smem (scaled by 1/8, tripled)
    {
        int r = tid >> 1, c0 = (tid & 1) * 32;
        const float* p = g_Q + ((size_t)bh * S_LEN + q0 + r) * HD + c0;
        char* d = smem + r * SQ + c0 * 6;
#pragma unroll
        for (int g = 0; g < 4; g++)
            tripA8(p + g * 8, d + g * 48, 0.125f);
    }
    __syncthreads();

    // Q fragments (held in regs for whole kernel)
    uint32_t qf[12][4];
#pragma unroll
    for (int ks = 0; ks < 12; ks++)
        ldmx4(qf[ks], addrA(sb, SQ, wm, ks * 16, lane));

    float mi[2] = {-3.0e38f, -3.0e38f}, li[2] = {0.f, 0.f};
    float oacc[8][4];
#pragma unroll
    for (int j = 0; j < 8; j++)
#pragma unroll
        for (int e = 0; e < 4; e++) oacc[j][e] = 0.f;

    int kr = tid >> 2, kc = (tid & 3) * 16;

    for (int kb = 0; kb < 32; kb++) {
        // load K,V blocks (tripled, B-pattern)
        {
            const float* kp = g_K + ((size_t)bh * S_LEN + kb * 64 + kr) * HD + kc;
            const float* vp = g_V + ((size_t)bh * HD + kr) * S_LEN + kb * 64 + kc;
            char* kd = smem + FK_OFF + kr * SQ + kc * 6;
            char* vd = smem + FV_OFF + kr * SQ + kc * 6;
            tripB8(kp, kd);     tripB8(kp + 8, kd + 48);
            tripB8(vp, vd);     tripB8(vp + 8, vd + 48);
        }
        __syncthreads();

        // S = Q K^T
        float sacc[8][4];
#pragma unroll
        for (int j = 0; j < 8; j++)
#pragma unroll
            for (int e = 0; e < 4; e++) sacc[j][e] = 0.f;
#pragma unroll
        for (int ks = 0; ks < 12; ks++) {
#pragma unroll
            for (int j = 0; j < 8; j++) {
                uint32_t bf[2];
                ldmx2(bf, addrB(sb + FK_OFF, SQ, j * 8, ks * 16, lane));
                mma16816(sacc[j], qf[ks], bf);
            }
        }

        // online softmax (rows wm + rr, wm + rr + 8; quad-lane reductions)
        int rr = lane >> 2, cq = (lane & 3) * 2;
#pragma unroll
        for (int h2 = 0; h2 < 2; h2++) {
            float rmax = -3.0e38f;
#pragma unroll
            for (int j = 0; j < 8; j++)
                rmax = fmaxf(rmax, fmaxf(sacc[j][h2 * 2], sacc[j][h2 * 2 + 1]));
            rmax = fmaxf(rmax, __shfl_xor_sync(0xffffffffu, rmax, 1));
            rmax = fmaxf(rmax, __shfl_xor_sync(0xffffffffu, rmax, 2));
            float mnew = fmaxf(mi[h2], rmax);
            float alpha = __expf(mi[h2] - mnew);
            mi[h2] = mnew;
            float rsum = 0.f;
#pragma unroll
            for (int j = 0; j < 8; j++) {
                float p0 = __expf(sacc[j][h2 * 2] - mnew);
                float p1 = __expf(sacc[j][h2 * 2 + 1] - mnew);
                sacc[j][h2 * 2] = p0; sacc[j][h2 * 2 + 1] = p1;
                rsum += p0 + p1;
            }
            rsum += __shfl_xor_sync(0xffffffffu, rsum, 1);
            rsum += __shfl_xor_sync(0xffffffffu, rsum, 2);
            li[h2] = li[h2] * alpha + rsum;
            // O rescale
#pragma unroll
            for (int j = 0; j < 8; j++) {
                oacc[j][h2 * 2] *= alpha; oacc[j][h2 * 2 + 1] *= alpha;
            }
            // store P row (triple-A pattern) into reused Q region
            char* prow = smem + (wm + rr + h2 * 8) * SQ;
#pragma unroll
            for (int j = 0; j < 8; j++) {
                uint16_t h0, l0, h1, l1;
                splitf(sacc[j][h2 * 2], h0, l0);
                splitf(sacc[j][h2 * 2 + 1], h1, l1);
                uint32_t* pw = (uint32_t*)(prow + 6 * (cq + 8 * j));
                pw[0] = (uint32_t)h0 | ((uint32_t)l0 << 16);
                pw[1] = (uint32_t)h0 | ((uint32_t)h1 << 16);
                pw[2] = (uint32_t)l1 | ((uint32_t)h1 << 16);
            }
        }
        __syncwarp();

        // O += P V^T
#pragma unroll
        for (int ks = 0; ks < 12; ks++) {
            uint32_t pf[4];
            ldmx4(pf, addrA(sb, SQ, wm, ks * 16, lane));
#pragma unroll
            for (int j = 0; j < 8; j++) {
                uint32_t bf[2];
                ldmx2(bf, addrB(sb + FV_OFF, SQ, j * 8, ks * 16, lane));
                mma16816(oacc[j], pf, bf);
            }
        }
        __syncthreads();
    }

    // epilogue -> g_Y [s][b][f]
    int b = bh >> 3, h = bh & 7;
    int rr = lane >> 2, cq = (lane & 3) * 2;
#pragma unroll
    for (int h2 = 0; h2 < 2; h2++) {
        int srow = q0 + wm + rr + h2 * 8;
        float inv = 1.0f / li[h2];
        float* dst = &g_Y[((size_t)srow * B_SZ + b) * F_DIM + h * HD];
#pragma unroll
        for (int j = 0; j < 8; j++) {
            int d = j * 8 + cq;
            *(float2*)&dst[d] = make_float2(oacc[j][h2 * 2] * inv,
                                            oacc[j][h2 * 2 + 1] * inv);
        }
    }
}

// ---------------------------------------------------------------------------
extern "C" void kernel_launch(void* const* d_in, const int* in_sizes, int n_in,
                              void* d_out, int out_size) {
    const float* q  = (const float*)d_in[0];
    const float* k  = (const float*)d_in[1];
    const float* v  = (const float*)d_in[2];
    const float* Wq = (const float*)d_in[3];
    const float* bq = (const float*)d_in[4];
    const float* Wk = (const float*)d_in[5];
    const float* bk = (const float*)d_in[6];
    const float* Wv = (const float*)d_in[7];
    const float* bv = (const float*)d_in[8];
    const float* Wo = (const float*)d_in[9];
    const float* bo = (const float*)d_in[10];
    float* out = (float*)d_out;

    float *pQ, *pK, *pV, *pY;
    cudaGetSymbolAddress((void**)&pQ, g_Q);
    cudaGetSymbolAddress((void**)&pK, g_K);
    cudaGetSymbolAddress((void**)&pV, g_V);
    cudaGetSymbolAddress((void**)&pY, g_Y);

    cudaFuncSetAttribute(proj_kernel<0>, cudaFuncAttributeMaxDynamicSharedMemorySize, PROJ_SMEM);
    cudaFuncSetAttribute(proj_kernel<2>, cudaFuncAttributeMaxDynamicSharedMemorySize, PROJ_SMEM);
    cudaFuncSetAttribute(proj_kernel<3>, cudaFuncAttributeMaxDynamicSharedMemorySize, PROJ_SMEM);
    cudaFuncSetAttribute(flash_kernel,   cudaFuncAttributeMaxDynamicSharedMemorySize, FLASH_SMEM);

    rope_table_kernel<<<256, 256>>>();

    dim3 pg(F_DIM / 64, M_ROWS / 128);  // (8, 64)
    proj_kernel<2><<<pg, 256, PROJ_SMEM>>>(q, Wq, bq, pQ);
    proj_kernel<2><<<pg, 256, PROJ_SMEM>>>(k, Wk, bk, pK);
    proj_kernel<3><<<pg, 256, PROJ_SMEM>>>(v, Wv, bv, pV);

    flash_kernel<<<dim3(S_LEN / 128, NB), 256, FLASH_SMEM>>>();

    proj_kernel<0><<<pg, 256, PROJ_SMEM>>>(pY, Wo, bo, out);
}

// round 8
// speedup vs baseline: 1.5050x; 1.2564x over previous
#include <cuda_runtime.h>
#include <cstdint>
#include <math.h>

#define S_LEN  2048
#define B_SZ   4
#define F_DIM  512
#define NHEAD  8
#define NB     32
#define HD     64
#define M_ROWS 8192
#define TRIP   1536     // 3*F_DIM k' elements
#define TRIPQ  192      // 3*HD

typedef unsigned short u16;
typedef unsigned int u32;

// tripled-bf16 scratch
__device__ u16 g_inb[(size_t)3 * M_ROWS * TRIP];          // q,k,v A-pattern
__device__ u16 g_Wb[(size_t)4 * F_DIM * TRIP];            // Wq,Wk,Wv,Wo B-pattern
__device__ u16 g_Qb[(size_t)NB * S_LEN * TRIPQ];          // A-pattern, scaled 1/8
__device__ u16 g_Kb[(size_t)NB * S_LEN * TRIPQ];          // B-pattern
__device__ u16 g_Vb[(size_t)NB * HD * (3 * S_LEN)];       // B-pattern, [bh][d][s']
__device__ u16 g_Yb[(size_t)M_ROWS * TRIP];               // A-pattern
__device__ float g_cos[S_LEN * 32];
__device__ float g_sin[S_LEN * 32];

// ---------------- helpers ----------------
__device__ __forceinline__ u32 s2u(const void* p) {
    u32 a;
    asm("{ .reg .u64 t; cvta.to.shared.u64 t, %1; cvt.u32.u64 %0, t; }" : "=r"(a) : "l"(p));
    return a;
}
__device__ __forceinline__ u16 f2bf(float f) {
    u16 r; asm("cvt.rn.bf16.f32 %0, %1;" : "=h"(r) : "f"(f)); return r;
}
__device__ __forceinline__ float bf2f(u16 h) { return __uint_as_float(((u32)h) << 16); }
__device__ __forceinline__ void splitf(float a, u16 &h, u16 &l) {
    h = f2bf(a); l = f2bf(a - bf2f(h));
}
// pack a pair (v0,v1) -> 3 u32 (6 bf16)
__device__ __forceinline__ void packA(float v0, float v1, u32* w) {
    u16 h0, l0, h1, l1; splitf(v0, h0, l0); splitf(v1, h1, l1);
    w[0] = h0 | ((u32)l0 << 16); w[1] = h0 | ((u32)h1 << 16); w[2] = l1 | ((u32)h1 << 16);
}
__device__ __forceinline__ void packB(float v0, float v1, u32* w) {
    u16 h0, l0, h1, l1; splitf(v0, h0, l0); splitf(v1, h1, l1);
    w[0] = h0 | ((u32)h0 << 16); w[1] = l0 | ((u32)h1 << 16); w[2] = h1 | ((u32)l1 << 16);
}

__device__ __forceinline__ void mma16816(float* d, const u32* a, const u32* b) {
    asm volatile(
        "mma.sync.aligned.m16n8k16.row.col.f32.bf16.bf16.f32 "
        "{%0,%1,%2,%3}, {%4,%5,%6,%7}, {%8,%9}, {%0,%1,%2,%3};"
        : "+f"(d[0]), "+f"(d[1]), "+f"(d[2]), "+f"(d[3])
        : "r"(a[0]), "r"(a[1]), "r"(a[2]), "r"(a[3]), "r"(b[0]), "r"(b[1]));
}
__device__ __forceinline__ void ldmx4(u32* r, u32 a) {
    asm volatile("ldmatrix.sync.aligned.m8n8.x4.shared.b16 {%0,%1,%2,%3}, [%4];"
                 : "=r"(r[0]), "=r"(r[1]), "=r"(r[2]), "=r"(r[3]) : "r"(a));
}
__device__ __forceinline__ void ldmx2(u32* r, u32 a) {
    asm volatile("ldmatrix.sync.aligned.m8n8.x2.shared.b16 {%0,%1}, [%2];"
                 : "=r"(r[0]), "=r"(r[1]) : "r"(a));
}
__device__ __forceinline__ u32 addrA(u32 base, int stride, int m0, int k0, int lane) {
    int grp = lane >> 3, li = lane & 7;
    return base + (m0 + li + (grp & 1) * 8) * stride + (k0 + (grp >> 1) * 8) * 2;
}
__device__ __forceinline__ u32 addrB(u32 base, int stride, int n0, int k0, int lane) {
    int li = lane & 15;
    return base + (n0 + (li & 7)) * stride + (k0 + (li >> 3) * 8) * 2;
}
#define CPA16(s, g) asm volatile("cp.async.cg.shared.global [%0], [%1], 16;" :: "r"(s), "l"(g))
#define CPCOMMIT()  asm volatile("cp.async.commit_group;")
#define CPWAIT(n)   asm volatile("cp.async.wait_group %0;" :: "n"(n))

__global__ void rope_table_kernel() {
    int idx = blockIdx.x * blockDim.x + threadIdx.x;
    if (idx >= S_LEN * 32) return;
    int s = idx >> 5, j = idx & 31;
    double ang = (double)s * pow(10000.0, -(double)j / 32.0);
    g_cos[idx] = (float)cos(ang);
    g_sin[idx] = (float)sin(ang);
}

// ---------------------------------------------------------------------------
// conversion pre-pass: 8 floats -> 24 bf16 (PAT 0 = A (h,l,h), 1 = B (h,h,l))
// ---------------------------------------------------------------------------
template <int PAT>
__global__ void conv_kernel(const float* __restrict__ src, u16* __restrict__ dst, int n8) {
    int g = blockIdx.x * blockDim.x + threadIdx.x;
    if (g >= n8) return;
    float4 f0 = *(const float4*)(src + (size_t)g * 8);
    float4 f1 = *(const float4*)(src + (size_t)g * 8 + 4);
    float f[8] = {f0.x, f0.y, f0.z, f0.w, f1.x, f1.y, f1.z, f1.w};
    __align__(16) u32 w[12];
#pragma unroll
    for (int i = 0; i < 4; i++) {
        if (PAT == 0) packA(f[2*i], f[2*i+1], w + 3*i);
        else          packB(f[2*i], f[2*i+1], w + 3*i);
    }
    uint4* d = (uint4*)(dst + (size_t)g * 24);
    const uint4* s = (const uint4*)w;
    d[0] = s[0]; d[1] = s[1]; d[2] = s[2];
}

// ---------------------------------------------------------------------------
// Projection GEMM. BM=128, BN=64; k-chunk = 32 floats (96 k'); 16 chunks.
// 8 warps = 4m x 2n, warp tile 32x32. cp.async double-buffered.
// MODE 0: fp32 flat out; 1: Q (A-pat, rope, 1/8); 2: K (B-pat, rope); 3: V (B-pat, T)
// ---------------------------------------------------------------------------
#define SAP  208                        // stage row stride bytes
#define PSTG (192 * SAP)                // 39936
#define PROJ_SMEM (2 * PSTG)            // 79872

template <int MODE>
__global__ __launch_bounds__(256) void proj_kernel(
    const u16* __restrict__ Ab, const u16* __restrict__ Wb,
    const float* __restrict__ bias, void* __restrict__ outp)
{
    extern __shared__ char smem[];
    u32 sb = s2u(smem);
    int tid = threadIdx.x, lane = tid & 31, wid = tid >> 5;
    int m0 = blockIdx.y * 128, n0 = blockIdx.x * 64;
    int wm = (wid & 3) * 32, wn = (wid >> 2) * 32;

    const char* Abase = (const char*)Ab;
    const char* Wbase = (const char*)Wb;
    int arow = tid >> 1, acol = (tid & 1) * 96;   // A: 128 rows x 192B
    int wrow = tid >> 2, wcol = (tid & 3) * 48;   // W: 64 rows x 192B

    auto loadStage = [&](int c, int stg) {
        u32 base = sb + stg * PSTG;
        const char* asrc = Abase + ((size_t)(m0 + arow) * TRIP + c * 96) * 2 + acol;
        u32 adst = base + arow * SAP + acol;
#pragma unroll
        for (int i = 0; i < 6; i++) CPA16(adst + i * 16, asrc + i * 16);
        const char* wsrc = Wbase + ((size_t)(n0 + wrow) * TRIP + c * 96) * 2 + wcol;
        u32 wdst = base + 128 * SAP + wrow * SAP + wcol;
#pragma unroll
        for (int i = 0; i < 3; i++) CPA16(wdst + i * 16, wsrc + i * 16);
        CPCOMMIT();
    };

    float acc[2][4][4];
#pragma unroll
    for (int i = 0; i < 2; i++)
#pragma unroll
        for (int j = 0; j < 4; j++)
#pragma unroll
            for (int e = 0; e < 4; e++) acc[i][j][e] = 0.f;

    loadStage(0, 0);
    for (int c = 0; c < 16; c++) {
        if (c < 15) { loadStage(c + 1, (c + 1) & 1); CPWAIT(1); }
        else CPWAIT(0);
        __syncthreads();
        u32 abase = sb + (c & 1) * PSTG;
        u32 wbase = abase + 128 * SAP;
#pragma unroll
        for (int ks = 0; ks < 6; ks++) {
            u32 af[2][4], bf[4][2];
#pragma unroll
            for (int i = 0; i < 2; i++)
                ldmx4(af[i], addrA(abase, SAP, wm + i * 16, ks * 16, lane));
#pragma unroll
            for (int j = 0; j < 4; j++)
                ldmx2(bf[j], addrB(wbase, SAP, wn + j * 8, ks * 16, lane));
#pragma unroll
            for (int i = 0; i < 2; i++)
#pragma unroll
                for (int j = 0; j < 4; j++)
                    mma16816(acc[i][j], af[i], bf[j]);
        }
        __syncthreads();
    }

    // epilogue
    int rr = lane >> 2, cq = (lane & 3) * 2;
    int head = n0 >> 6;
#pragma unroll
    for (int i = 0; i < 2; i++) {
#pragma unroll
        for (int h2 = 0; h2 < 2; h2++) {
            int m = m0 + wm + i * 16 + rr + h2 * 8;
            int s = m >> 2, b = m & 3;
#pragma unroll
            for (int j = 0; j < 4; j++) {
                int n = wn + j * 8 + cq;   // even, 0..62
                float v0 = fmaxf(acc[i][j][h2 * 2]     + bias[n0 + n], 0.f);
                float v1 = fmaxf(acc[i][j][h2 * 2 + 1] + bias[n0 + n + 1], 0.f);
                if (MODE == 1 || MODE == 2) {   // RoPE
                    if (MODE == 1) { v0 *= 0.125f; v1 *= 0.125f; }
                    int p = (s << 5) + (n >> 1);
                    float cc = g_cos[p], sn = g_sin[p];
                    float e = v0 * cc - v1 * sn;
                    float o = v0 * sn + v1 * cc;
                    v0 = e; v1 = o;
                }
                if (MODE == 0) {
                    *(float2*)&((float*)outp)[(size_t)m * F_DIM + n0 + n] = make_float2(v0, v1);
                } else if (MODE == 1 || MODE == 2) {
                    int bh = b * NHEAD + head;
                    u32 w[3];
                    if (MODE == 1) packA(v0, v1, w); else packB(v0, v1, w);
                    u32* d = (u32*)((u16*)outp + ((size_t)bh * S_LEN + s) * TRIPQ + 3 * n);
                    d[0] = w[0]; d[1] = w[1]; d[2] = w[2];
                } else {   // V transposed B-pattern: rows d = n, n+1
                    int bh = b * NHEAD + head;
                    u16 h0, l0, h1, l1; splitf(v0, h0, l0); splitf(v1, h1, l1);
                    u16* d0 = (u16*)outp + ((size_t)bh * HD + n) * (3 * S_LEN) + 3 * s;
                    u16* d1 = d0 + 3 * S_LEN;
                    d0[0] = h0; d0[1] = h0; d0[2] = l0;
                    d1[0] = h1; d1[1] = h1; d1[2] = l1;
                }
            }
        }
    }
}

// ---------------------------------------------------------------------------
// Flash attention: CTA = 128 queries x 1 head; key blocks of 64, double-buffered.
// 8 warps, warp = 16 rows full width. Q frags in regs; P reuses Q smem region.
// smem: P/Q 128x400 | 2 x (K 64x400 + V 64x400) = 153600 B
// ---------------------------------------------------------------------------
#define FSQ 400
#define FP_OFF 0
#define FKV(stg) (128 * FSQ + (stg) * 2 * 64 * FSQ)
#define FV_REL (64 * FSQ)
#define FLASH_SMEM (128 * FSQ + 4 * 64 * FSQ)   // 153600

__global__ __launch_bounds__(256) void flash_kernel() {
    extern __shared__ char smem[];
    u32 sb = s2u(smem);
    int tid = threadIdx.x, lane = tid & 31, wid = tid >> 5;
    int q0 = blockIdx.x * 128, bh = blockIdx.y;
    int wm = wid * 16;

    // Q load (tripled A-pattern, pre-scaled)
    {
        int r = tid >> 1, c0 = (tid & 1) * 192;
        const char* src = (const char*)g_Qb + ((size_t)(bh * S_LEN) + q0 + r) * (TRIPQ * 2) + c0;
        u32 dst = sb + r * FSQ + c0;
#pragma unroll
        for (int i = 0; i < 12; i++) CPA16(dst + i * 16, src + i * 16);
        CPCOMMIT();
    }
    int kr = tid >> 2, kc = (tid & 3) * 96;
    auto loadKV = [&](int kb, int stg) {
        u32 base = sb + FKV(stg);
        const char* ksrc = (const char*)g_Kb + ((size_t)(bh * S_LEN) + kb * 64 + kr) * (TRIPQ * 2) + kc;
#pragma unroll
        for (int i = 0; i < 6; i++) CPA16(base + kr * FSQ + kc + i * 16, ksrc + i * 16);
        const char* vsrc = (const char*)g_Vb + ((size_t)(bh * HD) + kr) * (3 * S_LEN * 2) + kb * 384 + kc;
#pragma unroll
        for (int i = 0; i < 6; i++) CPA16(base + FV_REL + kr * FSQ + kc + i * 16, vsrc + i * 16);
        CPCOMMIT();
    };

    loadKV(0, 0);
    CPWAIT(1);          // Q done
    __syncthreads();

    u32 qf[12][4];
#pragma unroll
    for (int ks = 0; ks < 12; ks++)
        ldmx4(qf[ks], addrA(sb, FSQ, wm, ks * 16, lane));

    float mi[2] = {-3.0e38f, -3.0e38f}, li[2] = {0.f, 0.f};
    float oacc[8][4];
#pragma unroll
    for (int j = 0; j < 8; j++)
#pragma unroll
        for (int e = 0; e < 4; e++) oacc[j][e] = 0.f;

    for (int kb = 0; kb < 32; kb++) {
        if (kb < 31) { loadKV(kb + 1, (kb + 1) & 1); CPWAIT(1); }
        else CPWAIT(0);
        __syncthreads();
        u32 kbase = sb + FKV(kb & 1);
        u32 vbase = kbase + FV_REL;

        // S = Q K^T
        float sacc[8][4];
#pragma unroll
        for (int j = 0; j < 8; j++)
#pragma unroll
            for (int e = 0; e < 4; e++) sacc[j][e] = 0.f;
#pragma unroll
        for (int ks = 0; ks < 12; ks++) {
#pragma unroll
            for (int j = 0; j < 8; j++) {
                u32 bf[2];
                ldmx2(bf, addrB(kbase, FSQ, j * 8, ks * 16, lane));
                mma16816(sacc[j], qf[ks], bf);
            }
        }

        // online softmax
        int rr = lane >> 2, cq = (lane & 3) * 2;
#pragma unroll
        for (int h2 = 0; h2 < 2; h2++) {
            float rmax = -3.0e38f;
#pragma unroll
            for (int j = 0; j < 8; j++)
                rmax = fmaxf(rmax, fmaxf(sacc[j][h2 * 2], sacc[j][h2 * 2 + 1]));
            rmax = fmaxf(rmax, __shfl_xor_sync(0xffffffffu, rmax, 1));
            rmax = fmaxf(rmax, __shfl_xor_sync(0xffffffffu, rmax, 2));
            float mnew = fmaxf(mi[h2], rmax);
            float alpha = __expf(mi[h2] - mnew);
            mi[h2] = mnew;
            float rsum = 0.f;
#pragma unroll
            for (int j = 0; j < 8; j++) {
                float p0 = __expf(sacc[j][h2 * 2] - mnew);
                float p1 = __expf(sacc[j][h2 * 2 + 1] - mnew);
                sacc[j][h2 * 2] = p0; sacc[j][h2 * 2 + 1] = p1;
                rsum += p0 + p1;
            }
            rsum += __shfl_xor_sync(0xffffffffu, rsum, 1);
            rsum += __shfl_xor_sync(0xffffffffu, rsum, 2);
            li[h2] = li[h2] * alpha + rsum;
#pragma unroll
            for (int j = 0; j < 8; j++) {
                oacc[j][h2 * 2] *= alpha; oacc[j][h2 * 2 + 1] *= alpha;
            }
            // P -> smem (A-pattern)
            char* prow = smem + (wm + rr + h2 * 8) * FSQ;
#pragma unroll
            for (int j = 0; j < 8; j++) {
                u32 w[3];
                packA(sacc[j][h2 * 2], sacc[j][h2 * 2 + 1], w);
                u32* pw = (u32*)(prow + 6 * (cq + 8 * j));
                pw[0] = w[0]; pw[1] = w[1]; pw[2] = w[2];
            }
        }
        __syncwarp();

        // O += P V^T
#pragma unroll
        for (int ks = 0; ks < 12; ks++) {
            u32 pf[4];
            ldmx4(pf, addrA(sb, FSQ, wm, ks * 16, lane));
#pragma unroll
            for (int j = 0; j < 8; j++) {
                u32 bf[2];
                ldmx2(bf, addrB(vbase, FSQ, j * 8, ks * 16, lane));
                mma16816(oacc[j], pf, bf);
            }
        }
        __syncthreads();
    }

    // epilogue: write tripled A-pattern Y
    int b = bh >> 3, h = bh & 7;
    int rr = lane >> 2, cq = (lane & 3) * 2;
#pragma unroll
    for (int h2 = 0; h2 < 2; h2++) {
        int srow = q0 + wm + rr + h2 * 8;
        int m = srow * B_SZ + b;
        float inv = 1.0f / li[h2];
#pragma unroll
        for (int j = 0; j < 8; j++) {
            int f = h * HD + j * 8 + cq;   // even
            u32 w[3];
            packA(oacc[j][h2 * 2] * inv, oacc[j][h2 * 2 + 1] * inv, w);
            u32* d = (u32*)(g_Yb + (size_t)m * TRIP + 3 * f);
            d[0] = w[0]; d[1] = w[1]; d[2] = w[2];
        }
    }
}

// ---------------------------------------------------------------------------
extern "C" void kernel_launch(void* const* d_in, const int* in_sizes, int n_in,
                              void* d_out, int out_size) {
    const float* q  = (const float*)d_in[0];
    const float* k  = (const float*)d_in[1];
    const float* v  = (const float*)d_in[2];
    const float* Wq = (const float*)d_in[3];
    const float* bq = (const float*)d_in[4];
    const float* Wk = (const float*)d_in[5];
    const float* bk = (const float*)d_in[6];
    const float* Wv = (const float*)d_in[7];
    const float* bv = (const float*)d_in[8];
    const float* Wo = (const float*)d_in[9];
    const float* bo = (const float*)d_in[10];

    u16 *pIn, *pW, *pQ, *pK, *pV, *pY;
    cudaGetSymbolAddress((void**)&pIn, g_inb);
    cudaGetSymbolAddress((void**)&pW,  g_Wb);
    cudaGetSymbolAddress((void**)&pQ,  g_Qb);
    cudaGetSymbolAddress((void**)&pK,  g_Kb);
    cudaGetSymbolAddress((void**)&pV,  g_Vb);
    cudaGetSymbolAddress((void**)&pY,  g_Yb);

    cudaFuncSetAttribute(proj_kernel<0>, cudaFuncAttributeMaxDynamicSharedMemorySize, PROJ_SMEM);
    cudaFuncSetAttribute(proj_kernel<1>, cudaFuncAttributeMaxDynamicSharedMemorySize, PROJ_SMEM);
    cudaFuncSetAttribute(proj_kernel<2>, cudaFuncAttributeMaxDynamicSharedMemorySize, PROJ_SMEM);
    cudaFuncSetAttribute(proj_kernel<3>, cudaFuncAttributeMaxDynamicSharedMemorySize, PROJ_SMEM);
    cudaFuncSetAttribute(flash_kernel,   cudaFuncAttributeMaxDynamicSharedMemorySize, FLASH_SMEM);

    rope_table_kernel<<<256, 256>>>();

    const int nIn8 = M_ROWS * F_DIM / 8;     // 524288
    const int nW8  = F_DIM * F_DIM / 8;      // 32768
    conv_kernel<0><<<nIn8 / 256, 256>>>(q, pIn,                       nIn8);
    conv_kernel<0><<<nIn8 / 256, 256>>>(k, pIn + (size_t)M_ROWS*TRIP, nIn8);
    conv_kernel<0><<<nIn8 / 256, 256>>>(v, pIn + (size_t)2*M_ROWS*TRIP, nIn8);
    conv_kernel<1><<<nW8 / 256, 256>>>(Wq, pW,                        nW8);
    conv_kernel<1><<<nW8 / 256, 256>>>(Wk, pW + (size_t)F_DIM*TRIP,   nW8);
    conv_kernel<1><<<nW8 / 256, 256>>>(Wv, pW + (size_t)2*F_DIM*TRIP, nW8);
    conv_kernel<1><<<nW8 / 256, 256>>>(Wo, pW + (size_t)3*F_DIM*TRIP, nW8);

    dim3 pg(F_DIM / 64, M_ROWS / 128);  // (8, 64)
    proj_kernel<1><<<pg, 256, PROJ_SMEM>>>(pIn,                        pW,                      bq, pQ);
    proj_kernel<2><<<pg, 256, PROJ_SMEM>>>(pIn + (size_t)M_ROWS*TRIP,  pW + (size_t)F_DIM*TRIP, bk, pK);
    proj_kernel<3><<<pg, 256, PROJ_SMEM>>>(pIn + (size_t)2*M_ROWS*TRIP, pW + (size_t)2*F_DIM*TRIP, bv, pV);

    flash_kernel<<<dim3(S_LEN / 128, NB), 256, FLASH_SMEM>>>();

    proj_kernel<0><<<pg, 256, PROJ_SMEM>>>(pY, pW + (size_t)3*F_DIM*TRIP, bo, d_out);
}

// round 9
// speedup vs baseline: 1.6720x; 1.1110x over previous
#include <cuda_runtime.h>
#include <cstdint>
#include <math.h>

#define S_LEN  2048
#define B_SZ   4
#define F_DIM  512
#define NHEAD  8
#define NB     32
#define HD     64
#define M_ROWS 8192
#define TRIP   1536     // 3*F_DIM k' elements
#define TRIPQ  192      // 3*HD

typedef unsigned short u16;
typedef unsigned int u32;

// tripled-bf16 scratch
__device__ u16 g_inb[(size_t)3 * M_ROWS * TRIP];          // q,k,v A-pattern
__device__ u16 g_Wb[(size_t)4 * F_DIM * TRIP];            // Wq,Wk,Wv,Wo B-pattern
__device__ u16 g_Qb[(size_t)NB * S_LEN * TRIPQ];          // A-pattern, scaled 1/8
__device__ u16 g_Kb[(size_t)NB * S_LEN * TRIPQ];          // B-pattern
__device__ u16 g_Vb[(size_t)NB * HD * (3 * S_LEN)];       // B-pattern, [bh][d][s']
__device__ u16 g_Yb[(size_t)M_ROWS * TRIP];               // A-pattern
__device__ float g_cos[S_LEN * 32];
__device__ float g_sin[S_LEN * 32];

// ---------------- helpers ----------------
__device__ __forceinline__ u32 s2u(const void* p) {
    u32 a;
    asm("{ .reg .u64 t; cvta.to.shared.u64 t, %1; cvt.u32.u64 %0, t; }" : "=r"(a) : "l"(p));
    return a;
}
__device__ __forceinline__ u16 f2bf(float f) {
    u16 r; asm("cvt.rn.bf16.f32 %0, %1;" : "=h"(r) : "f"(f)); return r;
}
__device__ __forceinline__ float bf2f(u16 h) { return __uint_as_float(((u32)h) << 16); }
__device__ __forceinline__ void splitf(float a, u16 &h, u16 &l) {
    h = f2bf(a); l = f2bf(a - bf2f(h));
}
__device__ __forceinline__ void packA(float v0, float v1, u32* w) {
    u16 h0, l0, h1, l1; splitf(v0, h0, l0); splitf(v1, h1, l1);
    w[0] = h0 | ((u32)l0 << 16); w[1] = h0 | ((u32)h1 << 16); w[2] = l1 | ((u32)h1 << 16);
}
__device__ __forceinline__ void packB(float v0, float v1, u32* w) {
    u16 h0, l0, h1, l1; splitf(v0, h0, l0); splitf(v1, h1, l1);
    w[0] = h0 | ((u32)h0 << 16); w[1] = l0 | ((u32)h1 << 16); w[2] = h1 | ((u32)l1 << 16);
}

__device__ __forceinline__ void mma16816(float* d, const u32* a, const u32* b) {
    asm volatile(
        "mma.sync.aligned.m16n8k16.row.col.f32.bf16.bf16.f32 "
        "{%0,%1,%2,%3}, {%4,%5,%6,%7}, {%8,%9}, {%0,%1,%2,%3};"
        : "+f"(d[0]), "+f"(d[1]), "+f"(d[2]), "+f"(d[3])
        : "r"(a[0]), "r"(a[1]), "r"(a[2]), "r"(a[3]), "r"(b[0]), "r"(b[1]));
}
__device__ __forceinline__ void ldmx4(u32* r, u32 a) {
    asm volatile("ldmatrix.sync.aligned.m8n8.x4.shared.b16 {%0,%1,%2,%3}, [%4];"
                 : "=r"(r[0]), "=r"(r[1]), "=r"(r[2]), "=r"(r[3]) : "r"(a));
}
__device__ __forceinline__ u32 addrA(u32 base, int stride, int m0, int k0, int lane) {
    int grp = lane >> 3, li = lane & 7;
    return base + (m0 + li + (grp & 1) * 8) * stride + (k0 + (grp >> 1) * 8) * 2;
}
// B x4: covers n16 x k16 -> (r0,r1) = n0..7 frag, (r2,r3) = n8..15 frag
__device__ __forceinline__ u32 addrB16(u32 base, int stride, int n0, int k0, int lane) {
    int grp = lane >> 3, li = lane & 7;
    return base + (n0 + li + (grp >> 1) * 8) * stride + (k0 + (grp & 1) * 8) * 2;
}
#define CPA16(s, g) asm volatile("cp.async.cg.shared.global [%0], [%1], 16;" :: "r"(s), "l"(g))
#define CPCOMMIT()  asm volatile("cp.async.commit_group;")
#define CPWAIT(n)   asm volatile("cp.async.wait_group %0;" :: "n"(n))

__global__ void rope_table_kernel() {
    int idx = blockIdx.x * blockDim.x + threadIdx.x;
    if (idx >= S_LEN * 32) return;
    int s = idx >> 5, j = idx & 31;
    double ang = (double)s * pow(10000.0, -(double)j / 32.0);
    g_cos[idx] = (float)cos(ang);
    g_sin[idx] = (float)sin(ang);
}

// ---------------------------------------------------------------------------
// conversion pre-pass (merged): grid.y selects tensor
// ---------------------------------------------------------------------------
__global__ void conv_in_kernel(const float* __restrict__ q, const float* __restrict__ k,
                               const float* __restrict__ v, u16* __restrict__ dst, int n8) {
    int g = blockIdx.x * blockDim.x + threadIdx.x;
    if (g >= n8) return;
    int sel = blockIdx.y;
    const float* src = (sel == 0) ? q : (sel == 1) ? k : v;
    u16* d = dst + (size_t)sel * M_ROWS * TRIP;
    float4 f0 = *(const float4*)(src + (size_t)g * 8);
    float4 f1 = *(const float4*)(src + (size_t)g * 8 + 4);
    float f[8] = {f0.x, f0.y, f0.z, f0.w, f1.x, f1.y, f1.z, f1.w};
    __align__(16) u32 w[12];
#pragma unroll
    for (int i = 0; i < 4; i++) packA(f[2*i], f[2*i+1], w + 3*i);
    uint4* dd = (uint4*)(d + (size_t)g * 24);
    const uint4* s = (const uint4*)w;
    dd[0] = s[0]; dd[1] = s[1]; dd[2] = s[2];
}
__global__ void conv_w_kernel(const float* __restrict__ w0, const float* __restrict__ w1,
                              const float* __restrict__ w2, const float* __restrict__ w3,
                              u16* __restrict__ dst, int n8) {
    int g = blockIdx.x * blockDim.x + threadIdx.x;
    if (g >= n8) return;
    int sel = blockIdx.y;
    const float* src = (sel == 0) ? w0 : (sel == 1) ? w1 : (sel == 2) ? w2 : w3;
    u16* d = dst + (size_t)sel * F_DIM * TRIP;
    float4 f0 = *(const float4*)(src + (size_t)g * 8);
    float4 f1 = *(const float4*)(src + (size_t)g * 8 + 4);
    float f[8] = {f0.x, f0.y, f0.z, f0.w, f1.x, f1.y, f1.z, f1.w};
    __align__(16) u32 w[12];
#pragma unroll
    for (int i = 0; i < 4; i++) packB(f[2*i], f[2*i+1], w + 3*i);
    uint4* dd = (uint4*)(d + (size_t)g * 24);
    const uint4* s = (const uint4*)w;
    dd[0] = s[0]; dd[1] = s[1]; dd[2] = s[2];
}

// ---------------------------------------------------------------------------
// Projection GEMM. BM=128, BN=64; k-chunk = 32 floats (96 k'); 16 chunks.
// 8 warps = 4m x 2n, warp tile 32x32. cp.async double-buffered. ldmx4 B.
// MODE 0: fp32 flat out; 1: Q (A-pat, rope, 1/8); 2: K (B-pat, rope); 3: V (B-pat, T)
// ---------------------------------------------------------------------------
#define SAP  208
#define PSTG (192 * SAP)
#define PROJ_SMEM (2 * PSTG)            // 79872

template <int MODE>
__global__ __launch_bounds__(256) void proj_kernel(
    const u16* __restrict__ Ab, const u16* __restrict__ Wb,
    const float* __restrict__ bias, void* __restrict__ outp)
{
    extern __shared__ char smem[];
    u32 sb = s2u(smem);
    int tid = threadIdx.x, lane = tid & 31, wid = tid >> 5;
    int m0 = blockIdx.y * 128, n0 = blockIdx.x * 64;
    int wm = (wid & 3) * 32, wn = (wid >> 2) * 32;

    const char* Abase = (const char*)Ab;
    const char* Wbase = (const char*)Wb;
    int arow = tid >> 1, acol = (tid & 1) * 96;
    int wrow = tid >> 2, wcol = (tid & 3) * 48;

    auto loadStage = [&](int c, int stg) {
        u32 base = sb + stg * PSTG;
        const char* asrc = Abase + ((size_t)(m0 + arow) * TRIP + c * 96) * 2 + acol;
        u32 adst = base + arow * SAP + acol;
#pragma unroll
        for (int i = 0; i < 6; i++) CPA16(adst + i * 16, asrc + i * 16);
        const char* wsrc = Wbase + ((size_t)(n0 + wrow) * TRIP + c * 96) * 2 + wcol;
        u32 wdst = base + 128 * SAP + wrow * SAP + wcol;
#pragma unroll
        for (int i = 0; i < 3; i++) CPA16(wdst + i * 16, wsrc + i * 16);
        CPCOMMIT();
    };

    float acc[2][4][4];
#pragma unroll
    for (int i = 0; i < 2; i++)
#pragma unroll
        for (int j = 0; j < 4; j++)
#pragma unroll
            for (int e = 0; e < 4; e++) acc[i][j][e] = 0.f;

    loadStage(0, 0);
    for (int c = 0; c < 16; c++) {
        if (c < 15) { loadStage(c + 1, (c + 1) & 1); CPWAIT(1); }
        else CPWAIT(0);
        __syncthreads();
        u32 abase = sb + (c & 1) * PSTG;
        u32 wbase = abase + 128 * SAP;
#pragma unroll
        for (int ks = 0; ks < 6; ks++) {
            u32 af[2][4], bf[2][4];
#pragma unroll
            for (int i = 0; i < 2; i++)
                ldmx4(af[i], addrA(abase, SAP, wm + i * 16, ks * 16, lane));
#pragma unroll
            for (int j = 0; j < 2; j++)
                ldmx4(bf[j], addrB16(wbase, SAP, wn + j * 16, ks * 16, lane));
#pragma unroll
            for (int i = 0; i < 2; i++)
#pragma unroll
                for (int j = 0; j < 2; j++) {
                    mma16816(acc[i][2*j],     af[i], bf[j]);
                    mma16816(acc[i][2*j + 1], af[i], bf[j] + 2);
                }
        }
        __syncthreads();
    }

    // epilogue
    int rr = lane >> 2, cq = (lane & 3) * 2;
    int head = n0 >> 6;
#pragma unroll
    for (int i = 0; i < 2; i++) {
#pragma unroll
        for (int h2 = 0; h2 < 2; h2++) {
            int m = m0 + wm + i * 16 + rr + h2 * 8;
            int s = m >> 2, b = m & 3;
#pragma unroll
            for (int j = 0; j < 4; j++) {
                int n = wn + j * 8 + cq;
                float v0 = fmaxf(acc[i][j][h2 * 2]     + bias[n0 + n], 0.f);
                float v1 = fmaxf(acc[i][j][h2 * 2 + 1] + bias[n0 + n + 1], 0.f);
                if (MODE == 1 || MODE == 2) {
                    if (MODE == 1) { v0 *= 0.125f; v1 *= 0.125f; }
                    int p = (s << 5) + (n >> 1);
                    float cc = g_cos[p], sn = g_sin[p];
                    float e = v0 * cc - v1 * sn;
                    float o = v0 * sn + v1 * cc;
                    v0 = e; v1 = o;
                }
                if (MODE == 0) {
                    *(float2*)&((float*)outp)[(size_t)m * F_DIM + n0 + n] = make_float2(v0, v1);
                } else if (MODE == 1 || MODE == 2) {
                    int bh = b * NHEAD + head;
                    u32 w[3];
                    if (MODE == 1) packA(v0, v1, w); else packB(v0, v1, w);
                    u32* d = (u32*)((u16*)outp + ((size_t)bh * S_LEN + s) * TRIPQ + 3 * n);
                    d[0] = w[0]; d[1] = w[1]; d[2] = w[2];
                } else {
                    int bh = b * NHEAD + head;
                    u16 h0, l0, h1, l1; splitf(v0, h0, l0); splitf(v1, h1, l1);
                    u16* d0 = (u16*)outp + ((size_t)bh * HD + n) * (3 * S_LEN) + 3 * s;
                    u16* d1 = d0 + 3 * S_LEN;
                    d0[0] = h0; d0[1] = h0; d0[2] = l0;
                    d1[0] = h1; d1[1] = h1; d1[2] = l1;
                }
            }
        }
    }
}

// ---------------------------------------------------------------------------
// Flash attention: CTA = 256 queries x 1 head; 512 threads (16 warps).
// Key blocks of 64, double-buffered. Warp owns 16 rows. Q frags in regs.
// smem: P/Q 256x400 (102400) | 2 x (K 64x400 + V 64x400) (102400) = 204800
// ---------------------------------------------------------------------------
#define FSQ 400
#define FKV(stg) (256 * FSQ + (stg) * 2 * 64 * FSQ)
#define FV_REL (64 * FSQ)
#define FLASH_SMEM (256 * FSQ + 4 * 64 * FSQ)   // 204800

__global__ __launch_bounds__(512, 1) void flash_kernel() {
    extern __shared__ char smem[];
    u32 sb = s2u(smem);
    int tid = threadIdx.x, lane = tid & 31, wid = tid >> 5;
    int q0 = blockIdx.x * 256, bh = blockIdx.y;
    int wm = wid * 16;

    // Q load (tripled A-pattern, pre-scaled): 256 rows x 384B
    {
        int r = tid >> 1, c0 = (tid & 1) * 192;
        const char* src = (const char*)g_Qb + ((size_t)(bh * S_LEN) + q0 + r) * (TRIPQ * 2) + c0;
        u32 dst = sb + r * FSQ + c0;
#pragma unroll
        for (int i = 0; i < 12; i++) CPA16(dst + i * 16, src + i * 16);
        CPCOMMIT();
    }
    int kr = tid >> 3, kc = (tid & 7) * 48;
    auto loadKV = [&](int kb, int stg) {
        u32 base = sb + FKV(stg);
        const char* ksrc = (const char*)g_Kb + ((size_t)(bh * S_LEN) + kb * 64 + kr) * (TRIPQ * 2) + kc;
#pragma unroll
        for (int i = 0; i < 3; i++) CPA16(base + kr * FSQ + kc + i * 16, ksrc + i * 16);
        const char* vsrc = (const char*)g_Vb + ((size_t)(bh * HD) + kr) * (3 * S_LEN * 2) + kb * 384 + kc;
#pragma unroll
        for (int i = 0; i < 3; i++) CPA16(base + FV_REL + kr * FSQ + kc + i * 16, vsrc + i * 16);
        CPCOMMIT();
    };

    loadKV(0, 0);
    CPWAIT(1);          // Q done
    __syncthreads();

    u32 qf[12][4];
#pragma unroll
    for (int ks = 0; ks < 12; ks++)
        ldmx4(qf[ks], addrA(sb, FSQ, wm, ks * 16, lane));

    float mi[2] = {-3.0e38f, -3.0e38f}, li[2] = {0.f, 0.f};
    float oacc[8][4];
#pragma unroll
    for (int j = 0; j < 8; j++)
#pragma unroll
        for (int e = 0; e < 4; e++) oacc[j][e] = 0.f;

    for (int kb = 0; kb < 32; kb++) {
        if (kb < 31) { loadKV(kb + 1, (kb + 1) & 1); CPWAIT(1); }
        else CPWAIT(0);
        __syncthreads();
        u32 kbase = sb + FKV(kb & 1);
        u32 vbase = kbase + FV_REL;

        // S = Q K^T
        float sacc[8][4];
#pragma unroll
        for (int j = 0; j < 8; j++)
#pragma unroll
            for (int e = 0; e < 4; e++) sacc[j][e] = 0.f;
#pragma unroll
        for (int ks = 0; ks < 12; ks++) {
#pragma unroll
            for (int j16 = 0; j16 < 4; j16++) {
                u32 bf[4];
                ldmx4(bf, addrB16(kbase, FSQ, j16 * 16, ks * 16, lane));
                mma16816(sacc[2*j16],     qf[ks], bf);
                mma16816(sacc[2*j16 + 1], qf[ks], bf + 2);
            }
        }

        // online softmax
        int rr = lane >> 2, cq = (lane & 3) * 2;
#pragma unroll
        for (int h2 = 0; h2 < 2; h2++) {
            float rmax = -3.0e38f;
#pragma unroll
            for (int j = 0; j < 8; j++)
                rmax = fmaxf(rmax, fmaxf(sacc[j][h2 * 2], sacc[j][h2 * 2 + 1]));
            rmax = fmaxf(rmax, __shfl_xor_sync(0xffffffffu, rmax, 1));
            rmax = fmaxf(rmax, __shfl_xor_sync(0xffffffffu, rmax, 2));
            float mnew = fmaxf(mi[h2], rmax);
            float alpha = __expf(mi[h2] - mnew);
            mi[h2] = mnew;
            float rsum = 0.f;
#pragma unroll
            for (int j = 0; j < 8; j++) {
                float p0 = __expf(sacc[j][h2 * 2] - mnew);
                float p1 = __expf(sacc[j][h2 * 2 + 1] - mnew);
                sacc[j][h2 * 2] = p0; sacc[j][h2 * 2 + 1] = p1;
                rsum += p0 + p1;
            }
            rsum += __shfl_xor_sync(0xffffffffu, rsum, 1);
            rsum += __shfl_xor_sync(0xffffffffu, rsum, 2);
            li[h2] = li[h2] * alpha + rsum;
#pragma unroll
            for (int j = 0; j < 8; j++) {
                oacc[j][h2 * 2] *= alpha; oacc[j][h2 * 2 + 1] *= alpha;
            }
            char* prow = smem + (wm + rr + h2 * 8) * FSQ;
#pragma unroll
            for (int j = 0; j < 8; j++) {
                u32 w[3];
                packA(sacc[j][h2 * 2], sacc[j][h2 * 2 + 1], w);
                u32* pw = (u32*)(prow + 6 * (cq + 8 * j));
                pw[0] = w[0]; pw[1] = w[1]; pw[2] = w[2];
            }
        }
        __syncwarp();

        // O += P V^T
#pragma unroll
        for (int ks = 0; ks < 12; ks++) {
            u32 pf[4];
            ldmx4(pf, addrA(sb, FSQ, wm, ks * 16, lane));
#pragma unroll
            for (int j16 = 0; j16 < 4; j16++) {
                u32 bf[4];
                ldmx4(bf, addrB16(vbase, FSQ, j16 * 16, ks * 16, lane));
                mma16816(oacc[2*j16],     pf, bf);
                mma16816(oacc[2*j16 + 1], pf, bf + 2);
            }
        }
        __syncthreads();
    }

    // epilogue: write tripled A-pattern Y
    int b = bh >> 3, h = bh & 7;
    int rr = lane >> 2, cq = (lane & 3) * 2;
#pragma unroll
    for (int h2 = 0; h2 < 2; h2++) {
        int srow = q0 + wm + rr + h2 * 8;
        int m = srow * B_SZ + b;
        float inv = 1.0f / li[h2];
#pragma unroll
        for (int j = 0; j < 8; j++) {
            int f = h * HD + j * 8 + cq;
            u32 w[3];
            packA(oacc[j][h2 * 2] * inv, oacc[j][h2 * 2 + 1] * inv, w);
            u32* d = (u32*)(g_Yb + (size_t)m * TRIP + 3 * f);
            d[0] = w[0]; d[1] = w[1]; d[2] = w[2];
        }
    }
}

// ---------------------------------------------------------------------------
extern "C" void kernel_launch(void* const* d_in, const int* in_sizes, int n_in,
                              void* d_out, int out_size) {
    const float* q  = (const float*)d_in[0];
    const float* k  = (const float*)d_in[1];
    const float* v  = (const float*)d_in[2];
    const float* Wq = (const float*)d_in[3];
    const float* bq = (const float*)d_in[4];
    const float* Wk = (const float*)d_in[5];
    const float* bk = (const float*)d_in[6];
    const float* Wv = (const float*)d_in[7];
    const float* bv = (const float*)d_in[8];
    const float* Wo = (const float*)d_in[9];
    const float* bo = (const float*)d_in[10];

    u16 *pIn, *pW, *pQ, *pK, *pV, *pY;
    cudaGetSymbolAddress((void**)&pIn, g_inb);
    cudaGetSymbolAddress((void**)&pW,  g_Wb);
    cudaGetSymbolAddress((void**)&pQ,  g_Qb);
    cudaGetSymbolAddress((void**)&pK,  g_Kb);
    cudaGetSymbolAddress((void**)&pV,  g_Vb);
    cudaGetSymbolAddress((void**)&pY,  g_Yb);

    cudaFuncSetAttribute(proj_kernel<0>, cudaFuncAttributeMaxDynamicSharedMemorySize, PROJ_SMEM);
    cudaFuncSetAttribute(proj_kernel<1>, cudaFuncAttributeMaxDynamicSharedMemorySize, PROJ_SMEM);
    cudaFuncSetAttribute(proj_kernel<2>, cudaFuncAttributeMaxDynamicSharedMemorySize, PROJ_SMEM);
    cudaFuncSetAttribute(proj_kernel<3>, cudaFuncAttributeMaxDynamicSharedMemorySize, PROJ_SMEM);
    cudaFuncSetAttribute(flash_kernel,   cudaFuncAttributeMaxDynamicSharedMemorySize, FLASH_SMEM);

    rope_table_kernel<<<256, 256>>>();

    const int nIn8 = M_ROWS * F_DIM / 8;     // 524288
    const int nW8  = F_DIM * F_DIM / 8;      // 32768
    conv_in_kernel<<<dim3(nIn8 / 256, 3), 256>>>(q, k, v, pIn, nIn8);
    conv_w_kernel<<<dim3(nW8 / 256, 4), 256>>>(Wq, Wk, Wv, Wo, pW, nW8);

    dim3 pg(F_DIM / 64, M_ROWS / 128);  // (8, 64)
    proj_kernel<1><<<pg, 256, PROJ_SMEM>>>(pIn,                         pW,                        bq, pQ);
    proj_kernel<2><<<pg, 256, PROJ_SMEM>>>(pIn + (size_t)M_ROWS*TRIP,   pW + (size_t)F_DIM*TRIP,   bk, pK);
    proj_kernel<3><<<pg, 256, PROJ_SMEM>>>(pIn + (size_t)2*M_ROWS*TRIP, pW + (size_t)2*F_DIM*TRIP, bv, pV);

    flash_kernel<<<dim3(S_LEN / 256, NB), 512, FLASH_SMEM>>>();

    proj_kernel<0><<<pg, 256, PROJ_SMEM>>>(pY, pW + (size_t)3*F_DIM*TRIP, bo, d_out);
}

// round 10
// speedup vs baseline: 1.8769x; 1.1225x over previous
#include <cuda_runtime.h>
#include <cstdint>
#include <math.h>

#define S_LEN  2048
#define B_SZ   4
#define F_DIM  512
#define NHEAD  8
#define NB     32
#define HD     64
#define M_ROWS 8192
#define TRIP   1536     // 3*F_DIM k' elements
#define TRIPQ  192      // 3*HD

typedef unsigned short u16;
typedef unsigned int u32;

// tripled-bf16 scratch
__device__ u16 g_inb[(size_t)3 * M_ROWS * TRIP];          // q,k,v A-pattern
__device__ u16 g_Wb[(size_t)4 * F_DIM * TRIP];            // Wq,Wk,Wv,Wo B-pattern
__device__ u16 g_Qb[(size_t)NB * S_LEN * TRIPQ];          // A-pattern, scaled 1/8
__device__ u16 g_Kb[(size_t)NB * S_LEN * TRIPQ];          // B-pattern
__device__ u16 g_Vb[(size_t)NB * HD * (3 * S_LEN)];       // B-pattern, [bh][d][s']
__device__ u16 g_Yb[(size_t)M_ROWS * TRIP];               // A-pattern
__device__ float g_cos[S_LEN * 32];
__device__ float g_sin[S_LEN * 32];

// ---------------- helpers ----------------
__device__ __forceinline__ u32 s2u(const void* p) {
    u32 a;
    asm("{ .reg .u64 t; cvta.to.shared.u64 t, %1; cvt.u32.u64 %0, t; }" : "=r"(a) : "l"(p));
    return a;
}
__device__ __forceinline__ u16 f2bf(float f) {
    u16 r; asm("cvt.rn.bf16.f32 %0, %1;" : "=h"(r) : "f"(f)); return r;
}
__device__ __forceinline__ float bf2f(u16 h) { return __uint_as_float(((u32)h) << 16); }
__device__ __forceinline__ void splitf(float a, u16 &h, u16 &l) {
    h = f2bf(a); l = f2bf(a - bf2f(h));
}
__device__ __forceinline__ void packA(float v0, float v1, u32* w) {
    u16 h0, l0, h1, l1; splitf(v0, h0, l0); splitf(v1, h1, l1);
    w[0] = h0 | ((u32)l0 << 16); w[1] = h0 | ((u32)h1 << 16); w[2] = l1 | ((u32)h1 << 16);
}
__device__ __forceinline__ void packB(float v0, float v1, u32* w) {
    u16 h0, l0, h1, l1; splitf(v0, h0, l0); splitf(v1, h1, l1);
    w[0] = h0 | ((u32)h0 << 16); w[1] = l0 | ((u32)h1 << 16); w[2] = h1 | ((u32)l1 << 16);
}

__device__ __forceinline__ void mma16816(float* d, const u32* a, const u32* b) {
    asm volatile(
        "mma.sync.aligned.m16n8k16.row.col.f32.bf16.bf16.f32 "
        "{%0,%1,%2,%3}, {%4,%5,%6,%7}, {%8,%9}, {%0,%1,%2,%3};"
        : "+f"(d[0]), "+f"(d[1]), "+f"(d[2]), "+f"(d[3])
        : "r"(a[0]), "r"(a[1]), "r"(a[2]), "r"(a[3]), "r"(b[0]), "r"(b[1]));
}
__device__ __forceinline__ void ldmx4(u32* r, u32 a) {
    asm volatile("ldmatrix.sync.aligned.m8n8.x4.shared.b16 {%0,%1,%2,%3}, [%4];"
                 : "=r"(r[0]), "=r"(r[1]), "=r"(r[2]), "=r"(r[3]) : "r"(a));
}
__device__ __forceinline__ u32 addrA(u32 base, int stride, int m0, int k0, int lane) {
    int grp = lane >> 3, li = lane & 7;
    return base + (m0 + li + (grp & 1) * 8) * stride + (k0 + (grp >> 1) * 8) * 2;
}
// B x4: covers n16 x k16 -> (r0,r1) = n0..7 frag, (r2,r3) = n8..15 frag
__device__ __forceinline__ u32 addrB16(u32 base, int stride, int n0, int k0, int lane) {
    int grp = lane >> 3, li = lane & 7;
    return base + (n0 + li + (grp >> 1) * 8) * stride + (k0 + (grp & 1) * 8) * 2;
}
#define CPA16(s, g) asm volatile("cp.async.cg.shared.global [%0], [%1], 16;" :: "r"(s), "l"(g))
#define CPCOMMIT()  asm volatile("cp.async.commit_group;")
#define CPWAIT(n)   asm volatile("cp.async.wait_group %0;" :: "n"(n))

__global__ void rope_table_kernel() {
    int idx = blockIdx.x * blockDim.x + threadIdx.x;
    if (idx >= S_LEN * 32) return;
    int s = idx >> 5, j = idx & 31;
    double ang = (double)s * pow(10000.0, -(double)j / 32.0);
    g_cos[idx] = (float)cos(ang);
    g_sin[idx] = (float)sin(ang);
}

// ---------------------------------------------------------------------------
// conversion pre-pass (merged): grid.y selects tensor
// ---------------------------------------------------------------------------
__global__ void conv_in_kernel(const float* __restrict__ q, const float* __restrict__ k,
                               const float* __restrict__ v, u16* __restrict__ dst, int n8) {
    int g = blockIdx.x * blockDim.x + threadIdx.x;
    if (g >= n8) return;
    int sel = blockIdx.y;
    const float* src = (sel == 0) ? q : (sel == 1) ? k : v;
    u16* d = dst + (size_t)sel * M_ROWS * TRIP;
    float4 f0 = *(const float4*)(src + (size_t)g * 8);
    float4 f1 = *(const float4*)(src + (size_t)g * 8 + 4);
    float f[8] = {f0.x, f0.y, f0.z, f0.w, f1.x, f1.y, f1.z, f1.w};
    __align__(16) u32 w[12];
#pragma unroll
    for (int i = 0; i < 4; i++) packA(f[2*i], f[2*i+1], w + 3*i);
    uint4* dd = (uint4*)(d + (size_t)g * 24);
    const uint4* s = (const uint4*)w;
    dd[0] = s[0]; dd[1] = s[1]; dd[2] = s[2];
}
__global__ void conv_w_kernel(const float* __restrict__ w0, const float* __restrict__ w1,
                              const float* __restrict__ w2, const float* __restrict__ w3,
                              u16* __restrict__ dst, int n8) {
    int g = blockIdx.x * blockDim.x + threadIdx.x;
    if (g >= n8) return;
    int sel = blockIdx.y;
    const float* src = (sel == 0) ? w0 : (sel == 1) ? w1 : (sel == 2) ? w2 : w3;
    u16* d = dst + (size_t)sel * F_DIM * TRIP;
    float4 f0 = *(const float4*)(src + (size_t)g * 8);
    float4 f1 = *(const float4*)(src + (size_t)g * 8 + 4);
    float f[8] = {f0.x, f0.y, f0.z, f0.w, f1.x, f1.y, f1.z, f1.w};
    __align__(16) u32 w[12];
#pragma unroll
    for (int i = 0; i < 4; i++) packB(f[2*i], f[2*i+1], w + 3*i);
    uint4* dd = (uint4*)(d + (size_t)g * 24);
    const uint4* s = (const uint4*)w;
    dd[0] = s[0]; dd[1] = s[1]; dd[2] = s[2];
}

// ---------------------------------------------------------------------------
// Projection GEMM core: BM=128, BN=128; k-chunk = 32 floats (96 k'); 16 chunks.
// 8 warps = 4m x 2n, warp tile 32x64. cp.async double-buffered.
// MODE 0: fp32 flat out; 1: Q (A-pat, rope, 1/8); 2: K (B-pat, rope); 3: V (B-pat, T)
// ---------------------------------------------------------------------------
#define SAP  208
#define PSTG (256 * SAP)                // 53248 (A 128 rows + W 128 rows)
#define PROJ_SMEM (2 * PSTG)            // 106496

template <int MODED>   // -1 = runtime sel+1 (QKV), 0 = Wo
__device__ __forceinline__ void proj_body(
    const u16* __restrict__ Ab, const u16* __restrict__ Wb,
    const float* __restrict__ bias, void* __restrict__ outp, int mode)
{
    extern __shared__ char smem[];
    u32 sb = s2u(smem);
    int tid = threadIdx.x, lane = tid & 31, wid = tid >> 5;
    int m0 = blockIdx.y * 128, n0 = blockIdx.x * 128;
    int wm = (wid & 3) * 32, wn = (wid >> 2) * 64;

    const char* Abase = (const char*)Ab;
    const char* Wbase = (const char*)Wb;
    int arow = tid >> 1, acol = (tid & 1) * 96;   // byte offset within 192B row

    auto loadStage = [&](int c, int stg) {
        u32 base = sb + stg * PSTG;
        const char* asrc = Abase + ((size_t)(m0 + arow) * TRIP + c * 96) * 2 + acol;
        u32 adst = base + arow * SAP + acol;
#pragma unroll
        for (int i = 0; i < 6; i++) CPA16(adst + i * 16, asrc + i * 16);
        const char* wsrc = Wbase + ((size_t)(n0 + arow) * TRIP + c * 96) * 2 + acol;
        u32 wdst = base + 128 * SAP + arow * SAP + acol;
#pragma unroll
        for (int i = 0; i < 6; i++) CPA16(wdst + i * 16, wsrc + i * 16);
        CPCOMMIT();
    };

    float acc[2][8][4];
#pragma unroll
    for (int i = 0; i < 2; i++)
#pragma unroll
        for (int j = 0; j < 8; j++)
#pragma unroll
            for (int e = 0; e < 4; e++) acc[i][j][e] = 0.f;

    loadStage(0, 0);
    for (int c = 0; c < 16; c++) {
        if (c < 15) { loadStage(c + 1, (c + 1) & 1); CPWAIT(1); }
        else CPWAIT(0);
        __syncthreads();
        u32 abase = sb + (c & 1) * PSTG;
        u32 wbase = abase + 128 * SAP;
#pragma unroll
        for (int ks = 0; ks < 6; ks++) {
            u32 af[2][4], bf[4][4];
#pragma unroll
            for (int i = 0; i < 2; i++)
                ldmx4(af[i], addrA(abase, SAP, wm + i * 16, ks * 16, lane));
#pragma unroll
            for (int j = 0; j < 4; j++)
                ldmx4(bf[j], addrB16(wbase, SAP, wn + j * 16, ks * 16, lane));
#pragma unroll
            for (int i = 0; i < 2; i++)
#pragma unroll
                for (int j = 0; j < 4; j++) {
                    mma16816(acc[i][2*j],     af[i], bf[j]);
                    mma16816(acc[i][2*j + 1], af[i], bf[j] + 2);
                }
        }
        __syncthreads();
    }

    // epilogue
    int rr = lane >> 2, cq = (lane & 3) * 2;
#pragma unroll
    for (int i = 0; i < 2; i++) {
#pragma unroll
        for (int h2 = 0; h2 < 2; h2++) {
            int m = m0 + wm + i * 16 + rr + h2 * 8;
            int s = m >> 2, b = m & 3;
#pragma unroll
            for (int j = 0; j < 8; j++) {
                int nn = wn + j * 8 + cq;            // 0..127, even
                int head = (n0 + nn) >> 6, d = nn & 63;
                float v0 = fmaxf(acc[i][j][h2 * 2]     + bias[n0 + nn], 0.f);
                float v1 = fmaxf(acc[i][j][h2 * 2 + 1] + bias[n0 + nn + 1], 0.f);
                int mo = (MODED == 0) ? 0 : mode;
                if (mo == 1 || mo == 2) {
                    if (mo == 1) { v0 *= 0.125f; v1 *= 0.125f; }
                    int p = (s << 5) + (d >> 1);
                    float cc = g_cos[p], sn = g_sin[p];
                    float e = v0 * cc - v1 * sn;
                    float o = v0 * sn + v1 * cc;
                    v0 = e; v1 = o;
                }
                if (mo == 0) {
                    *(float2*)&((float*)outp)[(size_t)m * F_DIM + n0 + nn] = make_float2(v0, v1);
                } else if (mo == 1 || mo == 2) {
                    int bh = b * NHEAD + head;
                    u32 w[3];
                    if (mo == 1) packA(v0, v1, w); else packB(v0, v1, w);
                    u32* dd = (u32*)((u16*)outp + ((size_t)bh * S_LEN + s) * TRIPQ + 3 * d);
                    dd[0] = w[0]; dd[1] = w[1]; dd[2] = w[2];
                } else {
                    int bh = b * NHEAD + head;
                    u16 h0, l0, h1, l1; splitf(v0, h0, l0); splitf(v1, h1, l1);
                    u16* d0 = (u16*)outp + ((size_t)bh * HD + d) * (3 * S_LEN) + 3 * s;
                    u16* d1 = d0 + 3 * S_LEN;
                    d0[0] = h0; d0[1] = h0; d0[2] = l0;
                    d1[0] = h1; d1[1] = h1; d1[2] = l1;
                }
            }
        }
    }
}

// merged Q/K/V projection: blockIdx.z selects tensor
__global__ __launch_bounds__(256, 2) void projqkv_kernel(
    const u16* __restrict__ Ain, const u16* __restrict__ Wall,
    const float* __restrict__ bq, const float* __restrict__ bk,
    const float* __restrict__ bv,
    u16* __restrict__ oq, u16* __restrict__ ok, u16* __restrict__ ov)
{
    int sel = blockIdx.z;
    const u16* Ab = Ain + (size_t)sel * M_ROWS * TRIP;
    const u16* Wb = Wall + (size_t)sel * F_DIM * TRIP;
    const float* bias = (sel == 0) ? bq : (sel == 1) ? bk : bv;
    void* outp = (sel == 0) ? (void*)oq : (sel == 1) ? (void*)ok : (void*)ov;
    proj_body<-1>(Ab, Wb, bias, outp, sel + 1);
}

// output projection
__global__ __launch_bounds__(256, 2) void projo_kernel(
    const u16* __restrict__ Ab, const u16* __restrict__ Wb,
    const float* __restrict__ bias, float* __restrict__ outp)
{
    proj_body<0>(Ab, Wb, bias, outp, 0);
}

// ---------------------------------------------------------------------------
// Flash attention: CTA = 256 queries x 1 head; 512 threads (16 warps).
// Key blocks of 64, double-buffered. Warp owns 16 rows. Q frags in regs.
// smem: P/Q 256x400 (102400) | 2 x (K 64x400 + V 64x400) (102400) = 204800
// ---------------------------------------------------------------------------
#define FSQ 400
#define FKV(stg) (256 * FSQ + (stg) * 2 * 64 * FSQ)
#define FV_REL (64 * FSQ)
#define FLASH_SMEM (256 * FSQ + 4 * 64 * FSQ)   // 204800

__global__ __launch_bounds__(512, 1) void flash_kernel() {
    extern __shared__ char smem[];
    u32 sb = s2u(smem);
    int tid = threadIdx.x, lane = tid & 31, wid = tid >> 5;
    int q0 = blockIdx.x * 256, bh = blockIdx.y;
    int wm = wid * 16;

    // Q load (tripled A-pattern, pre-scaled): 256 rows x 384B
    {
        int r = tid >> 1, c0 = (tid & 1) * 192;
        const char* src = (const char*)g_Qb + ((size_t)(bh * S_LEN) + q0 + r) * (TRIPQ * 2) + c0;
        u32 dst = sb + r * FSQ + c0;
#pragma unroll
        for (int i = 0; i < 12; i++) CPA16(dst + i * 16, src + i * 16);
        CPCOMMIT();
    }
    int kr = tid >> 3, kc = (tid & 7) * 48;
    auto loadKV = [&](int kb, int stg) {
        u32 base = sb + FKV(stg);
        const char* ksrc = (const char*)g_Kb + ((size_t)(bh * S_LEN) + kb * 64 + kr) * (TRIPQ * 2) + kc;
#pragma unroll
        for (int i = 0; i < 3; i++) CPA16(base + kr * FSQ + kc + i * 16, ksrc + i * 16);
        const char* vsrc = (const char*)g_Vb + ((size_t)(bh * HD) + kr) * (3 * S_LEN * 2) + kb * 384 + kc;
#pragma unroll
        for (int i = 0; i < 3; i++) CPA16(base + FV_REL + kr * FSQ + kc + i * 16, vsrc + i * 16);
        CPCOMMIT();
    };

    loadKV(0, 0);
    CPWAIT(1);          // Q done
    __syncthreads();

    u32 qf[12][4];
#pragma unroll
    for (int ks = 0; ks < 12; ks++)
        ldmx4(qf[ks], addrA(sb, FSQ, wm, ks * 16, lane));

    float mi[2] = {-3.0e38f, -3.0e38f}, li[2] = {0.f, 0.f};
    float oacc[8][4];
#pragma unroll
    for (int j = 0; j < 8; j++)
#pragma unroll
        for (int e = 0; e < 4; e++) oacc[j][e] = 0.f;

    for (int kb = 0; kb < 32; kb++) {
        if (kb < 31) { loadKV(kb + 1, (kb + 1) & 1); CPWAIT(1); }
        else CPWAIT(0);
        __syncthreads();
        u32 kbase = sb + FKV(kb & 1);
        u32 vbase = kbase + FV_REL;

        // S = Q K^T
        float sacc[8][4];
#pragma unroll
        for (int j = 0; j < 8; j++)
#pragma unroll
            for (int e = 0; e < 4; e++) sacc[j][e] = 0.f;
#pragma unroll
        for (int ks = 0; ks < 12; ks++) {
#pragma unroll
            for (int j16 = 0; j16 < 4; j16++) {
                u32 bf[4];
                ldmx4(bf, addrB16(kbase, FSQ, j16 * 16, ks * 16, lane));
                mma16816(sacc[2*j16],     qf[ks], bf);
                mma16816(sacc[2*j16 + 1], qf[ks], bf + 2);
            }
        }

        // online softmax
        int rr = lane >> 2, cq = (lane & 3) * 2;
#pragma unroll
        for (int h2 = 0; h2 < 2; h2++) {
            float rmax = -3.0e38f;
#pragma unroll
            for (int j = 0; j < 8; j++)
                rmax = fmaxf(rmax, fmaxf(sacc[j][h2 * 2], sacc[j][h2 * 2 + 1]));
            rmax = fmaxf(rmax, __shfl_xor_sync(0xffffffffu, rmax, 1));
            rmax = fmaxf(rmax, __shfl_xor_sync(0xffffffffu, rmax, 2));
            float mnew = fmaxf(mi[h2], rmax);
            float alpha = __expf(mi[h2] - mnew);
            mi[h2] = mnew;
            float rsum = 0.f;
#pragma unroll
            for (int j = 0; j < 8; j++) {
                float p0 = __expf(sacc[j][h2 * 2] - mnew);
                float p1 = __expf(sacc[j][h2 * 2 + 1] - mnew);
                sacc[j][h2 * 2] = p0; sacc[j][h2 * 2 + 1] = p1;
                rsum += p0 + p1;
            }
            rsum += __shfl_xor_sync(0xffffffffu, rsum, 1);
            rsum += __shfl_xor_sync(0xffffffffu, rsum, 2);
            li[h2] = li[h2] * alpha + rsum;
#pragma unroll
            for (int j = 0; j < 8; j++) {
                oacc[j][h2 * 2] *= alpha; oacc[j][h2 * 2 + 1] *= alpha;
            }
            char* prow = smem + (wm + rr + h2 * 8) * FSQ;
#pragma unroll
            for (int j = 0; j < 8; j++) {
                u32 w[3];
                packA(sacc[j][h2 * 2], sacc[j][h2 * 2 + 1], w);
                u32* pw = (u32*)(prow + 6 * (cq + 8 * j));
                pw[0] = w[0]; pw[1] = w[1]; pw[2] = w[2];
            }
        }
        __syncwarp();

        // O += P V^T
#pragma unroll
        for (int ks = 0; ks < 12; ks++) {
            u32 pf[4];
            ldmx4(pf, addrA(sb, FSQ, wm, ks * 16, lane));
#pragma unroll
            for (int j16 = 0; j16 < 4; j16++) {
                u32 bf[4];
                ldmx4(bf, addrB16(vbase, FSQ, j16 * 16, ks * 16, lane));
                mma16816(oacc[2*j16],     pf, bf);
                mma16816(oacc[2*j16 + 1], pf, bf + 2);
            }
        }
        __syncthreads();
    }

    // epilogue: write tripled A-pattern Y
    int b = bh >> 3, h = bh & 7;
    int rr = lane >> 2, cq = (lane & 3) * 2;
#pragma unroll
    for (int h2 = 0; h2 < 2; h2++) {
        int srow = q0 + wm + rr + h2 * 8;
        int m = srow * B_SZ + b;
        float inv = 1.0f / li[h2];
#pragma unroll
        for (int j = 0; j < 8; j++) {
            int f = h * HD + j * 8 + cq;
            u32 w[3];
            packA(oacc[j][h2 * 2] * inv, oacc[j][h2 * 2 + 1] * inv, w);
            u32* d = (u32*)(g_Yb + (size_t)m * TRIP + 3 * f);
            d[0] = w[0]; d[1] = w[1]; d[2] = w[2];
        }
    }
}

// ---------------------------------------------------------------------------
extern "C" void kernel_launch(void* const* d_in, const int* in_sizes, int n_in,
                              void* d_out, int out_size) {
    const float* q  = (const float*)d_in[0];
    const float* k  = (const float*)d_in[1];
    const float* v  = (const float*)d_in[2];
    const float* Wq = (const float*)d_in[3];
    const float* bq = (const float*)d_in[4];
    const float* Wk = (const float*)d_in[5];
    const float* bk = (const float*)d_in[6];
    const float* Wv = (const float*)d_in[7];
    const float* bv = (const float*)d_in[8];
    const float* Wo = (const float*)d_in[9];
    const float* bo = (const float*)d_in[10];

    u16 *pIn, *pW, *pQ, *pK, *pV, *pY;
    cudaGetSymbolAddress((void**)&pIn, g_inb);
    cudaGetSymbolAddress((void**)&pW,  g_Wb);
    cudaGetSymbolAddress((void**)&pQ,  g_Qb);
    cudaGetSymbolAddress((void**)&pK,  g_Kb);
    cudaGetSymbolAddress((void**)&pV,  g_Vb);
    cudaGetSymbolAddress((void**)&pY,  g_Yb);

    cudaFuncSetAttribute(projqkv_kernel, cudaFuncAttributeMaxDynamicSharedMemorySize, PROJ_SMEM);
    cudaFuncSetAttribute(projo_kernel,   cudaFuncAttributeMaxDynamicSharedMemorySize, PROJ_SMEM);
    cudaFuncSetAttribute(flash_kernel,   cudaFuncAttributeMaxDynamicSharedMemorySize, FLASH_SMEM);

    rope_table_kernel<<<256, 256>>>();

    const int nIn8 = M_ROWS * F_DIM / 8;     // 524288
    const int nW8  = F_DIM * F_DIM / 8;      // 32768
    conv_in_kernel<<<dim3(nIn8 / 256, 3), 256>>>(q, k, v, pIn, nIn8);
    conv_w_kernel<<<dim3(nW8 / 256, 4), 256>>>(Wq, Wk, Wv, Wo, pW, nW8);

    dim3 pg(F_DIM / 128, M_ROWS / 128, 3);   // (4, 64, 3)
    projqkv_kernel<<<pg, 256, PROJ_SMEM>>>(pIn, pW, bq, bk, bv, pQ, pK, pV);

    flash_kernel<<<dim3(S_LEN / 256, NB), 512, FLASH_SMEM>>>();

    projo_kernel<<<dim3(F_DIM / 128, M_ROWS / 128), 256, PROJ_SMEM>>>(
        pY, pW + (size_t)3 * F_DIM * TRIP, bo, (float*)d_out);
}

// round 12
// speedup vs baseline: 2.6280x; 1.4001x over previous
#include <cuda_runtime.h>
#include <cstdint>
#include <math.h>

#define S_LEN  2048
#define B_SZ   4
#define F_DIM  512
#define NHEAD  8
#define NB     32
#define HD     64
#define M_ROWS 8192
#define TRIP   1536     // 3*F_DIM k' elements
#define TRIPQ  192      // 3*HD

typedef unsigned short u16;
typedef unsigned int u32;

// scratch
__device__ u16 g_inb[(size_t)3 * M_ROWS * TRIP];          // q,k,v A-pattern (tripled)
__device__ u16 g_Wb[(size_t)4 * F_DIM * TRIP];            // weights B-pattern (tripled)
__device__ u16 g_Qb[(size_t)NB * S_LEN * TRIPQ];          // A-pattern tripled, scaled 1/8
__device__ u16 g_Kb[(size_t)NB * S_LEN * TRIPQ];          // B-pattern tripled
__device__ u16 g_Vb[(size_t)NB * HD * S_LEN];             // PLAIN bf16, [bh][d][s]
__device__ u16 g_Yb[(size_t)M_ROWS * TRIP];               // A-pattern tripled
__device__ float g_cos[S_LEN * 32];
__device__ float g_sin[S_LEN * 32];

// ---------------- helpers ----------------
__device__ __forceinline__ u32 s2u(const void* p) {
    u32 a;
    asm("{ .reg .u64 t; cvta.to.shared.u64 t, %1; cvt.u32.u64 %0, t; }" : "=r"(a) : "l"(p));
    return a;
}
__device__ __forceinline__ u16 f2bf(float f) {
    u16 r; asm("cvt.rn.bf16.f32 %0, %1;" : "=h"(r) : "f"(f)); return r;
}
__device__ __forceinline__ float bf2f(u16 h) { return __uint_as_float(((u32)h) << 16); }
__device__ __forceinline__ void splitf(float a, u16 &h, u16 &l) {
    h = f2bf(a); l = f2bf(a - bf2f(h));
}
__device__ __forceinline__ void packA(float v0, float v1, u32* w) {
    u16 h0, l0, h1, l1; splitf(v0, h0, l0); splitf(v1, h1, l1);
    w[0] = h0 | ((u32)l0 << 16); w[1] = h0 | ((u32)h1 << 16); w[2] = l1 | ((u32)h1 << 16);
}
__device__ __forceinline__ void packB(float v0, float v1, u32* w) {
    u16 h0, l0, h1, l1; splitf(v0, h0, l0); splitf(v1, h1, l1);
    w[0] = h0 | ((u32)h0 << 16); w[1] = l0 | ((u32)h1 << 16); w[2] = h1 | ((u32)l1 << 16);
}
// pack (lo, hi) floats -> bf16x2 u32
__device__ __forceinline__ u32 pk2(float lo, float hi) {
    u32 d; asm("cvt.rn.bf16x2.f32 %0, %1, %2;" : "=r"(d) : "f"(hi), "f"(lo)); return d;
}

__device__ __forceinline__ void mma16816(float* d, const u32* a, const u32* b) {
    asm volatile(
        "mma.sync.aligned.m16n8k16.row.col.f32.bf16.bf16.f32 "
        "{%0,%1,%2,%3}, {%4,%5,%6,%7}, {%8,%9}, {%0,%1,%2,%3};"
        : "+f"(d[0]), "+f"(d[1]), "+f"(d[2]), "+f"(d[3])
        : "r"(a[0]), "r"(a[1]), "r"(a[2]), "r"(a[3]), "r"(b[0]), "r"(b[1]));
}
__device__ __forceinline__ void ldmx4(u32* r, u32 a) {
    asm volatile("ldmatrix.sync.aligned.m8n8.x4.shared.b16 {%0,%1,%2,%3}, [%4];"
                 : "=r"(r[0]), "=r"(r[1]), "=r"(r[2]), "=r"(r[3]) : "r"(a));
}
__device__ __forceinline__ u32 addrA(u32 base, int stride, int m0, int k0, int lane) {
    int grp = lane >> 3, li = lane & 7;
    return base + (m0 + li + (grp & 1) * 8) * stride + (k0 + (grp >> 1) * 8) * 2;
}
__device__ __forceinline__ u32 addrB16(u32 base, int stride, int n0, int k0, int lane) {
    int grp = lane >> 3, li = lane & 7;
    return base + (n0 + li + (grp >> 1) * 8) * stride + (k0 + (grp & 1) * 8) * 2;
}
#define CPA16(s, g) asm volatile("cp.async.cg.shared.global [%0], [%1], 16;" :: "r"(s), "l"(g))
#define CPCOMMIT()  asm volatile("cp.async.commit_group;")
#define CPWAIT(n)   asm volatile("cp.async.wait_group %0;" :: "n"(n))

__global__ void rope_table_kernel() {
    int idx = blockIdx.x * blockDim.x + threadIdx.x;
    if (idx >= S_LEN * 32) return;
    int s = idx >> 5, j = idx & 31;
    double ang = (double)s * pow(10000.0, -(double)j / 32.0);
    g_cos[idx] = (float)cos(ang);
    g_sin[idx] = (float)sin(ang);
}

// ---------------------------------------------------------------------------
// conversion pre-pass (merged): grid.y selects tensor
// ---------------------------------------------------------------------------
__global__ void conv_in_kernel(const float* __restrict__ q, const float* __restrict__ k,
                               const float* __restrict__ v, u16* __restrict__ dst, int n8) {
    int g = blockIdx.x * blockDim.x + threadIdx.x;
    if (g >= n8) return;
    int sel = blockIdx.y;
    const float* src = (sel == 0) ? q : (sel == 1) ? k : v;
    u16* d = dst + (size_t)sel * M_ROWS * TRIP;
    float4 f0 = *(const float4*)(src + (size_t)g * 8);
    float4 f1 = *(const float4*)(src + (size_t)g * 8 + 4);
    float f[8] = {f0.x, f0.y, f0.z, f0.w, f1.x, f1.y, f1.z, f1.w};
    __align__(16) u32 w[12];
#pragma unroll
    for (int i = 0; i < 4; i++) packA(f[2*i], f[2*i+1], w + 3*i);
    uint4* dd = (uint4*)(d + (size_t)g * 24);
    const uint4* s = (const uint4*)w;
    dd[0] = s[0]; dd[1] = s[1]; dd[2] = s[2];
}
__global__ void conv_w_kernel(const float* __restrict__ w0, const float* __restrict__ w1,
                              const float* __restrict__ w2, const float* __restrict__ w3,
                              u16* __restrict__ dst, int n8) {
    int g = blockIdx.x * blockDim.x + threadIdx.x;
    if (g >= n8) return;
    int sel = blockIdx.y;
    const float* src = (sel == 0) ? w0 : (sel == 1) ? w1 : (sel == 2) ? w2 : w3;
    u16* d = dst + (size_t)sel * F_DIM * TRIP;
    float4 f0 = *(const float4*)(src + (size_t)g * 8);
    float4 f1 = *(const float4*)(src + (size_t)g * 8 + 4);
    float f[8] = {f0.x, f0.y, f0.z, f0.w, f1.x, f1.y, f1.z, f1.w};
    __align__(16) u32 w[12];
#pragma unroll
    for (int i = 0; i < 4; i++) packB(f[2*i], f[2*i+1], w + 3*i);
    uint4* dd = (uint4*)(d + (size_t)g * 24);
    const uint4* s = (const uint4*)w;
    dd[0] = s[0]; dd[1] = s[1]; dd[2] = s[2];
}

// ---------------------------------------------------------------------------
// Projection GEMM core: BM=128, BN=128; k-chunk = 32 floats (96 k'); 16 chunks.
// 8 warps = 4m x 2n, warp tile 32x64. cp.async double-buffered.
// mode 0: fp32 flat; 1: Q (tripled A-pat, rope, 1/8); 2: K (tripled B-pat, rope);
// mode 3: V plain bf16 transposed [bh][d][s]
// ---------------------------------------------------------------------------
#define SAP  208
#define PSTG (256 * SAP)
#define PROJ_SMEM (2 * PSTG)            // 106496

template <int MODED>
__device__ __forceinline__ void proj_body(
    const u16* __restrict__ Ab, const u16* __restrict__ Wb,
    const float* __restrict__ bias, void* __restrict__ outp, int mode)
{
    extern __shared__ char smem[];
    u32 sb = s2u(smem);
    int tid = threadIdx.x, lane = tid & 31, wid = tid >> 5;
    int m0 = blockIdx.y * 128, n0 = blockIdx.x * 128;
    int wm = (wid & 3) * 32, wn = (wid >> 2) * 64;

    const char* Abase = (const char*)Ab;
    const char* Wbase = (const char*)Wb;
    int arow = tid >> 1, acol = (tid & 1) * 96;

    auto loadStage = [&](int c, int stg) {
        u32 base = sb + stg * PSTG;
        const char* asrc = Abase + ((size_t)(m0 + arow) * TRIP + c * 96) * 2 + acol;
        u32 adst = base + arow * SAP + acol;
#pragma unroll
        for (int i = 0; i < 6; i++) CPA16(adst + i * 16, asrc + i * 16);
        const char* wsrc = Wbase + ((size_t)(n0 + arow) * TRIP + c * 96) * 2 + acol;
        u32 wdst = base + 128 * SAP + arow * SAP + acol;
#pragma unroll
        for (int i = 0; i < 6; i++) CPA16(wdst + i * 16, wsrc + i * 16);
        CPCOMMIT();
    };

    float acc[2][8][4];
#pragma unroll
    for (int i = 0; i < 2; i++)
#pragma unroll
        for (int j = 0; j < 8; j++)
#pragma unroll
            for (int e = 0; e < 4; e++) acc[i][j][e] = 0.f;

    loadStage(0, 0);
    for (int c = 0; c < 16; c++) {
        if (c < 15) { loadStage(c + 1, (c + 1) & 1); CPWAIT(1); }
        else CPWAIT(0);
        __syncthreads();
        u32 abase = sb + (c & 1) * PSTG;
        u32 wbase = abase + 128 * SAP;
#pragma unroll
        for (int ks = 0; ks < 6; ks++) {
            u32 af[2][4], bf[4][4];
#pragma unroll
            for (int i = 0; i < 2; i++)
                ldmx4(af[i], addrA(abase, SAP, wm + i * 16, ks * 16, lane));
#pragma unroll
            for (int j = 0; j < 4; j++)
                ldmx4(bf[j], addrB16(wbase, SAP, wn + j * 16, ks * 16, lane));
#pragma unroll
            for (int i = 0; i < 2; i++)
#pragma unroll
                for (int j = 0; j < 4; j++) {
                    mma16816(acc[i][2*j],     af[i], bf[j]);
                    mma16816(acc[i][2*j + 1], af[i], bf[j] + 2);
                }
        }
        __syncthreads();
    }

    // epilogue
    int rr = lane >> 2, cq = (lane & 3) * 2;
#pragma unroll
    for (int i = 0; i < 2; i++) {
#pragma unroll
        for (int h2 = 0; h2 < 2; h2++) {
            int m = m0 + wm + i * 16 + rr + h2 * 8;
            int s = m >> 2, b = m & 3;
#pragma unroll
            for (int j = 0; j < 8; j++) {
                int nn = wn + j * 8 + cq;
                int head = (n0 + nn) >> 6, d = nn & 63;
                float v0 = fmaxf(acc[i][j][h2 * 2]     + bias[n0 + nn], 0.f);
                float v1 = fmaxf(acc[i][j][h2 * 2 + 1] + bias[n0 + nn + 1], 0.f);
                int mo = (MODED == 0) ? 0 : mode;
                if (mo == 1 || mo == 2) {
                    if (mo == 1) { v0 *= 0.125f; v1 *= 0.125f; }
                    int p = (s << 5) + (d >> 1);
                    float cc = g_cos[p], sn = g_sin[p];
                    float e = v0 * cc - v1 * sn;
                    float o = v0 * sn + v1 * cc;
                    v0 = e; v1 = o;
                }
                if (mo == 0) {
                    *(float2*)&((float*)outp)[(size_t)m * F_DIM + n0 + nn] = make_float2(v0, v1);
                } else if (mo == 1 || mo == 2) {
                    int bh = b * NHEAD + head;
                    u32 w[3];
                    if (mo == 1) packA(v0, v1, w); else packB(v0, v1, w);
                    u32* dd = (u32*)((u16*)outp + ((size_t)bh * S_LEN + s) * TRIPQ + 3 * d);
                    dd[0] = w[0]; dd[1] = w[1]; dd[2] = w[2];
                } else {   // V plain bf16 transposed [bh][d][s]
                    int bh = b * NHEAD + head;
                    u16* d0 = (u16*)outp + ((size_t)bh * HD + d) * S_LEN + s;
                    d0[0] = f2bf(v0);
                    d0[S_LEN] = f2bf(v1);
                }
            }
        }
    }
}

__global__ __launch_bounds__(256, 2) void projqkv_kernel(
    const u16* __restrict__ Ain, const u16* __restrict__ Wall,
    const float* __restrict__ bq, const float* __restrict__ bk,
    const float* __restrict__ bv,
    u16* __restrict__ oq, u16* __restrict__ ok, u16* __restrict__ ov)
{
    int sel = blockIdx.z;
    const u16* Ab = Ain + (size_t)sel * M_ROWS * TRIP;
    const u16* Wb = Wall + (size_t)sel * F_DIM * TRIP;
    const float* bias = (sel == 0) ? bq : (sel == 1) ? bk : bv;
    void* outp = (sel == 0) ? (void*)oq : (sel == 1) ? (void*)ok : (void*)ov;
    proj_body<-1>(Ab, Wb, bias, outp, sel + 1);
}

__global__ __launch_bounds__(256, 2) void projo_kernel(
    const u16* __restrict__ Ab, const u16* __restrict__ Wb,
    const float* __restrict__ bias, float* __restrict__ outp)
{
    proj_body<0>(Ab, Wb, bias, outp, 0);
}

// ---------------------------------------------------------------------------
// Flash attention: CTA = 256 queries x 1 head; 512 threads (16 warps).
// QK^T tripled (k'=192). PV: P bf16 DIRECT FROM REGISTERS (C-frag == A-frag),
// V plain bf16 (K=64). Key blocks of 64, KV double-buffered.
// smem: Q 256x400 (102400) | 2 x (K 64x400 + V 64x144) = 174080
// ---------------------------------------------------------------------------
#define FSQ 400
#define VSP 144                 // 16B-aligned row stride (was 136: misaligned cp.async)
#define QBYTES (256 * FSQ)
#define KSTG (64 * FSQ)
#define VSTG (64 * VSP)
#define FKV(stg) (QBYTES + (stg) * (KSTG + VSTG))
#define FLASH_SMEM (QBYTES + 2 * (KSTG + VSTG))   // 174080

__global__ __launch_bounds__(512, 1) void flash_kernel() {
    extern __shared__ char smem[];
    u32 sb = s2u(smem);
    int tid = threadIdx.x, lane = tid & 31, wid = tid >> 5;
    int q0 = blockIdx.x * 256, bh = blockIdx.y;
    int wm = wid * 16;

    // Q load (tripled A-pattern, pre-scaled): 256 rows x 384B
    {
        int r = tid >> 1, c0 = (tid & 1) * 192;
        const char* src = (const char*)g_Qb + ((size_t)(bh * S_LEN) + q0 + r) * (TRIPQ * 2) + c0;
        u32 dst = sb + r * FSQ + c0;
#pragma unroll
        for (int i = 0; i < 12; i++) CPA16(dst + i * 16, src + i * 16);
        CPCOMMIT();
    }
    int kr = tid >> 3, kc = (tid & 7) * 48;   // K loader
    int vc = (tid & 7) * 16;                  // V loader (row kr, 16B each)
    auto loadKV = [&](int kb, int stg) {
        u32 base = sb + FKV(stg);
        const char* ksrc = (const char*)g_Kb + ((size_t)(bh * S_LEN) + kb * 64 + kr) * (TRIPQ * 2) + kc;
#pragma unroll
        for (int i = 0; i < 3; i++) CPA16(base + kr * FSQ + kc + i * 16, ksrc + i * 16);
        const char* vsrc = (const char*)g_Vb + (((size_t)(bh * HD) + kr) * S_LEN + kb * 64) * 2 + vc;
        CPA16(base + KSTG + kr * VSP + vc, vsrc);
        CPCOMMIT();
    };

    loadKV(0, 0);
    CPWAIT(1);          // Q done
    __syncthreads();

    u32 qf[12][4];
#pragma unroll
    for (int ks = 0; ks < 12; ks++)
        ldmx4(qf[ks], addrA(sb, FSQ, wm, ks * 16, lane));

    float mi[2] = {-3.0e38f, -3.0e38f}, li[2] = {0.f, 0.f};
    float oacc[8][4];
#pragma unroll
    for (int j = 0; j < 8; j++)
#pragma unroll
        for (int e = 0; e < 4; e++) oacc[j][e] = 0.f;

    for (int kb = 0; kb < 32; kb++) {
        if (kb < 31) { loadKV(kb + 1, (kb + 1) & 1); CPWAIT(1); }
        else CPWAIT(0);
        __syncthreads();
        u32 kbase = sb + FKV(kb & 1);
        u32 vbase = kbase + KSTG;

        // S = Q K^T (tripled, fp32-grade)
        float sacc[8][4];
#pragma unroll
        for (int j = 0; j < 8; j++)
#pragma unroll
            for (int e = 0; e < 4; e++) sacc[j][e] = 0.f;
#pragma unroll
        for (int ks = 0; ks < 12; ks++) {
#pragma unroll
            for (int j16 = 0; j16 < 4; j16++) {
                u32 bf[4];
                ldmx4(bf, addrB16(kbase, FSQ, j16 * 16, ks * 16, lane));
                mma16816(sacc[2*j16],     qf[ks], bf);
                mma16816(sacc[2*j16 + 1], qf[ks], bf + 2);
            }
        }

        // online softmax (rows rr, rr+8); sacc becomes P in-place
        int rr = lane >> 2;
#pragma unroll
        for (int h2 = 0; h2 < 2; h2++) {
            float rmax = -3.0e38f;
#pragma unroll
            for (int j = 0; j < 8; j++)
                rmax = fmaxf(rmax, fmaxf(sacc[j][h2 * 2], sacc[j][h2 * 2 + 1]));
            rmax = fmaxf(rmax, __shfl_xor_sync(0xffffffffu, rmax, 1));
            rmax = fmaxf(rmax, __shfl_xor_sync(0xffffffffu, rmax, 2));
            float mnew = fmaxf(mi[h2], rmax);
            float alpha = __expf(mi[h2] - mnew);
            mi[h2] = mnew;
            float rsum = 0.f;
#pragma unroll
            for (int j = 0; j < 8; j++) {
                float p0 = __expf(sacc[j][h2 * 2] - mnew);
                float p1 = __expf(sacc[j][h2 * 2 + 1] - mnew);
                sacc[j][h2 * 2] = p0; sacc[j][h2 * 2 + 1] = p1;
                rsum += p0 + p1;
            }
            rsum += __shfl_xor_sync(0xffffffffu, rsum, 1);
            rsum += __shfl_xor_sync(0xffffffffu, rsum, 2);
            li[h2] = li[h2] * alpha + rsum;
#pragma unroll
            for (int j = 0; j < 8; j++) {
                oacc[j][h2 * 2] *= alpha; oacc[j][h2 * 2 + 1] *= alpha;
            }
        }

        // O += P V : P A-frags packed straight from registers (C-frag == A-frag)
#pragma unroll
        for (int ks = 0; ks < 4; ks++) {
            u32 pf[4];
            pf[0] = pk2(sacc[2*ks][0],     sacc[2*ks][1]);
            pf[1] = pk2(sacc[2*ks][2],     sacc[2*ks][3]);
            pf[2] = pk2(sacc[2*ks + 1][0], sacc[2*ks + 1][1]);
            pf[3] = pk2(sacc[2*ks + 1][2], sacc[2*ks + 1][3]);
#pragma unroll
            for (int j16 = 0; j16 < 4; j16++) {
                u32 bf[4];
                ldmx4(bf, addrB16(vbase, VSP, j16 * 16, ks * 16, lane));
                mma16816(oacc[2*j16],     pf, bf);
                mma16816(oacc[2*j16 + 1], pf, bf + 2);
            }
        }
        __syncthreads();
    }

    // epilogue: write tripled A-pattern Y
    int b = bh >> 3, h = bh & 7;
    int rr = lane >> 2, cq = (lane & 3) * 2;
#pragma unroll
    for (int h2 = 0; h2 < 2; h2++) {
        int srow = q0 + wm + rr + h2 * 8;
        int m = srow * B_SZ + b;
        float inv = 1.0f / li[h2];
#pragma unroll
        for (int j = 0; j < 8; j++) {
            int f = h * HD + j * 8 + cq;
            u32 w[3];
            packA(oacc[j][h2 * 2] * inv, oacc[j][h2 * 2 + 1] * inv, w);
            u32* d = (u32*)(g_Yb + (size_t)m * TRIP + 3 * f);
            d[0] = w[0]; d[1] = w[1]; d[2] = w[2];
        }
    }
}

// ---------------------------------------------------------------------------
extern "C" void kernel_launch(void* const* d_in, const int* in_sizes, int n_in,
                              void* d_out, int out_size) {
    const float* q  = (const float*)d_in[0];
    const float* k  = (const float*)d_in[1];
    const float* v  = (const float*)d_in[2];
    const float* Wq = (const float*)d_in[3];
    const float* bq = (const float*)d_in[4];
    const float* Wk = (const float*)d_in[5];
    const float* bk = (const float*)d_in[6];
    const float* Wv = (const float*)d_in[7];
    const float* bv = (const float*)d_in[8];
    const float* Wo = (const float*)d_in[9];
    const float* bo = (const float*)d_in[10];

    u16 *pIn, *pW, *pQ, *pK, *pV, *pY;
    cudaGetSymbolAddress((void**)&pIn, g_inb);
    cudaGetSymbolAddress((void**)&pW,  g_Wb);
    cudaGetSymbolAddress((void**)&pQ,  g_Qb);
    cudaGetSymbolAddress((void**)&pK,  g_Kb);
    cudaGetSymbolAddress((void**)&pV,  g_Vb);
    cudaGetSymbolAddress((void**)&pY,  g_Yb);

    cudaFuncSetAttribute(projqkv_kernel, cudaFuncAttributeMaxDynamicSharedMemorySize, PROJ_SMEM);
    cudaFuncSetAttribute(projo_kernel,   cudaFuncAttributeMaxDynamicSharedMemorySize, PROJ_SMEM);
    cudaFuncSetAttribute(flash_kernel,   cudaFuncAttributeMaxDynamicSharedMemorySize, FLASH_SMEM);

    rope_table_kernel<<<256, 256>>>();

    const int nIn8 = M_ROWS * F_DIM / 8;
    const int nW8  = F_DIM * F_DIM / 8;
    conv_in_kernel<<<dim3(nIn8 / 256, 3), 256>>>(q, k, v, pIn, nIn8);
    conv_w_kernel<<<dim3(nW8 / 256, 4), 256>>>(Wq, Wk, Wv, Wo, pW, nW8);

    dim3 pg(F_DIM / 128, M_ROWS / 128, 3);
    projqkv_kernel<<<pg, 256, PROJ_SMEM>>>(pIn, pW, bq, bk, bv, pQ, pK, pV);

    flash_kernel<<<dim3(S_LEN / 256, NB), 512, FLASH_SMEM>>>();

    projo_kernel<<<dim3(F_DIM / 128, M_ROWS / 128), 256, PROJ_SMEM>>>(
        pY, pW + (size_t)3 * F_DIM * TRIP, bo, (float*)d_out);
}

// round 14
// speedup vs baseline: 2.6992x; 1.0271x over previous
#include <cuda_runtime.h>
#include <cstdint>
#include <math.h>

#define S_LEN  2048
#define B_SZ   4
#define F_DIM  512
#define NHEAD  8
#define NB     32
#define HD     64
#define M_ROWS 8192
#define TRIP   1536     // 3*F_DIM k' (3-term split: precision floor)
#define TRIPQ  192      // 3*HD

typedef unsigned short u16;
typedef unsigned int u32;

// scratch
__device__ u16 g_inb[(size_t)3 * M_ROWS * TRIP];          // q,k,v tripled A-pattern
__device__ u16 g_Wb[(size_t)4 * F_DIM * TRIP];            // weights tripled B-pattern
__device__ u16 g_Qb[(size_t)NB * S_LEN * TRIPQ];          // tripled A-pattern, scaled 1/8
__device__ u16 g_Kb[(size_t)NB * S_LEN * TRIPQ];          // tripled B-pattern
__device__ u16 g_Vb[(size_t)NB * HD * S_LEN];             // plain bf16, [bh][d][s]
__device__ u16 g_Yb[(size_t)M_ROWS * TRIP];               // tripled A-pattern
__device__ float g_cos[S_LEN * 32];
__device__ float g_sin[S_LEN * 32];

// ---------------- helpers ----------------
__device__ __forceinline__ u32 s2u(const void* p) {
    u32 a;
    asm("{ .reg .u64 t; cvta.to.shared.u64 t, %1; cvt.u32.u64 %0, t; }" : "=r"(a) : "l"(p));
    return a;
}
__device__ __forceinline__ u16 f2bf(float f) {
    u16 r; asm("cvt.rn.bf16.f32 %0, %1;" : "=h"(r) : "f"(f)); return r;
}
__device__ __forceinline__ float bf2f(u16 h) { return __uint_as_float(((u32)h) << 16); }
__device__ __forceinline__ void splitf(float a, u16 &h, u16 &l) {
    h = f2bf(a); l = f2bf(a - bf2f(h));
}
__device__ __forceinline__ void packA(float v0, float v1, u32* w) {
    u16 h0, l0, h1, l1; splitf(v0, h0, l0); splitf(v1, h1, l1);
    w[0] = h0 | ((u32)l0 << 16); w[1] = h0 | ((u32)h1 << 16); w[2] = l1 | ((u32)h1 << 16);
}
__device__ __forceinline__ void packB(float v0, float v1, u32* w) {
    u16 h0, l0, h1, l1; splitf(v0, h0, l0); splitf(v1, h1, l1);
    w[0] = h0 | ((u32)h0 << 16); w[1] = l0 | ((u32)h1 << 16); w[2] = h1 | ((u32)l1 << 16);
}
__device__ __forceinline__ u32 pk2(float lo, float hi) {
    u32 d; asm("cvt.rn.bf16x2.f32 %0, %1, %2;" : "=r"(d) : "f"(hi), "f"(lo)); return d;
}

__device__ __forceinline__ void mma16816(float* d, const u32* a, const u32* b) {
    asm volatile(
        "mma.sync.aligned.m16n8k16.row.col.f32.bf16.bf16.f32 "
        "{%0,%1,%2,%3}, {%4,%5,%6,%7}, {%8,%9}, {%0,%1,%2,%3};"
        : "+f"(d[0]), "+f"(d[1]), "+f"(d[2]), "+f"(d[3])
        : "r"(a[0]), "r"(a[1]), "r"(a[2]), "r"(a[3]), "r"(b[0]), "r"(b[1]));
}
__device__ __forceinline__ void ldmx4(u32* r, u32 a) {
    asm volatile("ldmatrix.sync.aligned.m8n8.x4.shared.b16 {%0,%1,%2,%3}, [%4];"
                 : "=r"(r[0]), "=r"(r[1]), "=r"(r[2]), "=r"(r[3]) : "r"(a));
}
__device__ __forceinline__ u32 addrA(u32 base, int stride, int m0, int k0, int lane) {
    int grp = lane >> 3, li = lane & 7;
    return base + (m0 + li + (grp & 1) * 8) * stride + (k0 + (grp >> 1) * 8) * 2;
}
__device__ __forceinline__ u32 addrB16(u32 base, int stride, int n0, int k0, int lane) {
    int grp = lane >> 3, li = lane & 7;
    return base + (n0 + li + (grp >> 1) * 8) * stride + (k0 + (grp & 1) * 8) * 2;
}
#define CPA16(s, g) asm volatile("cp.async.cg.shared.global [%0], [%1], 16;" :: "r"(s), "l"(g))
#define CPCOMMIT()  asm volatile("cp.async.commit_group;")
#define CPWAIT(n)   asm volatile("cp.async.wait_group %0;" :: "n"(n))

__global__ void rope_table_kernel() {
    int idx = blockIdx.x * blockDim.x + threadIdx.x;
    if (idx >= S_LEN * 32) return;
    int s = idx >> 5, j = idx & 31;
    double ang = (double)s * pow(10000.0, -(double)j / 32.0);
    g_cos[idx] = (float)cos(ang);
    g_sin[idx] = (float)sin(ang);
}

// ---------------------------------------------------------------------------
// conversion pre-pass: 8 floats -> 24 bf16 (3-term)
// ---------------------------------------------------------------------------
__global__ void conv_in_kernel(const float* __restrict__ q, const float* __restrict__ k,
                               const float* __restrict__ v, u16* __restrict__ dst, int n8) {
    int g = blockIdx.x * blockDim.x + threadIdx.x;
    if (g >= n8) return;
    int sel = blockIdx.y;
    const float* src = (sel == 0) ? q : (sel == 1) ? k : v;
    u16* d = dst + (size_t)sel * M_ROWS * TRIP;
    float4 f0 = *(const float4*)(src + (size_t)g * 8);
    float4 f1 = *(const float4*)(src + (size_t)g * 8 + 4);
    float f[8] = {f0.x, f0.y, f0.z, f0.w, f1.x, f1.y, f1.z, f1.w};
    __align__(16) u32 w[12];
#pragma unroll
    for (int i = 0; i < 4; i++) packA(f[2*i], f[2*i+1], w + 3*i);
    uint4* dd = (uint4*)(d + (size_t)g * 24);
    const uint4* s = (const uint4*)w;
    dd[0] = s[0]; dd[1] = s[1]; dd[2] = s[2];
}
__global__ void conv_w_kernel(const float* __restrict__ w0, const float* __restrict__ w1,
                              const float* __restrict__ w2, const float* __restrict__ w3,
                              u16* __restrict__ dst, int n8) {
    int g = blockIdx.x * blockDim.x + threadIdx.x;
    if (g >= n8) return;
    int sel = blockIdx.y;
    const float* src = (sel == 0) ? w0 : (sel == 1) ? w1 : (sel == 2) ? w2 : w3;
    u16* d = dst + (size_t)sel * F_DIM * TRIP;
    float4 f0 = *(const float4*)(src + (size_t)g * 8);
    float4 f1 = *(const float4*)(src + (size_t)g * 8 + 4);
    float f[8] = {f0.x, f0.y, f0.z, f0.w, f1.x, f1.y, f1.z, f1.w};
    __align__(16) u32 w[12];
#pragma unroll
    for (int i = 0; i < 4; i++) packB(f[2*i], f[2*i+1], w + 3*i);
    uint4* dd = (uint4*)(d + (size_t)g * 24);
    const uint4* s = (const uint4*)w;
    dd[0] = s[0]; dd[1] = s[1]; dd[2] = s[2];
}

// ---------------------------------------------------------------------------
// Projection GEMM core: BM=128, BN=256; k-chunk = 32 floats (96 k'); 16 chunks.
// 8 warps = 2m x 4n, warp tile 64x64 (4 mma per ldmx4). 1 CTA/SM.
// mode 0: fp32 flat; 1: Q (tripled A, rope, 1/8); 2: K (tripled B, rope);
// mode 3: V plain bf16 transposed [bh][d][s]
// ---------------------------------------------------------------------------
#define SAP  208
#define PSTG (384 * SAP)                // A 128 rows + W 256 rows = 79872
#define PROJ_SMEM (2 * PSTG)            // 159744

template <int MODED>
__device__ __forceinline__ void proj_body(
    const u16* __restrict__ Ab, const u16* __restrict__ Wb,
    const float* __restrict__ bias, void* __restrict__ outp, int mode)
{
    extern __shared__ char smem[];
    u32 sb = s2u(smem);
    int tid = threadIdx.x, lane = tid & 31, wid = tid >> 5;
    int m0 = blockIdx.y * 128, n0 = blockIdx.x * 256;
    int wm = (wid & 1) * 64, wn = (wid >> 1) * 64;

    const char* Abase = (const char*)Ab;
    const char* Wbase = (const char*)Wb;
    int arow = tid >> 1, acol = (tid & 1) * 96;

    auto loadStage = [&](int c, int stg) {
        u32 base = sb + stg * PSTG;
        const char* asrc = Abase + ((size_t)(m0 + arow) * TRIP + c * 96) * 2 + acol;
        u32 adst = base + arow * SAP + acol;
#pragma unroll
        for (int i = 0; i < 6; i++) CPA16(adst + i * 16, asrc + i * 16);
        const char* wsrc = Wbase + ((size_t)(n0 + tid) * TRIP + c * 96) * 2;
        u32 wdst = base + 128 * SAP + tid * SAP;
#pragma unroll
        for (int i = 0; i < 12; i++) CPA16(wdst + i * 16, wsrc + i * 16);
        CPCOMMIT();
    };

    float acc[4][8][4];
#pragma unroll
    for (int i = 0; i < 4; i++)
#pragma unroll
        for (int j = 0; j < 8; j++)
#pragma unroll
            for (int e = 0; e < 4; e++) acc[i][j][e] = 0.f;

    loadStage(0, 0);
    for (int c = 0; c < 16; c++) {
        CPWAIT(0);
        __syncthreads();
        if (c < 15) loadStage(c + 1, (c + 1) & 1);
        u32 abase = sb + (c & 1) * PSTG;
        u32 wbase = abase + 128 * SAP;
#pragma unroll
        for (int ks = 0; ks < 6; ks++) {
            u32 af[4][4], bf[4][4];
#pragma unroll
            for (int i = 0; i < 4; i++)
                ldmx4(af[i], addrA(abase, SAP, wm + i * 16, ks * 16, lane));
#pragma unroll
            for (int j = 0; j < 4; j++)
                ldmx4(bf[j], addrB16(wbase, SAP, wn + j * 16, ks * 16, lane));
#pragma unroll
            for (int i = 0; i < 4; i++)
#pragma unroll
                for (int j = 0; j < 4; j++) {
                    mma16816(acc[i][2*j],     af[i], bf[j]);
                    mma16816(acc[i][2*j + 1], af[i], bf[j] + 2);
                }
        }
    }

    // epilogue
    int rr = lane >> 2, cq = (lane & 3) * 2;
#pragma unroll
    for (int i = 0; i < 4; i++) {
#pragma unroll
        for (int h2 = 0; h2 < 2; h2++) {
            int m = m0 + wm + i * 16 + rr + h2 * 8;
            int s = m >> 2, b = m & 3;
#pragma unroll
            for (int j = 0; j < 8; j++) {
                int nn = wn + j * 8 + cq;            // 0..255, even
                int head = (n0 + nn) >> 6, d = nn & 63;
                float v0 = fmaxf(acc[i][j][h2 * 2]     + bias[n0 + nn], 0.f);
                float v1 = fmaxf(acc[i][j][h2 * 2 + 1] + bias[n0 + nn + 1], 0.f);
                int mo = (MODED == 0) ? 0 : mode;
                if (mo == 1 || mo == 2) {
                    if (mo == 1) { v0 *= 0.125f; v1 *= 0.125f; }
                    int p = (s << 5) + (d >> 1);
                    float cc = g_cos[p], sn = g_sin[p];
                    float e = v0 * cc - v1 * sn;
                    float o = v0 * sn + v1 * cc;
                    v0 = e; v1 = o;
                }
                if (mo == 0) {
                    *(float2*)&((float*)outp)[(size_t)m * F_DIM + n0 + nn] = make_float2(v0, v1);
                } else if (mo == 1 || mo == 2) {
                    int bh = b * NHEAD + head;
                    u32 w[3];
                    if (mo == 1) packA(v0, v1, w); else packB(v0, v1, w);
                    u32* dd = (u32*)((u16*)outp + ((size_t)bh * S_LEN + s) * TRIPQ + 3 * d);
                    dd[0] = w[0]; dd[1] = w[1]; dd[2] = w[2];
                } else {   // V plain bf16 transposed [bh][d][s]
                    int bh = b * NHEAD + head;
                    u16* d0 = (u16*)outp + ((size_t)bh * HD + d) * S_LEN + s;
                    d0[0] = f2bf(v0);
                    d0[S_LEN] = f2bf(v1);
                }
            }
        }
    }
}

__global__ __launch_bounds__(256, 1) void projqkv_kernel(
    const u16* __restrict__ Ain, const u16* __restrict__ Wall,
    const float* __restrict__ bq, const float* __restrict__ bk,
    const float* __restrict__ bv,
    u16* __restrict__ oq, u16* __restrict__ ok, u16* __restrict__ ov)
{
    int sel = blockIdx.z;
    const u16* Ab = Ain + (size_t)sel * M_ROWS * TRIP;
    const u16* Wb = Wall + (size_t)sel * F_DIM * TRIP;
    const float* bias = (sel == 0) ? bq : (sel == 1) ? bk : bv;
    void* outp = (sel == 0) ? (void*)oq : (sel == 1) ? (void*)ok : (void*)ov;
    proj_body<-1>(Ab, Wb, bias, outp, sel + 1);
}

__global__ __launch_bounds__(256, 1) void projo_kernel(
    const u16* __restrict__ Ab, const u16* __restrict__ Wb,
    const float* __restrict__ bias, float* __restrict__ outp)
{
    proj_body<0>(Ab, Wb, bias, outp, 0);
}

// ---------------------------------------------------------------------------
// Flash attention: CTA = 256 queries x 1 head; 512 threads (16 warps).
// QK^T tripled (k'=192). PV: P bf16 direct from registers, V plain bf16.
// Key blocks of 64, KV double-buffered, one sync per block.
// smem: Q 256x400 (102400) | 2 x (K 64x400 + V 64x144) = 174080
// ---------------------------------------------------------------------------
#define FSQ 400
#define VSP 144
#define QBYTES (256 * FSQ)
#define KSTG (64 * FSQ)
#define VSTG (64 * VSP)
#define FKV(stg) (QBYTES + (stg) * (KSTG + VSTG))
#define FLASH_SMEM (QBYTES + 2 * (KSTG + VSTG))   // 174080

__global__ __launch_bounds__(512, 1) void flash_kernel() {
    extern __shared__ char smem[];
    u32 sb = s2u(smem);
    int tid = threadIdx.x, lane = tid & 31, wid = tid >> 5;
    int q0 = blockIdx.x * 256, bh = blockIdx.y;
    int wm = wid * 16;

    // Q load (tripled A-pattern, pre-scaled): 256 rows x 384B
    {
        int r = tid >> 1, c0 = (tid & 1) * 192;
        const char* src = (const char*)g_Qb + ((size_t)(bh * S_LEN) + q0 + r) * (TRIPQ * 2) + c0;
        u32 dst = sb + r * FSQ + c0;
#pragma unroll
        for (int i = 0; i < 12; i++) CPA16(dst + i * 16, src + i * 16);
        CPCOMMIT();
    }
    int kr = tid >> 3, kc = (tid & 7) * 48;
    int vc = (tid & 7) * 16;
    auto loadKV = [&](int kb, int stg) {
        u32 base = sb + FKV(stg);
        const char* ksrc = (const char*)g_Kb + ((size_t)(bh * S_LEN) + kb * 64 + kr) * (TRIPQ * 2) + kc;
#pragma unroll
        for (int i = 0; i < 3; i++) CPA16(base + kr * FSQ + kc + i * 16, ksrc + i * 16);
        const char* vsrc = (const char*)g_Vb + (((size_t)(bh * HD) + kr) * S_LEN + kb * 64) * 2 + vc;
        CPA16(base + KSTG + kr * VSP + vc, vsrc);
        CPCOMMIT();
    };

    loadKV(0, 0);
    CPWAIT(0);          // Q + KV0 done
    __syncthreads();

    u32 qf[12][4];
#pragma unroll
    for (int ks = 0; ks < 12; ks++)
        ldmx4(qf[ks], addrA(sb, FSQ, wm, ks * 16, lane));

    float mi[2] = {-3.0e38f, -3.0e38f}, li[2] = {0.f, 0.f};
    float oacc[8][4];
#pragma unroll
    for (int j = 0; j < 8; j++)
#pragma unroll
        for (int e = 0; e < 4; e++) oacc[j][e] = 0.f;

    for (int kb = 0; kb < 32; kb++) {
        if (kb > 0) { CPWAIT(0); __syncthreads(); }
        if (kb < 31) loadKV(kb + 1, (kb + 1) & 1);
        u32 kbase = sb + FKV(kb & 1);
        u32 vbase = kbase + KSTG;

        // S = Q K^T (tripled, fp32-grade)
        float sacc[8][4];
#pragma unroll
        for (int j = 0; j < 8; j++)
#pragma unroll
            for (int e = 0; e < 4; e++) sacc[j][e] = 0.f;
#pragma unroll
        for (int ks = 0; ks < 12; ks++) {
#pragma unroll
            for (int j16 = 0; j16 < 4; j16++) {
                u32 bf[4];
                ldmx4(bf, addrB16(kbase, FSQ, j16 * 16, ks * 16, lane));
                mma16816(sacc[2*j16],     qf[ks], bf);
                mma16816(sacc[2*j16 + 1], qf[ks], bf + 2);
            }
        }

        // online softmax; sacc becomes P in-place
#pragma unroll
        for (int h2 = 0; h2 < 2; h2++) {
            float rmax = -3.0e38f;
#pragma unroll
            for (int j = 0; j < 8; j++)
                rmax = fmaxf(rmax, fmaxf(sacc[j][h2 * 2], sacc[j][h2 * 2 + 1]));
            rmax = fmaxf(rmax, __shfl_xor_sync(0xffffffffu, rmax, 1));
            rmax = fmaxf(rmax, __shfl_xor_sync(0xffffffffu, rmax, 2));
            float mnew = fmaxf(mi[h2], rmax);
            float alpha = __expf(mi[h2] - mnew);
            mi[h2] = mnew;
            float rsum = 0.f;
#pragma unroll
            for (int j = 0; j < 8; j++) {
                float p0 = __expf(sacc[j][h2 * 2] - mnew);
                float p1 = __expf(sacc[j][h2 * 2 + 1] - mnew);
                sacc[j][h2 * 2] = p0; sacc[j][h2 * 2 + 1] = p1;
                rsum += p0 + p1;
            }
            rsum += __shfl_xor_sync(0xffffffffu, rsum, 1);
            rsum += __shfl_xor_sync(0xffffffffu, rsum, 2);
            li[h2] = li[h2] * alpha + rsum;
#pragma unroll
            for (int j = 0; j < 8; j++) {
                oacc[j][h2 * 2] *= alpha; oacc[j][h2 * 2 + 1] *= alpha;
            }
        }

        // O += P V : P A-frags packed straight from registers
#pragma unroll
        for (int ks = 0; ks < 4; ks++) {
            u32 pf[4];
            pf[0] = pk2(sacc[2*ks][0],     sacc[2*ks][1]);
            pf[1] = pk2(sacc[2*ks][2],     sacc[2*ks][3]);
            pf[2] = pk2(sacc[2*ks + 1][0], sacc[2*ks + 1][1]);
            pf[3] = pk2(sacc[2*ks + 1][2], sacc[2*ks + 1][3]);
#pragma unroll
            for (int j16 = 0; j16 < 4; j16++) {
                u32 bf[4];
                ldmx4(bf, addrB16(vbase, VSP, j16 * 16, ks * 16, lane));
                mma16816(oacc[2*j16],     pf, bf);
                mma16816(oacc[2*j16 + 1], pf, bf + 2);
            }
        }
    }

    // epilogue: write tripled A-pattern Y
    int b = bh >> 3, h = bh & 7;
    int rr = lane >> 2, cq = (lane & 3) * 2;
#pragma unroll
    for (int h2 = 0; h2 < 2; h2++) {
        int srow = q0 + wm + rr + h2 * 8;
        int m = srow * B_SZ + b;
        float inv = 1.0f / li[h2];
#pragma unroll
        for (int j = 0; j < 8; j++) {
            int f = h * HD + j * 8 + cq;
            u32 w[3];
            packA(oacc[j][h2 * 2] * inv, oacc[j][h2 * 2 + 1] * inv, w);
            u32* d = (u32*)(g_Yb + (size_t)m * TRIP + 3 * f);
            d[0] = w[0]; d[1] = w[1]; d[2] = w[2];
        }
    }
}

// ---------------------------------------------------------------------------
extern "C" void kernel_launch(void* const* d_in, const int* in_sizes, int n_in,
                              void* d_out, int out_size) {
    const float* q  = (const float*)d_in[0];
    const float* k  = (const float*)d_in[1];
    const float* v  = (const float*)d_in[2];
    const float* Wq = (const float*)d_in[3];
    const float* bq = (const float*)d_in[4];
    const float* Wk = (const float*)d_in[5];
    const float* bk = (const float*)d_in[6];
    const float* Wv = (const float*)d_in[7];
    const float* bv = (const float*)d_in[8];
    const float* Wo = (const float*)d_in[9];
    const float* bo = (const float*)d_in[10];

    u16 *pIn, *pW, *pQ, *pK, *pV, *pY;
    cudaGetSymbolAddress((void**)&pIn, g_inb);
    cudaGetSymbolAddress((void**)&pW,  g_Wb);
    cudaGetSymbolAddress((void**)&pQ,  g_Qb);
    cudaGetSymbolAddress((void**)&pK,  g_Kb);
    cudaGetSymbolAddress((void**)&pV,  g_Vb);
    cudaGetSymbolAddress((void**)&pY,  g_Yb);

    cudaFuncSetAttribute(projqkv_kernel, cudaFuncAttributeMaxDynamicSharedMemorySize, PROJ_SMEM);
    cudaFuncSetAttribute(projo_kernel,   cudaFuncAttributeMaxDynamicSharedMemorySize, PROJ_SMEM);
    cudaFuncSetAttribute(flash_kernel,   cudaFuncAttributeMaxDynamicSharedMemorySize, FLASH_SMEM);

    rope_table_kernel<<<256, 256>>>();

    const int nIn8 = M_ROWS * F_DIM / 8;
    const int nW8  = F_DIM * F_DIM / 8;
    conv_in_kernel<<<dim3(nIn8 / 256, 3), 256>>>(q, k, v, pIn, nIn8);
    conv_w_kernel<<<dim3(nW8 / 256, 4), 256>>>(Wq, Wk, Wv, Wo, pW, nW8);

    dim3 pg(F_DIM / 256, M_ROWS / 128, 3);   // (2, 64, 3)
    projqkv_kernel<<<pg, 256, PROJ_SMEM>>>(pIn, pW, bq, bk, bv, pQ, pK, pV);

    flash_kernel<<<dim3(S_LEN / 256, NB), 512, FLASH_SMEM>>>();

    projo_kernel<<<dim3(F_DIM / 256, M_ROWS / 128), 256, PROJ_SMEM>>>(
        pY, pW + (size_t)3 * F_DIM * TRIP, bo, (float*)d_out);
}

// round 15
// speedup vs baseline: 3.1851x; 1.1800x over previous
#include <cuda_runtime.h>
#include <cstdint>
#include <math.h>

#define S_LEN  2048
#define B_SZ   4
#define F_DIM  512
#define NHEAD  8
#define NB     32
#define HD     64
#define M_ROWS 8192
#define TRIP   1024     // 2*F_DIM k' (2-term fp16 split for projections)
#define TRIPQ  192      // 3*HD (flash QK stays tripled bf16)

typedef unsigned short u16;
typedef unsigned int u32;

// scratch
__device__ u16 g_inb[(size_t)3 * M_ROWS * TRIP];          // q,k,v 2-term fp16 A-pattern
__device__ u16 g_Wb[(size_t)4 * F_DIM * TRIP];            // weights 2-term fp16 B-pattern
__device__ u16 g_Qb[(size_t)NB * S_LEN * TRIPQ];          // tripled bf16 A-pattern, scaled 1/8
__device__ u16 g_Kb[(size_t)NB * S_LEN * TRIPQ];          // tripled bf16 B-pattern
__device__ u16 g_Vb[(size_t)NB * HD * S_LEN];             // plain bf16, [bh][d][s]
__device__ u16 g_Yb[(size_t)M_ROWS * TRIP];               // 2-term fp16 A-pattern
__device__ float g_cos[S_LEN * 32];
__device__ float g_sin[S_LEN * 32];

// ---------------- helpers ----------------
__device__ __forceinline__ u32 s2u(const void* p) {
    u32 a;
    asm("{ .reg .u64 t; cvta.to.shared.u64 t, %1; cvt.u32.u64 %0, t; }" : "=r"(a) : "l"(p));
    return a;
}
// bf16 (flash)
__device__ __forceinline__ u16 f2bf(float f) {
    u16 r; asm("cvt.rn.bf16.f32 %0, %1;" : "=h"(r) : "f"(f)); return r;
}
__device__ __forceinline__ float bf2f(u16 h) { return __uint_as_float(((u32)h) << 16); }
__device__ __forceinline__ void splitf(float a, u16 &h, u16 &l) {
    h = f2bf(a); l = f2bf(a - bf2f(h));
}
__device__ __forceinline__ void packA(float v0, float v1, u32* w) {   // tripled bf16 A
    u16 h0, l0, h1, l1; splitf(v0, h0, l0); splitf(v1, h1, l1);
    w[0] = h0 | ((u32)l0 << 16); w[1] = h0 | ((u32)h1 << 16); w[2] = l1 | ((u32)h1 << 16);
}
__device__ __forceinline__ void packB(float v0, float v1, u32* w) {   // tripled bf16 B
    u16 h0, l0, h1, l1; splitf(v0, h0, l0); splitf(v1, h1, l1);
    w[0] = h0 | ((u32)h0 << 16); w[1] = l0 | ((u32)h1 << 16); w[2] = h1 | ((u32)l1 << 16);
}
__device__ __forceinline__ u32 pk2(float lo, float hi) {              // bf16x2
    u32 d; asm("cvt.rn.bf16x2.f32 %0, %1, %2;" : "=r"(d) : "f"(hi), "f"(lo)); return d;
}
// fp16 (projections)
__device__ __forceinline__ u16 f2h(float f) {
    u16 r; asm("cvt.rn.f16.f32 %0, %1;" : "=h"(r) : "f"(f)); return r;
}
__device__ __forceinline__ float h2f(u16 h) {
    float f; asm("cvt.f32.f16 %0, %1;" : "=f"(f) : "h"(h)); return f;
}
__device__ __forceinline__ void packA2h(float v0, float v1, u32* w) { // 2-term fp16 A
    u16 h0 = f2h(v0), h1 = f2h(v1);
    u16 l0 = f2h(v0 - h2f(h0)), l1 = f2h(v1 - h2f(h1));
    w[0] = h0 | ((u32)l0 << 16); w[1] = h1 | ((u32)l1 << 16);
}
__device__ __forceinline__ void packB2h(float v0, float v1, u32* w) { // 2-term fp16 B
    u16 h0 = f2h(v0), h1 = f2h(v1);
    w[0] = h0 | ((u32)h0 << 16); w[1] = h1 | ((u32)h1 << 16);
}

__device__ __forceinline__ void mma_bf(float* d, const u32* a, const u32* b) {
    asm volatile(
        "mma.sync.aligned.m16n8k16.row.col.f32.bf16.bf16.f32 "
        "{%0,%1,%2,%3}, {%4,%5,%6,%7}, {%8,%9}, {%0,%1,%2,%3};"
        : "+f"(d[0]), "+f"(d[1]), "+f"(d[2]), "+f"(d[3])
        : "r"(a[0]), "r"(a[1]), "r"(a[2]), "r"(a[3]), "r"(b[0]), "r"(b[1]));
}
__device__ __forceinline__ void mma_fp(float* d, const u32* a, const u32* b) {
    asm volatile(
        "mma.sync.aligned.m16n8k16.row.col.f32.f16.f16.f32 "
        "{%0,%1,%2,%3}, {%4,%5,%6,%7}, {%8,%9}, {%0,%1,%2,%3};"
        : "+f"(d[0]), "+f"(d[1]), "+f"(d[2]), "+f"(d[3])
        : "r"(a[0]), "r"(a[1]), "r"(a[2]), "r"(a[3]), "r"(b[0]), "r"(b[1]));
}
__device__ __forceinline__ void ldmx4(u32* r, u32 a) {
    asm volatile("ldmatrix.sync.aligned.m8n8.x4.shared.b16 {%0,%1,%2,%3}, [%4];"
                 : "=r"(r[0]), "=r"(r[1]), "=r"(r[2]), "=r"(r[3]) : "r"(a));
}
__device__ __forceinline__ u32 addrA(u32 base, int stride, int m0, int k0, int lane) {
    int grp = lane >> 3, li = lane & 7;
    return base + (m0 + li + (grp & 1) * 8) * stride + (k0 + (grp >> 1) * 8) * 2;
}
__device__ __forceinline__ u32 addrB16(u32 base, int stride, int n0, int k0, int lane) {
    int grp = lane >> 3, li = lane & 7;
    return base + (n0 + li + (grp >> 1) * 8) * stride + (k0 + (grp & 1) * 8) * 2;
}
#define CPA16(s, g) asm volatile("cp.async.cg.shared.global [%0], [%1], 16;" :: "r"(s), "l"(g))
#define CPCOMMIT()  asm volatile("cp.async.commit_group;")
#define CPWAIT(n)   asm volatile("cp.async.wait_group %0;" :: "n"(n))

__global__ void rope_table_kernel() {
    int idx = blockIdx.x * blockDim.x + threadIdx.x;
    if (idx >= S_LEN * 32) return;
    int s = idx >> 5, j = idx & 31;
    double ang = (double)s * pow(10000.0, -(double)j / 32.0);
    g_cos[idx] = (float)cos(ang);
    g_sin[idx] = (float)sin(ang);
}

// ---------------------------------------------------------------------------
// conversion pre-pass: 8 floats -> 16 fp16 (2-term)
// ---------------------------------------------------------------------------
__global__ void conv_in_kernel(const float* __restrict__ q, const float* __restrict__ k,
                               const float* __restrict__ v, u16* __restrict__ dst, int n8) {
    int g = blockIdx.x * blockDim.x + threadIdx.x;
    if (g >= n8) return;
    int sel = blockIdx.y;
    const float* src = (sel == 0) ? q : (sel == 1) ? k : v;
    u16* d = dst + (size_t)sel * M_ROWS * TRIP;
    float4 f0 = *(const float4*)(src + (size_t)g * 8);
    float4 f1 = *(const float4*)(src + (size_t)g * 8 + 4);
    float f[8] = {f0.x, f0.y, f0.z, f0.w, f1.x, f1.y, f1.z, f1.w};
    __align__(16) u32 w[8];
#pragma unroll
    for (int i = 0; i < 4; i++) packA2h(f[2*i], f[2*i+1], w + 2*i);
    uint4* dd = (uint4*)(d + (size_t)g * 16);
    const uint4* s = (const uint4*)w;
    dd[0] = s[0]; dd[1] = s[1];
}
__global__ void conv_w_kernel(const float* __restrict__ w0, const float* __restrict__ w1,
                              const float* __restrict__ w2, const float* __restrict__ w3,
                              u16* __restrict__ dst, int n8) {
    int g = blockIdx.x * blockDim.x + threadIdx.x;
    if (g >= n8) return;
    int sel = blockIdx.y;
    const float* src = (sel == 0) ? w0 : (sel == 1) ? w1 : (sel == 2) ? w2 : w3;
    u16* d = dst + (size_t)sel * F_DIM * TRIP;
    float4 f0 = *(const float4*)(src + (size_t)g * 8);
    float4 f1 = *(const float4*)(src + (size_t)g * 8 + 4);
    float f[8] = {f0.x, f0.y, f0.z, f0.w, f1.x, f1.y, f1.z, f1.w};
    __align__(16) u32 w[8];
#pragma unroll
    for (int i = 0; i < 4; i++) packB2h(f[2*i], f[2*i+1], w + 2*i);
    uint4* dd = (uint4*)(d + (size_t)g * 16);
    const uint4* s = (const uint4*)w;
    dd[0] = s[0]; dd[1] = s[1];
}

// ---------------------------------------------------------------------------
// Projection GEMM core (fp16 2-term): BM=128, BN=256; k-chunk = 64 floats
// (128 k'); 8 chunks. 8 warps = 2m x 4n, warp tile 64x64. Double-buffered.
// mode 0: fp32 flat; 1: Q (tripled bf16 A, rope, 1/8); 2: K (tripled bf16 B,
// rope); 3: V plain bf16 transposed [bh][d][s]
// ---------------------------------------------------------------------------
#define SAP  272                        // 256B row + 16 pad
#define PSTG (384 * SAP)                // 104448
#define PROJ_SMEM (2 * PSTG)            // 208896

template <int MODED>
__device__ __forceinline__ void proj_body(
    const u16* __restrict__ Ab, const u16* __restrict__ Wb,
    const float* __restrict__ bias, void* __restrict__ outp, int mode)
{
    extern __shared__ char smem[];
    u32 sb = s2u(smem);
    int tid = threadIdx.x, lane = tid & 31, wid = tid >> 5;
    int m0 = blockIdx.y * 128, n0 = blockIdx.x * 256;
    int wm = (wid & 1) * 64, wn = (wid >> 1) * 64;

    const char* Abase = (const char*)Ab;
    const char* Wbase = (const char*)Wb;
    int arow = tid >> 1, acol = (tid & 1) * 128;

    auto loadStage = [&](int c, int stg) {
        u32 base = sb + stg * PSTG;
        const char* asrc = Abase + ((size_t)(m0 + arow) * TRIP + c * 128) * 2 + acol;
        u32 adst = base + arow * SAP + acol;
#pragma unroll
        for (int i = 0; i < 8; i++) CPA16(adst + i * 16, asrc + i * 16);
        const char* wsrc = Wbase + ((size_t)(n0 + tid) * TRIP + c * 128) * 2;
        u32 wdst = base + 128 * SAP + tid * SAP;
#pragma unroll
        for (int i = 0; i < 16; i++) CPA16(wdst + i * 16, wsrc + i * 16);
        CPCOMMIT();
    };

    float acc[4][8][4];
#pragma unroll
    for (int i = 0; i < 4; i++)
#pragma unroll
        for (int j = 0; j < 8; j++)
#pragma unroll
            for (int e = 0; e < 4; e++) acc[i][j][e] = 0.f;

    loadStage(0, 0);
    for (int c = 0; c < 8; c++) {
        CPWAIT(0);
        __syncthreads();
        if (c < 7) loadStage(c + 1, (c + 1) & 1);
        u32 abase = sb + (c & 1) * PSTG;
        u32 wbase = abase + 128 * SAP;
#pragma unroll
        for (int ks = 0; ks < 8; ks++) {
            u32 af[4][4], bf[4][4];
#pragma unroll
            for (int i = 0; i < 4; i++)
                ldmx4(af[i], addrA(abase, SAP, wm + i * 16, ks * 16, lane));
#pragma unroll
            for (int j = 0; j < 4; j++)
                ldmx4(bf[j], addrB16(wbase, SAP, wn + j * 16, ks * 16, lane));
#pragma unroll
            for (int i = 0; i < 4; i++)
#pragma unroll
                for (int j = 0; j < 4; j++) {
                    mma_fp(acc[i][2*j],     af[i], bf[j]);
                    mma_fp(acc[i][2*j + 1], af[i], bf[j] + 2);
                }
        }
    }

    // epilogue
    int rr = lane >> 2, cq = (lane & 3) * 2;
#pragma unroll
    for (int i = 0; i < 4; i++) {
#pragma unroll
        for (int h2 = 0; h2 < 2; h2++) {
            int m = m0 + wm + i * 16 + rr + h2 * 8;
            int s = m >> 2, b = m & 3;
#pragma unroll
            for (int j = 0; j < 8; j++) {
                int nn = wn + j * 8 + cq;            // 0..255, even
                int head = (n0 + nn) >> 6, d = nn & 63;
                float v0 = fmaxf(acc[i][j][h2 * 2]     + bias[n0 + nn], 0.f);
                float v1 = fmaxf(acc[i][j][h2 * 2 + 1] + bias[n0 + nn + 1], 0.f);
                int mo = (MODED == 0) ? 0 : mode;
                if (mo == 1 || mo == 2) {
                    if (mo == 1) { v0 *= 0.125f; v1 *= 0.125f; }
                    int p = (s << 5) + (d >> 1);
                    float cc = g_cos[p], sn = g_sin[p];
                    float e = v0 * cc - v1 * sn;
                    float o = v0 * sn + v1 * cc;
                    v0 = e; v1 = o;
                }
                if (mo == 0) {
                    *(float2*)&((float*)outp)[(size_t)m * F_DIM + n0 + nn] = make_float2(v0, v1);
                } else if (mo == 1 || mo == 2) {
                    int bh = b * NHEAD + head;
                    u32 w[3];
                    if (mo == 1) packA(v0, v1, w); else packB(v0, v1, w);
                    u32* dd = (u32*)((u16*)outp + ((size_t)bh * S_LEN + s) * TRIPQ + 3 * d);
                    dd[0] = w[0]; dd[1] = w[1]; dd[2] = w[2];
                } else {   // V plain bf16 transposed [bh][d][s]
                    int bh = b * NHEAD + head;
                    u16* d0 = (u16*)outp + ((size_t)bh * HD + d) * S_LEN + s;
                    d0[0] = f2bf(v0);
                    d0[S_LEN] = f2bf(v1);
                }
            }
        }
    }
}

__global__ __launch_bounds__(256, 1) void projqkv_kernel(
    const u16* __restrict__ Ain, const u16* __restrict__ Wall,
    const float* __restrict__ bq, const float* __restrict__ bk,
    const float* __restrict__ bv,
    u16* __restrict__ oq, u16* __restrict__ ok, u16* __restrict__ ov)
{
    int sel = blockIdx.z;
    const u16* Ab = Ain + (size_t)sel * M_ROWS * TRIP;
    const u16* Wb = Wall + (size_t)sel * F_DIM * TRIP;
    const float* bias = (sel == 0) ? bq : (sel == 1) ? bk : bv;
    void* outp = (sel == 0) ? (void*)oq : (sel == 1) ? (void*)ok : (void*)ov;
    proj_body<-1>(Ab, Wb, bias, outp, sel + 1);
}

__global__ __launch_bounds__(256, 1) void projo_kernel(
    const u16* __restrict__ Ab, const u16* __restrict__ Wb,
    const float* __restrict__ bias, float* __restrict__ outp)
{
    proj_body<0>(Ab, Wb, bias, outp, 0);
}

// ---------------------------------------------------------------------------
// Flash attention (UNCHANGED numerics): CTA = 256 q x 1 head; 512 threads.
// QK^T tripled bf16 (k'=192). PV: P bf16 from registers, V plain bf16.
// smem: Q 256x400 (102400) | 2 x (K 64x400 + V 64x144) = 174080
// ---------------------------------------------------------------------------
#define FSQ 400
#define VSP 144
#define QBYTES (256 * FSQ)
#define KSTG (64 * FSQ)
#define VSTG (64 * VSP)
#define FKV(stg) (QBYTES + (stg) * (KSTG + VSTG))
#define FLASH_SMEM (QBYTES + 2 * (KSTG + VSTG))   // 174080

__global__ __launch_bounds__(512, 1) void flash_kernel() {
    extern __shared__ char smem[];
    u32 sb = s2u(smem);
    int tid = threadIdx.x, lane = tid & 31, wid = tid >> 5;
    int q0 = blockIdx.x * 256, bh = blockIdx.y;
    int wm = wid * 16;

    // Q load (tripled bf16 A-pattern, pre-scaled): 256 rows x 384B
    {
        int r = tid >> 1, c0 = (tid & 1) * 192;
        const char* src = (const char*)g_Qb + ((size_t)(bh * S_LEN) + q0 + r) * (TRIPQ * 2) + c0;
        u32 dst = sb + r * FSQ + c0;
#pragma unroll
        for (int i = 0; i < 12; i++) CPA16(dst + i * 16, src + i * 16);
        CPCOMMIT();
    }
    int kr = tid >> 3, kc = (tid & 7) * 48;
    int vc = (tid & 7) * 16;
    auto loadKV = [&](int kb, int stg) {
        u32 base = sb + FKV(stg);
        const char* ksrc = (const char*)g_Kb + ((size_t)(bh * S_LEN) + kb * 64 + kr) * (TRIPQ * 2) + kc;
#pragma unroll
        for (int i = 0; i < 3; i++) CPA16(base + kr * FSQ + kc + i * 16, ksrc + i * 16);
        const char* vsrc = (const char*)g_Vb + (((size_t)(bh * HD) + kr) * S_LEN + kb * 64) * 2 + vc;
        CPA16(base + KSTG + kr * VSP + vc, vsrc);
        CPCOMMIT();
    };

    loadKV(0, 0);
    CPWAIT(0);          // Q + KV0 done
    __syncthreads();

    u32 qf[12][4];
#pragma unroll
    for (int ks = 0; ks < 12; ks++)
        ldmx4(qf[ks], addrA(sb, FSQ, wm, ks * 16, lane));

    float mi[2] = {-3.0e38f, -3.0e38f}, li[2] = {0.f, 0.f};
    float oacc[8][4];
#pragma unroll
    for (int j = 0; j < 8; j++)
#pragma unroll
        for (int e = 0; e < 4; e++) oacc[j][e] = 0.f;

    for (int kb = 0; kb < 32; kb++) {
        if (kb > 0) { CPWAIT(0); __syncthreads(); }
        if (kb < 31) loadKV(kb + 1, (kb + 1) & 1);
        u32 kbase = sb + FKV(kb & 1);
        u32 vbase = kbase + KSTG;

        // S = Q K^T (tripled bf16, fp32-grade)
        float sacc[8][4];
#pragma unroll
        for (int j = 0; j < 8; j++)
#pragma unroll
            for (int e = 0; e < 4; e++) sacc[j][e] = 0.f;
#pragma unroll
        for (int ks = 0; ks < 12; ks++) {
#pragma unroll
            for (int j16 = 0; j16 < 4; j16++) {
                u32 bf[4];
                ldmx4(bf, addrB16(kbase, FSQ, j16 * 16, ks * 16, lane));
                mma_bf(sacc[2*j16],     qf[ks], bf);
                mma_bf(sacc[2*j16 + 1], qf[ks], bf + 2);
            }
        }

        // online softmax; sacc becomes P in-place
#pragma unroll
        for (int h2 = 0; h2 < 2; h2++) {
            float rmax = -3.0e38f;
#pragma unroll
            for (int j = 0; j < 8; j++)
                rmax = fmaxf(rmax, fmaxf(sacc[j][h2 * 2], sacc[j][h2 * 2 + 1]));
            rmax = fmaxf(rmax, __shfl_xor_sync(0xffffffffu, rmax, 1));
            rmax = fmaxf(rmax, __shfl_xor_sync(0xffffffffu, rmax, 2));
            float mnew = fmaxf(mi[h2], rmax);
            float alpha = __expf(mi[h2] - mnew);
            mi[h2] = mnew;
            float rsum = 0.f;
#pragma unroll
            for (int j = 0; j < 8; j++) {
                float p0 = __expf(sacc[j][h2 * 2] - mnew);
                float p1 = __expf(sacc[j][h2 * 2 + 1] - mnew);
                sacc[j][h2 * 2] = p0; sacc[j][h2 * 2 + 1] = p1;
                rsum += p0 + p1;
            }
            rsum += __shfl_xor_sync(0xffffffffu, rsum, 1);
            rsum += __shfl_xor_sync(0xffffffffu, rsum, 2);
            li[h2] = li[h2] * alpha + rsum;
#pragma unroll
            for (int j = 0; j < 8; j++) {
                oacc[j][h2 * 2] *= alpha; oacc[j][h2 * 2 + 1] *= alpha;
            }
        }

        // O += P V : P A-frags packed straight from registers
#pragma unroll
        for (int ks = 0; ks < 4; ks++) {
            u32 pf[4];
            pf[0] = pk2(sacc[2*ks][0],     sacc[2*ks][1]);
            pf[1] = pk2(sacc[2*ks][2],     sacc[2*ks][3]);
            pf[2] = pk2(sacc[2*ks + 1][0], sacc[2*ks + 1][1]);
            pf[3] = pk2(sacc[2*ks + 1][2], sacc[2*ks + 1][3]);
#pragma unroll
            for (int j16 = 0; j16 < 4; j16++) {
                u32 bf[4];
                ldmx4(bf, addrB16(vbase, VSP, j16 * 16, ks * 16, lane));
                mma_bf(oacc[2*j16],     pf, bf);
                mma_bf(oacc[2*j16 + 1], pf, bf + 2);
            }
        }
    }

    // epilogue: write 2-term fp16 A-pattern Y
    int b = bh >> 3, h = bh & 7;
    int rr = lane >> 2, cq = (lane & 3) * 2;
#pragma unroll
    for (int h2 = 0; h2 < 2; h2++) {
        int srow = q0 + wm + rr + h2 * 8;
        int m = srow * B_SZ + b;
        float inv = 1.0f / li[h2];
#pragma unroll
        for (int j = 0; j < 8; j++) {
            int f = h * HD + j * 8 + cq;
            u32 w[2];
            packA2h(oacc[j][h2 * 2] * inv, oacc[j][h2 * 2 + 1] * inv, w);
            u32* d = (u32*)(g_Yb + (size_t)m * TRIP + 2 * f);
            d[0] = w[0]; d[1] = w[1];
        }
    }
}

// ---------------------------------------------------------------------------
extern "C" void kernel_launch(void* const* d_in, const int* in_sizes, int n_in,
                              void* d_out, int out_size) {
    const float* q  = (const float*)d_in[0];
    const float* k  = (const float*)d_in[1];
    const float* v  = (const float*)d_in[2];
    const float* Wq = (const float*)d_in[3];
    const float* bq = (const float*)d_in[4];
    const float* Wk = (const float*)d_in[5];
    const float* bk = (const float*)d_in[6];
    const float* Wv = (const float*)d_in[7];
    const float* bv = (const float*)d_in[8];
    const float* Wo = (const float*)d_in[9];
    const float* bo = (const float*)d_in[10];

    u16 *pIn, *pW, *pQ, *pK, *pV, *pY;
    cudaGetSymbolAddress((void**)&pIn, g_inb);
    cudaGetSymbolAddress((void**)&pW,  g_Wb);
    cudaGetSymbolAddress((void**)&pQ,  g_Qb);
    cudaGetSymbolAddress((void**)&pK,  g_Kb);
    cudaGetSymbolAddress((void**)&pV,  g_Vb);
    cudaGetSymbolAddress((void**)&pY,  g_Yb);

    cudaFuncSetAttribute(projqkv_kernel, cudaFuncAttributeMaxDynamicSharedMemorySize, PROJ_SMEM);
    cudaFuncSetAttribute(projo_kernel,   cudaFuncAttributeMaxDynamicSharedMemorySize, PROJ_SMEM);
    cudaFuncSetAttribute(flash_kernel,   cudaFuncAttributeMaxDynamicSharedMemorySize, FLASH_SMEM);

    rope_table_kernel<<<256, 256>>>();

    const int nIn8 = M_ROWS * F_DIM / 8;
    const int nW8  = F_DIM * F_DIM / 8;
    conv_in_kernel<<<dim3(nIn8 / 256, 3), 256>>>(q, k, v, pIn, nIn8);
    conv_w_kernel<<<dim3(nW8 / 256, 4), 256>>>(Wq, Wk, Wv, Wo, pW, nW8);

    dim3 pg(F_DIM / 256, M_ROWS / 128, 3);   // (2, 64, 3)
    projqkv_kernel<<<pg, 256, PROJ_SMEM>>>(pIn, pW, bq, bk, bv, pQ, pK, pV);

    flash_kernel<<<dim3(S_LEN / 256, NB), 512, FLASH_SMEM>>>();

    projo_kernel<<<dim3(F_DIM / 256, M_ROWS / 128), 256, PROJ_SMEM>>>(
        pY, pW + (size_t)3 * F_DIM * TRIP, bo, (float*)d_out);
}

// round 16
// speedup vs baseline: 3.3158x; 1.0411x over previous
#include <cuda_runtime.h>
#include <cstdint>
#include <math.h>

#define S_LEN  2048
#define B_SZ   4
#define F_DIM  512
#define NHEAD  8
#define NB     32
#define HD     64
#define M_ROWS 8192
#define TRIP   1024     // 2*F_DIM k' (2-term fp16 split for projections)
#define TRIPQ  192      // 3*HD (flash QK tripled bf16)

typedef unsigned short u16;
typedef unsigned int u32;

// scratch
__device__ u16 g_inb[(size_t)3 * M_ROWS * TRIP];          // q,k,v 2-term fp16 A-pattern
__device__ u16 g_Wb[(size_t)4 * F_DIM * TRIP];            // weights 2-term fp16 B-pattern
__device__ u16 g_Qb[(size_t)NB * S_LEN * TRIPQ];          // tripled bf16 A-pattern, scaled 1/8
__device__ u16 g_Kb[(size_t)NB * S_LEN * TRIPQ];          // tripled bf16 B-pattern
__device__ u16 g_Vb[(size_t)NB * HD * S_LEN];             // plain bf16, [bh][d][s]
__device__ u16 g_Yb[(size_t)M_ROWS * TRIP];               // 2-term fp16 A-pattern
__device__ float g_cos[S_LEN * 32];
__device__ float g_sin[S_LEN * 32];

// ---------------- helpers ----------------
__device__ __forceinline__ u32 s2u(const void* p) {
    u32 a;
    asm("{ .reg .u64 t; cvta.to.shared.u64 t, %1; cvt.u32.u64 %0, t; }" : "=r"(a) : "l"(p));
    return a;
}
// bf16 (flash)
__device__ __forceinline__ u16 f2bf(float f) {
    u16 r; asm("cvt.rn.bf16.f32 %0, %1;" : "=h"(r) : "f"(f)); return r;
}
__device__ __forceinline__ float bf2f(u16 h) { return __uint_as_float(((u32)h) << 16); }
__device__ __forceinline__ void splitf(float a, u16 &h, u16 &l) {
    h = f2bf(a); l = f2bf(a - bf2f(h));
}
__device__ __forceinline__ void packA(float v0, float v1, u32* w) {
    u16 h0, l0, h1, l1; splitf(v0, h0, l0); splitf(v1, h1, l1);
    w[0] = h0 | ((u32)l0 << 16); w[1] = h0 | ((u32)h1 << 16); w[2] = l1 | ((u32)h1 << 16);
}
__device__ __forceinline__ void packB(float v0, float v1, u32* w) {
    u16 h0, l0, h1, l1; splitf(v0, h0, l0); splitf(v1, h1, l1);
    w[0] = h0 | ((u32)h0 << 16); w[1] = l0 | ((u32)h1 << 16); w[2] = h1 | ((u32)l1 << 16);
}
__device__ __forceinline__ u32 pk2(float lo, float hi) {
    u32 d; asm("cvt.rn.bf16x2.f32 %0, %1, %2;" : "=r"(d) : "f"(hi), "f"(lo)); return d;
}
// fp16 (projections)
__device__ __forceinline__ u16 f2h(float f) {
    u16 r; asm("cvt.rn.f16.f32 %0, %1;" : "=h"(r) : "f"(f)); return r;
}
__device__ __forceinline__ float h2f(u16 h) {
    float f; asm("cvt.f32.f16 %0, %1;" : "=f"(f) : "h"(h)); return f;
}
__device__ __forceinline__ void packA2h(float v0, float v1, u32* w) {
    u16 h0 = f2h(v0), h1 = f2h(v1);
    u16 l0 = f2h(v0 - h2f(h0)), l1 = f2h(v1 - h2f(h1));
    w[0] = h0 | ((u32)l0 << 16); w[1] = h1 | ((u32)l1 << 16);
}
__device__ __forceinline__ void packB2h(float v0, float v1, u32* w) {
    u16 h0 = f2h(v0), h1 = f2h(v1);
    w[0] = h0 | ((u32)h0 << 16); w[1] = h1 | ((u32)h1 << 16);
}

__device__ __forceinline__ void mma_bf(float* d, const u32* a, const u32* b) {
    asm volatile(
        "mma.sync.aligned.m16n8k16.row.col.f32.bf16.bf16.f32 "
        "{%0,%1,%2,%3}, {%4,%5,%6,%7}, {%8,%9}, {%0,%1,%2,%3};"
        : "+f"(d[0]), "+f"(d[1]), "+f"(d[2]), "+f"(d[3])
        : "r"(a[0]), "r"(a[1]), "r"(a[2]), "r"(a[3]), "r"(b[0]), "r"(b[1]));
}
__device__ __forceinline__ void mma_fp(float* d, const u32* a, const u32* b) {
    asm volatile(
        "mma.sync.aligned.m16n8k16.row.col.f32.f16.f16.f32 "
        "{%0,%1,%2,%3}, {%4,%5,%6,%7}, {%8,%9}, {%0,%1,%2,%3};"
        : "+f"(d[0]), "+f"(d[1]), "+f"(d[2]), "+f"(d[3])
        : "r"(a[0]), "r"(a[1]), "r"(a[2]), "r"(a[3]), "r"(b[0]), "r"(b[1]));
}
__device__ __forceinline__ void ldmx4(u32* r, u32 a) {
    asm volatile("ldmatrix.sync.aligned.m8n8.x4.shared.b16 {%0,%1,%2,%3}, [%4];"
                 : "=r"(r[0]), "=r"(r[1]), "=r"(r[2]), "=r"(r[3]) : "r"(a));
}
__device__ __forceinline__ u32 addrA(u32 base, int stride, int m0, int k0, int lane) {
    int grp = lane >> 3, li = lane & 7;
    return base + (m0 + li + (grp & 1) * 8) * stride + (k0 + (grp >> 1) * 8) * 2;
}
__device__ __forceinline__ u32 addrB16(u32 base, int stride, int n0, int k0, int lane) {
    int grp = lane >> 3, li = lane & 7;
    return base + (n0 + li + (grp >> 1) * 8) * stride + (k0 + (grp & 1) * 8) * 2;
}
#define CPA16(s, g) asm volatile("cp.async.cg.shared.global [%0], [%1], 16;" :: "r"(s), "l"(g))
#define CPCOMMIT()  asm volatile("cp.async.commit_group;")
#define CPWAIT(n)   asm volatile("cp.async.wait_group %0;" :: "n"(n))

__global__ void rope_table_kernel() {
    int idx = blockIdx.x * blockDim.x + threadIdx.x;
    if (idx >= S_LEN * 32) return;
    int s = idx >> 5, j = idx & 31;
    double ang = (double)s * pow(10000.0, -(double)j / 32.0);
    g_cos[idx] = (float)cos(ang);
    g_sin[idx] = (float)sin(ang);
}

// ---------------------------------------------------------------------------
// conversion pre-pass: 8 floats -> 16 fp16 (2-term)
// ---------------------------------------------------------------------------
__global__ void conv_in_kernel(const float* __restrict__ q, const float* __restrict__ k,
                               const float* __restrict__ v, u16* __restrict__ dst, int n8) {
    int g = blockIdx.x * blockDim.x + threadIdx.x;
    if (g >= n8) return;
    int sel = blockIdx.y;
    const float* src = (sel == 0) ? q : (sel == 1) ? k : v;
    u16* d = dst + (size_t)sel * M_ROWS * TRIP;
    float4 f0 = *(const float4*)(src + (size_t)g * 8);
    float4 f1 = *(const float4*)(src + (size_t)g * 8 + 4);
    float f[8] = {f0.x, f0.y, f0.z, f0.w, f1.x, f1.y, f1.z, f1.w};
    __align__(16) u32 w[8];
#pragma unroll
    for (int i = 0; i < 4; i++) packA2h(f[2*i], f[2*i+1], w + 2*i);
    uint4* dd = (uint4*)(d + (size_t)g * 16);
    const uint4* s = (const uint4*)w;
    dd[0] = s[0]; dd[1] = s[1];
}
__global__ void conv_w_kernel(const float* __restrict__ w0, const float* __restrict__ w1,
                              const float* __restrict__ w2, const float* __restrict__ w3,
                              u16* __restrict__ dst, int n8) {
    int g = blockIdx.x * blockDim.x + threadIdx.x;
    if (g >= n8) return;
    int sel = blockIdx.y;
    const float* src = (sel == 0) ? w0 : (sel == 1) ? w1 : (sel == 2) ? w2 : w3;
    u16* d = dst + (size_t)sel * F_DIM * TRIP;
    float4 f0 = *(const float4*)(src + (size_t)g * 8);
    float4 f1 = *(const float4*)(src + (size_t)g * 8 + 4);
    float f[8] = {f0.x, f0.y, f0.z, f0.w, f1.x, f1.y, f1.z, f1.w};
    __align__(16) u32 w[8];
#pragma unroll
    for (int i = 0; i < 4; i++) packB2h(f[2*i], f[2*i+1], w + 2*i);
    uint4* dd = (uint4*)(d + (size_t)g * 16);
    const uint4* s = (const uint4*)w;
    dd[0] = s[0]; dd[1] = s[1];
}

// ---------------------------------------------------------------------------
// Projection GEMM core (fp16 2-term): BM=128, BN=256; k-chunk = 64 floats
// (128 k'); 8 chunks. 512 threads, 16 warps = 4m x 4n, warp tile 32x64.
// mode 0: fp32 flat; 1: Q (tripled bf16 A, rope, 1/8); 2: K (tripled bf16 B,
// rope); 3: V plain bf16 transposed [bh][d][s]
// ---------------------------------------------------------------------------
#define SAP  272                        // 256B row + 16 pad
#define PSTG (384 * SAP)                // 104448
#define PROJ_SMEM (2 * PSTG)            // 208896

template <int MODED>
__device__ __forceinline__ void proj_body(
    const u16* __restrict__ Ab, const u16* __restrict__ Wb,
    const float* __restrict__ bias, void* __restrict__ outp, int mode)
{
    extern __shared__ char smem[];
    u32 sb = s2u(smem);
    int tid = threadIdx.x, lane = tid & 31, wid = tid >> 5;
    int m0 = blockIdx.y * 128, n0 = blockIdx.x * 256;
    int wm = (wid & 3) * 32, wn = (wid >> 2) * 64;

    const char* Abase = (const char*)Ab;
    const char* Wbase = (const char*)Wb;
    int arow = tid >> 2, acol = (tid & 3) * 64;   // A: 128 rows x 256B, 4 thr/row
    int wrow = tid >> 1, wcol = (tid & 1) * 128;  // W: 256 rows x 256B, 2 thr/row

    auto loadStage = [&](int c, int stg) {
        u32 base = sb + stg * PSTG;
        const char* asrc = Abase + ((size_t)(m0 + arow) * TRIP + c * 128) * 2 + acol;
        u32 adst = base + arow * SAP + acol;
#pragma unroll
        for (int i = 0; i < 4; i++) CPA16(adst + i * 16, asrc + i * 16);
        const char* wsrc = Wbase + ((size_t)(n0 + wrow) * TRIP + c * 128) * 2 + wcol;
        u32 wdst = base + 128 * SAP + wrow * SAP + wcol;
#pragma unroll
        for (int i = 0; i < 8; i++) CPA16(wdst + i * 16, wsrc + i * 16);
        CPCOMMIT();
    };

    float acc[2][8][4];
#pragma unroll
    for (int i = 0; i < 2; i++)
#pragma unroll
        for (int j = 0; j < 8; j++)
#pragma unroll
            for (int e = 0; e < 4; e++) acc[i][j][e] = 0.f;

    loadStage(0, 0);
    for (int c = 0; c < 8; c++) {
        CPWAIT(0);
        __syncthreads();
        if (c < 7) loadStage(c + 1, (c + 1) & 1);
        u32 abase = sb + (c & 1) * PSTG;
        u32 wbase = abase + 128 * SAP;
#pragma unroll
        for (int ks = 0; ks < 8; ks++) {
            u32 af[2][4], bf[4][4];
#pragma unroll
            for (int i = 0; i < 2; i++)
                ldmx4(af[i], addrA(abase, SAP, wm + i * 16, ks * 16, lane));
#pragma unroll
            for (int j = 0; j < 4; j++)
                ldmx4(bf[j], addrB16(wbase, SAP, wn + j * 16, ks * 16, lane));
#pragma unroll
            for (int i = 0; i < 2; i++)
#pragma unroll
                for (int j = 0; j < 4; j++) {
                    mma_fp(acc[i][2*j],     af[i], bf[j]);
                    mma_fp(acc[i][2*j + 1], af[i], bf[j] + 2);
                }
        }
    }

    // epilogue
    int rr = lane >> 2, cq = (lane & 3) * 2;
#pragma unroll
    for (int i = 0; i < 2; i++) {
#pragma unroll
        for (int h2 = 0; h2 < 2; h2++) {
            int m = m0 + wm + i * 16 + rr + h2 * 8;
            int s = m >> 2, b = m & 3;
#pragma unroll
            for (int j = 0; j < 8; j++) {
                int nn = wn + j * 8 + cq;            // 0..255, even
                int head = (n0 + nn) >> 6, d = nn & 63;
                float v0 = fmaxf(acc[i][j][h2 * 2]     + bias[n0 + nn], 0.f);
                float v1 = fmaxf(acc[i][j][h2 * 2 + 1] + bias[n0 + nn + 1], 0.f);
                int mo = (MODED == 0) ? 0 : mode;
                if (mo == 1 || mo == 2) {
                    if (mo == 1) { v0 *= 0.125f; v1 *= 0.125f; }
                    int p = (s << 5) + (d >> 1);
                    float cc = g_cos[p], sn = g_sin[p];
                    float e = v0 * cc - v1 * sn;
                    float o = v0 * sn + v1 * cc;
                    v0 = e; v1 = o;
                }
                if (mo == 0) {
                    *(float2*)&((float*)outp)[(size_t)m * F_DIM + n0 + nn] = make_float2(v0, v1);
                } else if (mo == 1 || mo == 2) {
                    int bh = b * NHEAD + head;
                    u32 w[3];
                    if (mo == 1) packA(v0, v1, w); else packB(v0, v1, w);
                    u32* dd = (u32*)((u16*)outp + ((size_t)bh * S_LEN + s) * TRIPQ + 3 * d);
                    dd[0] = w[0]; dd[1] = w[1]; dd[2] = w[2];
                } else {   // V plain bf16 transposed [bh][d][s]
                    int bh = b * NHEAD + head;
                    u16* d0 = (u16*)outp + ((size_t)bh * HD + d) * S_LEN + s;
                    d0[0] = f2bf(v0);
                    d0[S_LEN] = f2bf(v1);
                }
            }
        }
    }
}

__global__ __launch_bounds__(512, 1) void projqkv_kernel(
    const u16* __restrict__ Ain, const u16* __restrict__ Wall,
    const float* __restrict__ bq, const float* __restrict__ bk,
    const float* __restrict__ bv,
    u16* __restrict__ oq, u16* __restrict__ ok, u16* __restrict__ ov)
{
    int sel = blockIdx.z;
    const u16* Ab = Ain + (size_t)sel * M_ROWS * TRIP;
    const u16* Wb = Wall + (size_t)sel * F_DIM * TRIP;
    const float* bias = (sel == 0) ? bq : (sel == 1) ? bk : bv;
    void* outp = (sel == 0) ? (void*)oq : (sel == 1) ? (void*)ok : (void*)ov;
    proj_body<-1>(Ab, Wb, bias, outp, sel + 1);
}

__global__ __launch_bounds__(512, 1) void projo_kernel(
    const u16* __restrict__ Ab, const u16* __restrict__ Wb,
    const float* __restrict__ bias, float* __restrict__ outp)
{
    proj_body<0>(Ab, Wb, bias, outp, 0);
}

// ---------------------------------------------------------------------------
// Flash attention (UNCHANGED): CTA = 256 q x 1 head; 512 threads.
// QK^T tripled bf16 (k'=192). PV: P bf16 from registers, V plain bf16.
// smem: Q 256x400 (102400) | 2 x (K 64x400 + V 64x144) = 174080
// ---------------------------------------------------------------------------
#define FSQ 400
#define VSP 144
#define QBYTES (256 * FSQ)
#define KSTG (64 * FSQ)
#define VSTG (64 * VSP)
#define FKV(stg) (QBYTES + (stg) * (KSTG + VSTG))
#define FLASH_SMEM (QBYTES + 2 * (KSTG + VSTG))   // 174080

__global__ __launch_bounds__(512, 1) void flash_kernel() {
    extern __shared__ char smem[];
    u32 sb = s2u(smem);
    int tid = threadIdx.x, lane = tid & 31, wid = tid >> 5;
    int q0 = blockIdx.x * 256, bh = blockIdx.y;
    int wm = wid * 16;

    // Q load (tripled bf16 A-pattern, pre-scaled): 256 rows x 384B
    {
        int r = tid >> 1, c0 = (tid & 1) * 192;
        const char* src = (const char*)g_Qb + ((size_t)(bh * S_LEN) + q0 + r) * (TRIPQ * 2) + c0;
        u32 dst = sb + r * FSQ + c0;
#pragma unroll
        for (int i = 0; i < 12; i++) CPA16(dst + i * 16, src + i * 16);
        CPCOMMIT();
    }
    int kr = tid >> 3, kc = (tid & 7) * 48;
    int vc = (tid & 7) * 16;
    auto loadKV = [&](int kb, int stg) {
        u32 base = sb + FKV(stg);
        const char* ksrc = (const char*)g_Kb + ((size_t)(bh * S_LEN) + kb * 64 + kr) * (TRIPQ * 2) + kc;
#pragma unroll
        for (int i = 0; i < 3; i++) CPA16(base + kr * FSQ + kc + i * 16, ksrc + i * 16);
        const char* vsrc = (const char*)g_Vb + (((size_t)(bh * HD) + kr) * S_LEN + kb * 64) * 2 + vc;
        CPA16(base + KSTG + kr * VSP + vc, vsrc);
        CPCOMMIT();
    };

    loadKV(0, 0);
    CPWAIT(0);
    __syncthreads();

    u32 qf[12][4];
#pragma unroll
    for (int ks = 0; ks < 12; ks++)
        ldmx4(qf[ks], addrA(sb, FSQ, wm, ks * 16, lane));

    float mi[2] = {-3.0e38f, -3.0e38f}, li[2] = {0.f, 0.f};
    float oacc[8][4];
#pragma unroll
    for (int j = 0; j < 8; j++)
#pragma unroll
        for (int e = 0; e < 4; e++) oacc[j][e] = 0.f;

    for (int kb = 0; kb < 32; kb++) {
        if (kb > 0) { CPWAIT(0); __syncthreads(); }
        if (kb < 31) loadKV(kb + 1, (kb + 1) & 1);
        u32 kbase = sb + FKV(kb & 1);
        u32 vbase = kbase + KSTG;

        // S = Q K^T (tripled bf16, fp32-grade)
        float sacc[8][4];
#pragma unroll
        for (int j = 0; j < 8; j++)
#pragma unroll
            for (int e = 0; e < 4; e++) sacc[j][e] = 0.f;
#pragma unroll
        for (int ks = 0; ks < 12; ks++) {
#pragma unroll
            for (int j16 = 0; j16 < 4; j16++) {
                u32 bf[4];
                ldmx4(bf, addrB16(kbase, FSQ, j16 * 16, ks * 16, lane));
                mma_bf(sacc[2*j16],     qf[ks], bf);
                mma_bf(sacc[2*j16 + 1], qf[ks], bf + 2);
            }
        }

        // online softmax; sacc becomes P in-place
#pragma unroll
        for (int h2 = 0; h2 < 2; h2++) {
            float rmax = -3.0e38f;
#pragma unroll
            for (int j = 0; j < 8; j++)
                rmax = fmaxf(rmax, fmaxf(sacc[j][h2 * 2], sacc[j][h2 * 2 + 1]));
            rmax = fmaxf(rmax, __shfl_xor_sync(0xffffffffu, rmax, 1));
            rmax = fmaxf(rmax, __shfl_xor_sync(0xffffffffu, rmax, 2));
            float mnew = fmaxf(mi[h2], rmax);
            float alpha = __expf(mi[h2] - mnew);
            mi[h2] = mnew;
            float rsum = 0.f;
#pragma unroll
            for (int j = 0; j < 8; j++) {
                float p0 = __expf(sacc[j][h2 * 2] - mnew);
                float p1 = __expf(sacc[j][h2 * 2 + 1] - mnew);
                sacc[j][h2 * 2] = p0; sacc[j][h2 * 2 + 1] = p1;
                rsum += p0 + p1;
            }
            rsum += __shfl_xor_sync(0xffffffffu, rsum, 1);
            rsum += __shfl_xor_sync(0xffffffffu, rsum, 2);
            li[h2] = li[h2] * alpha + rsum;
#pragma unroll
            for (int j = 0; j < 8; j++) {
                oacc[j][h2 * 2] *= alpha; oacc[j][h2 * 2 + 1] *= alpha;
            }
        }

        // O += P V : P A-frags packed straight from registers
#pragma unroll
        for (int ks = 0; ks < 4; ks++) {
            u32 pf[4];
            pf[0] = pk2(sacc[2*ks][0],     sacc[2*ks][1]);
            pf[1] = pk2(sacc[2*ks][2],     sacc[2*ks][3]);
            pf[2] = pk2(sacc[2*ks + 1][0], sacc[2*ks + 1][1]);
            pf[3] = pk2(sacc[2*ks + 1][2], sacc[2*ks + 1][3]);
#pragma unroll
            for (int j16 = 0; j16 < 4; j16++) {
                u32 bf[4];
                ldmx4(bf, addrB16(vbase, VSP, j16 * 16, ks * 16, lane));
                mma_bf(oacc[2*j16],     pf, bf);
                mma_bf(oacc[2*j16 + 1], pf, bf + 2);
            }
        }
    }

    // epilogue: write 2-term fp16 A-pattern Y
    int b = bh >> 3, h = bh & 7;
    int rr = lane >> 2, cq = (lane & 3) * 2;
#pragma unroll
    for (int h2 = 0; h2 < 2; h2++) {
        int srow = q0 + wm + rr + h2 * 8;
        int m = srow * B_SZ + b;
        float inv = 1.0f / li[h2];
#pragma unroll
        for (int j = 0; j < 8; j++) {
            int f = h * HD + j * 8 + cq;
            u32 w[2];
            packA2h(oacc[j][h2 * 2] * inv, oacc[j][h2 * 2 + 1] * inv, w);
            u32* d = (u32*)(g_Yb + (size_t)m * TRIP + 2 * f);
            d[0] = w[0]; d[1] = w[1];
        }
    }
}

// ---------------------------------------------------------------------------
extern "C" void kernel_launch(void* const* d_in, const int* in_sizes, int n_in,
                              void* d_out, int out_size) {
    const float* q  = (const float*)d_in[0];
    const float* k  = (const float*)d_in[1];
    const float* v  = (const float*)d_in[2];
    const float* Wq = (const float*)d_in[3];
    const float* bq = (const float*)d_in[4];
    const float* Wk = (const float*)d_in[5];
    const float* bk = (const float*)d_in[6];
    const float* Wv = (const float*)d_in[7];
    const float* bv = (const float*)d_in[8];
    const float* Wo = (const float*)d_in[9];
    const float* bo = (const float*)d_in[10];

    u16 *pIn, *pW, *pQ, *pK, *pV, *pY;
    cudaGetSymbolAddress((void**)&pIn, g_inb);
    cudaGetSymbolAddress((void**)&pW,  g_Wb);
    cudaGetSymbolAddress((void**)&pQ,  g_Qb);
    cudaGetSymbolAddress((void**)&pK,  g_Kb);
    cudaGetSymbolAddress((void**)&pV,  g_Vb);
    cudaGetSymbolAddress((void**)&pY,  g_Yb);

    cudaFuncSetAttribute(projqkv_kernel, cudaFuncAttributeMaxDynamicSharedMemorySize, PROJ_SMEM);
    cudaFuncSetAttribute(projo_kernel,   cudaFuncAttributeMaxDynamicSharedMemorySize, PROJ_SMEM);
    cudaFuncSetAttribute(flash_kernel,   cudaFuncAttributeMaxDynamicSharedMemorySize, FLASH_SMEM);

    rope_table_kernel<<<256, 256>>>();

    const int nIn8 = M_ROWS * F_DIM / 8;
    const int nW8  = F_DIM * F_DIM / 8;
    conv_in_kernel<<<dim3(nIn8 / 256, 3), 256>>>(q, k, v, pIn, nIn8);
    conv_w_kernel<<<dim3(nW8 / 256, 4), 256>>>(Wq, Wk, Wv, Wo, pW, nW8);

    dim3 pg(F_DIM / 256, M_ROWS / 128, 3);   // (2, 64, 3)
    projqkv_kernel<<<pg, 512, PROJ_SMEM>>>(pIn, pW, bq, bk, bv, pQ, pK, pV);

    flash_kernel<<<dim3(S_LEN / 256, NB), 512, FLASH_SMEM>>>();

    projo_kernel<<<dim3(F_DIM / 256, M_ROWS / 128), 512, PROJ_SMEM>>>(
        pY, pW + (size_t)3 * F_DIM * TRIP, bo, (float*)d_out);
}

// round 17
// speedup vs baseline: 4.0416x; 1.2189x over previous
#include <cuda_runtime.h>
#include <cstdint>
#include <math.h>

#define S_LEN  2048
#define B_SZ   4
#define F_DIM  512
#define NHEAD  8
#define NB     32
#define HD     64
#define M_ROWS 8192
#define TRIP   1024     // 2*F_DIM k' (2-term fp16, projections)
#define TRIPQ  128      // 2*HD   k' (2-term fp16, flash QK)

typedef unsigned short u16;
typedef unsigned int u32;

// scratch
__device__ u16 g_inb[(size_t)3 * M_ROWS * TRIP];          // q,k,v 2-term fp16 A-pattern
__device__ u16 g_Wb[(size_t)4 * F_DIM * TRIP];            // weights 2-term fp16 B-pattern
__device__ u16 g_Qb[(size_t)NB * S_LEN * TRIPQ];          // 2-term fp16 A-pattern, scaled 1/8
__device__ u16 g_Kb[(size_t)NB * S_LEN * TRIPQ];          // 2-term fp16 B-pattern
__device__ u16 g_Vb[(size_t)NB * HD * S_LEN];             // plain fp16, [bh][d][s]
__device__ u16 g_Yb[(size_t)M_ROWS * TRIP];               // 2-term fp16 A-pattern
__device__ float g_cos[S_LEN * 32];
__device__ float g_sin[S_LEN * 32];

// ---------------- helpers ----------------
__device__ __forceinline__ u32 s2u(const void* p) {
    u32 a;
    asm("{ .reg .u64 t; cvta.to.shared.u64 t, %1; cvt.u32.u64 %0, t; }" : "=r"(a) : "l"(p));
    return a;
}
// fp16
__device__ __forceinline__ u16 f2h(float f) {
    u16 r; asm("cvt.rn.f16.f32 %0, %1;" : "=h"(r) : "f"(f)); return r;
}
__device__ __forceinline__ float h2f(u16 h) {
    float f; asm("cvt.f32.f16 %0, %1;" : "=f"(f) : "h"(h)); return f;
}
__device__ __forceinline__ void packA2h(float v0, float v1, u32* w) { // 2-term fp16 A
    u16 h0 = f2h(v0), h1 = f2h(v1);
    u16 l0 = f2h(v0 - h2f(h0)), l1 = f2h(v1 - h2f(h1));
    w[0] = h0 | ((u32)l0 << 16); w[1] = h1 | ((u32)l1 << 16);
}
__device__ __forceinline__ void packB2h(float v0, float v1, u32* w) { // 2-term fp16 B
    u16 h0 = f2h(v0), h1 = f2h(v1);
    w[0] = h0 | ((u32)h0 << 16); w[1] = h1 | ((u32)h1 << 16);
}
__device__ __forceinline__ u32 pk2h(float lo, float hi) {             // fp16x2 pack
    u32 d; asm("cvt.rn.f16x2.f32 %0, %1, %2;" : "=r"(d) : "f"(hi), "f"(lo)); return d;
}

__device__ __forceinline__ void mma_fp(float* d, const u32* a, const u32* b) {
    asm volatile(
        "mma.sync.aligned.m16n8k16.row.col.f32.f16.f16.f32 "
        "{%0,%1,%2,%3}, {%4,%5,%6,%7}, {%8,%9}, {%0,%1,%2,%3};"
        : "+f"(d[0]), "+f"(d[1]), "+f"(d[2]), "+f"(d[3])
        : "r"(a[0]), "r"(a[1]), "r"(a[2]), "r"(a[3]), "r"(b[0]), "r"(b[1]));
}
__device__ __forceinline__ void ldmx4(u32* r, u32 a) {
    asm volatile("ldmatrix.sync.aligned.m8n8.x4.shared.b16 {%0,%1,%2,%3}, [%4];"
                 : "=r"(r[0]), "=r"(r[1]), "=r"(r[2]), "=r"(r[3]) : "r"(a));
}
__device__ __forceinline__ u32 addrA(u32 base, int stride, int m0, int k0, int lane) {
    int grp = lane >> 3, li = lane & 7;
    return base + (m0 + li + (grp & 1) * 8) * stride + (k0 + (grp >> 1) * 8) * 2;
}
__device__ __forceinline__ u32 addrB16(u32 base, int stride, int n0, int k0, int lane) {
    int grp = lane >> 3, li = lane & 7;
    return base + (n0 + li + (grp >> 1) * 8) * stride + (k0 + (grp & 1) * 8) * 2;
}
#define CPA16(s, g) asm volatile("cp.async.cg.shared.global [%0], [%1], 16;" :: "r"(s), "l"(g))
#define CPCOMMIT()  asm volatile("cp.async.commit_group;")
#define CPWAIT(n)   asm volatile("cp.async.wait_group %0;" :: "n"(n))

__global__ void rope_table_kernel() {
    int idx = blockIdx.x * blockDim.x + threadIdx.x;
    if (idx >= S_LEN * 32) return;
    int s = idx >> 5, j = idx & 31;
    double ang = (double)s * pow(10000.0, -(double)j / 32.0);
    g_cos[idx] = (float)cos(ang);
    g_sin[idx] = (float)sin(ang);
}

// ---------------------------------------------------------------------------
// conversion pre-pass: 8 floats -> 16 fp16 (2-term)
// ---------------------------------------------------------------------------
__global__ void conv_in_kernel(const float* __restrict__ q, const float* __restrict__ k,
                               const float* __restrict__ v, u16* __restrict__ dst, int n8) {
    int g = blockIdx.x * blockDim.x + threadIdx.x;
    if (g >= n8) return;
    int sel = blockIdx.y;
    const float* src = (sel == 0) ? q : (sel == 1) ? k : v;
    u16* d = dst + (size_t)sel * M_ROWS * TRIP;
    float4 f0 = *(const float4*)(src + (size_t)g * 8);
    float4 f1 = *(const float4*)(src + (size_t)g * 8 + 4);
    float f[8] = {f0.x, f0.y, f0.z, f0.w, f1.x, f1.y, f1.z, f1.w};
    __align__(16) u32 w[8];
#pragma unroll
    for (int i = 0; i < 4; i++) packA2h(f[2*i], f[2*i+1], w + 2*i);
    uint4* dd = (uint4*)(d + (size_t)g * 16);
    const uint4* s = (const uint4*)w;
    dd[0] = s[0]; dd[1] = s[1];
}
__global__ void conv_w_kernel(const float* __restrict__ w0, const float* __restrict__ w1,
                              const float* __restrict__ w2, const float* __restrict__ w3,
                              u16* __restrict__ dst, int n8) {
    int g = blockIdx.x * blockDim.x + threadIdx.x;
    if (g >= n8) return;
    int sel = blockIdx.y;
    const float* src = (sel == 0) ? w0 : (sel == 1) ? w1 : (sel == 2) ? w2 : w3;
    u16* d = dst + (size_t)sel * F_DIM * TRIP;
    float4 f0 = *(const float4*)(src + (size_t)g * 8);
    float4 f1 = *(const float4*)(src + (size_t)g * 8 + 4);
    float f[8] = {f0.x, f0.y, f0.z, f0.w, f1.x, f1.y, f1.z, f1.w};
    __align__(16) u32 w[8];
#pragma unroll
    for (int i = 0; i < 4; i++) packB2h(f[2*i], f[2*i+1], w + 2*i);
    uint4* dd = (uint4*)(d + (size_t)g * 16);
    const uint4* s = (const uint4*)w;
    dd[0] = s[0]; dd[1] = s[1];
}

// ---------------------------------------------------------------------------
// Projection GEMM core (fp16 2-term): BM=128, BN=256; k-chunk = 64 floats
// (128 k'); 8 chunks. 512 threads, 16 warps = 4m x 4n, warp tile 32x64.
// mode 0: fp32 flat; 1: Q (2-term fp16 A, rope, 1/8); 2: K (2-term fp16 B,
// rope); 3: V plain fp16 transposed [bh][d][s]
// ---------------------------------------------------------------------------
#define SAP  272                        // 256B row + 16 pad
#define PSTG (384 * SAP)                // 104448
#define PROJ_SMEM (2 * PSTG)            // 208896

template <int MODED>
__device__ __forceinline__ void proj_body(
    const u16* __restrict__ Ab, const u16* __restrict__ Wb,
    const float* __restrict__ bias, void* __restrict__ outp, int mode)
{
    extern __shared__ char smem[];
    u32 sb = s2u(smem);
    int tid = threadIdx.x, lane = tid & 31, wid = tid >> 5;
    int m0 = blockIdx.y * 128, n0 = blockIdx.x * 256;
    int wm = (wid & 3) * 32, wn = (wid >> 2) * 64;

    const char* Abase = (const char*)Ab;
    const char* Wbase = (const char*)Wb;
    int arow = tid >> 2, acol = (tid & 3) * 64;
    int wrow = tid >> 1, wcol = (tid & 1) * 128;

    auto loadStage = [&](int c, int stg) {
        u32 base = sb + stg * PSTG;
        const char* asrc = Abase + ((size_t)(m0 + arow) * TRIP + c * 128) * 2 + acol;
        u32 adst = base + arow * SAP + acol;
#pragma unroll
        for (int i = 0; i < 4; i++) CPA16(adst + i * 16, asrc + i * 16);
        const char* wsrc = Wbase + ((size_t)(n0 + wrow) * TRIP + c * 128) * 2 + wcol;
        u32 wdst = base + 128 * SAP + wrow * SAP + wcol;
#pragma unroll
        for (int i = 0; i < 8; i++) CPA16(wdst + i * 16, wsrc + i * 16);
        CPCOMMIT();
    };

    float acc[2][8][4];
#pragma unroll
    for (int i = 0; i < 2; i++)
#pragma unroll
        for (int j = 0; j < 8; j++)
#pragma unroll
            for (int e = 0; e < 4; e++) acc[i][j][e] = 0.f;

    loadStage(0, 0);
    for (int c = 0; c < 8; c++) {
        CPWAIT(0);
        __syncthreads();
        if (c < 7) loadStage(c + 1, (c + 1) & 1);
        u32 abase = sb + (c & 1) * PSTG;
        u32 wbase = abase + 128 * SAP;
#pragma unroll
        for (int ks = 0; ks < 8; ks++) {
            u32 af[2][4], bf[4][4];
#pragma unroll
            for (int i = 0; i < 2; i++)
                ldmx4(af[i], addrA(abase, SAP, wm + i * 16, ks * 16, lane));
#pragma unroll
            for (int j = 0; j < 4; j++)
                ldmx4(bf[j], addrB16(wbase, SAP, wn + j * 16, ks * 16, lane));
#pragma unroll
            for (int i = 0; i < 2; i++)
#pragma unroll
                for (int j = 0; j < 4; j++) {
                    mma_fp(acc[i][2*j],     af[i], bf[j]);
                    mma_fp(acc[i][2*j + 1], af[i], bf[j] + 2);
                }
        }
    }

    // epilogue
    int rr = lane >> 2, cq = (lane & 3) * 2;
#pragma unroll
    for (int i = 0; i < 2; i++) {
#pragma unroll
        for (int h2 = 0; h2 < 2; h2++) {
            int m = m0 + wm + i * 16 + rr + h2 * 8;
            int s = m >> 2, b = m & 3;
#pragma unroll
            for (int j = 0; j < 8; j++) {
                int nn = wn + j * 8 + cq;            // 0..255, even
                int head = (n0 + nn) >> 6, d = nn & 63;
                float v0 = fmaxf(acc[i][j][h2 * 2]     + bias[n0 + nn], 0.f);
                float v1 = fmaxf(acc[i][j][h2 * 2 + 1] + bias[n0 + nn + 1], 0.f);
                int mo = (MODED == 0) ? 0 : mode;
                if (mo == 1 || mo == 2) {
                    if (mo == 1) { v0 *= 0.125f; v1 *= 0.125f; }
                    int p = (s << 5) + (d >> 1);
                    float cc = g_cos[p], sn = g_sin[p];
                    float e = v0 * cc - v1 * sn;
                    float o = v0 * sn + v1 * cc;
                    v0 = e; v1 = o;
                }
                if (mo == 0) {
                    *(float2*)&((float*)outp)[(size_t)m * F_DIM + n0 + nn] = make_float2(v0, v1);
                } else if (mo == 1 || mo == 2) {
                    int bh = b * NHEAD + head;
                    u32 w[2];
                    if (mo == 1) packA2h(v0, v1, w); else packB2h(v0, v1, w);
                    u32* dd = (u32*)((u16*)outp + ((size_t)bh * S_LEN + s) * TRIPQ + 2 * d);
                    dd[0] = w[0]; dd[1] = w[1];
                } else {   // V plain fp16 transposed [bh][d][s]
                    int bh = b * NHEAD + head;
                    u16* d0 = (u16*)outp + ((size_t)bh * HD + d) * S_LEN + s;
                    d0[0] = f2h(v0);
                    d0[S_LEN] = f2h(v1);
                }
            }
        }
    }
}

__global__ __launch_bounds__(512, 1) void projqkv_kernel(
    const u16* __restrict__ Ain, const u16* __restrict__ Wall,
    const float* __restrict__ bq, const float* __restrict__ bk,
    const float* __restrict__ bv,
    u16* __restrict__ oq, u16* __restrict__ ok, u16* __restrict__ ov)
{
    int sel = blockIdx.z;
    const u16* Ab = Ain + (size_t)sel * M_ROWS * TRIP;
    const u16* Wb = Wall + (size_t)sel * F_DIM * TRIP;
    const float* bias = (sel == 0) ? bq : (sel == 1) ? bk : bv;
    void* outp = (sel == 0) ? (void*)oq : (sel == 1) ? (void*)ok : (void*)ov;
    proj_body<-1>(Ab, Wb, bias, outp, sel + 1);
}

__global__ __launch_bounds__(512, 1) void projo_kernel(
    const u16* __restrict__ Ab, const u16* __restrict__ Wb,
    const float* __restrict__ bias, float* __restrict__ outp)
{
    proj_body<0>(Ab, Wb, bias, outp, 0);
}

// ---------------------------------------------------------------------------
// Flash attention (full fp16): CTA = 256 q x 1 head; 512 threads.
// QK^T 2-term fp16 (k'=128). PV: P fp16 from registers, V plain fp16.
// smem: Q 256x272 (69632) | 2 x (K 64x272 + V 64x144) = 122880
// ---------------------------------------------------------------------------
#define FSQ 272
#define VSP 144
#define QBYTES (256 * FSQ)
#define KSTG (64 * FSQ)
#define VSTG (64 * VSP)
#define FKV(stg) (QBYTES + (stg) * (KSTG + VSTG))
#define FLASH_SMEM (QBYTES + 2 * (KSTG + VSTG))   // 122880

__global__ __launch_bounds__(512, 1) void flash_kernel() {
    extern __shared__ char smem[];
    u32 sb = s2u(smem);
    int tid = threadIdx.x, lane = tid & 31, wid = tid >> 5;
    int q0 = blockIdx.x * 256, bh = blockIdx.y;
    int wm = wid * 16;

    // Q load (2-term fp16 A-pattern, pre-scaled): 256 rows x 256B
    {
        int r = tid >> 1, c0 = (tid & 1) * 128;
        const char* src = (const char*)g_Qb + ((size_t)(bh * S_LEN) + q0 + r) * (TRIPQ * 2) + c0;
        u32 dst = sb + r * FSQ + c0;
#pragma unroll
        for (int i = 0; i < 8; i++) CPA16(dst + i * 16, src + i * 16);
        CPCOMMIT();
    }
    int kr = tid >> 3, kc = (tid & 7) * 32;   // K: 64 rows x 256B, 8 thr/row
    int vc = (tid & 7) * 16;                  // V: 64 rows x 128B
    auto loadKV = [&](int kb, int stg) {
        u32 base = sb + FKV(stg);
        const char* ksrc = (const char*)g_Kb + ((size_t)(bh * S_LEN) + kb * 64 + kr) * (TRIPQ * 2) + kc;
#pragma unroll
        for (int i = 0; i < 2; i++) CPA16(base + kr * FSQ + kc + i * 16, ksrc + i * 16);
        const char* vsrc = (const char*)g_Vb + (((size_t)(bh * HD) + kr) * S_LEN + kb * 64) * 2 + vc;
        CPA16(base + KSTG + kr * VSP + vc, vsrc);
        CPCOMMIT();
    };

    loadKV(0, 0);
    CPWAIT(0);
    __syncthreads();

    u32 qf[8][4];
#pragma unroll
    for (int ks = 0; ks < 8; ks++)
        ldmx4(qf[ks], addrA(sb, FSQ, wm, ks * 16, lane));

    float mi[2] = {-3.0e38f, -3.0e38f}, li[2] = {0.f, 0.f};
    float oacc[8][4];
#pragma unroll
    for (int j = 0; j < 8; j++)
#pragma unroll
        for (int e = 0; e < 4; e++) oacc[j][e] = 0.f;

    for (int kb = 0; kb < 32; kb++) {
        if (kb > 0) { CPWAIT(0); __syncthreads(); }
        if (kb < 31) loadKV(kb + 1, (kb + 1) & 1);
        u32 kbase = sb + FKV(kb & 1);
        u32 vbase = kbase + KSTG;

        // S = Q K^T (2-term fp16)
        float sacc[8][4];
#pragma unroll
        for (int j = 0; j < 8; j++)
#pragma unroll
            for (int e = 0; e < 4; e++) sacc[j][e] = 0.f;
#pragma unroll
        for (int ks = 0; ks < 8; ks++) {
#pragma unroll
            for (int j16 = 0; j16 < 4; j16++) {
                u32 bf[4];
                ldmx4(bf, addrB16(kbase, FSQ, j16 * 16, ks * 16, lane));
                mma_fp(sacc[2*j16],     qf[ks], bf);
                mma_fp(sacc[2*j16 + 1], qf[ks], bf + 2);
            }
        }

        // online softmax; sacc becomes P in-place
#pragma unroll
        for (int h2 = 0; h2 < 2; h2++) {
            float rmax = -3.0e38f;
#pragma unroll
            for (int j = 0; j < 8; j++)
                rmax = fmaxf(rmax, fmaxf(sacc[j][h2 * 2], sacc[j][h2 * 2 + 1]));
            rmax = fmaxf(rmax, __shfl_xor_sync(0xffffffffu, rmax, 1));
            rmax = fmaxf(rmax, __shfl_xor_sync(0xffffffffu, rmax, 2));
            float mnew = fmaxf(mi[h2], rmax);
            float alpha = __expf(mi[h2] - mnew);
            mi[h2] = mnew;
            float rsum = 0.f;
#pragma unroll
            for (int j = 0; j < 8; j++) {
                float p0 = __expf(sacc[j][h2 * 2] - mnew);
                float p1 = __expf(sacc[j][h2 * 2 + 1] - mnew);
                sacc[j][h2 * 2] = p0; sacc[j][h2 * 2 + 1] = p1;
                rsum += p0 + p1;
            }
            rsum += __shfl_xor_sync(0xffffffffu, rsum, 1);
            rsum += __shfl_xor_sync(0xffffffffu, rsum, 2);
            li[h2] = li[h2] * alpha + rsum;
#pragma unroll
            for (int j = 0; j < 8; j++) {
                oacc[j][h2 * 2] *= alpha; oacc[j][h2 * 2 + 1] *= alpha;
            }
        }

        // O += P V : P fp16 A-frags packed straight from registers
#pragma unroll
        for (int ks = 0; ks < 4; ks++) {
            u32 pf[4];
            pf[0] = pk2h(sacc[2*ks][0],     sacc[2*ks][1]);
            pf[1] = pk2h(sacc[2*ks][2],     sacc[2*ks][3]);
            pf[2] = pk2h(sacc[2*ks + 1][0], sacc[2*ks + 1][1]);
            pf[3] = pk2h(sacc[2*ks + 1][2], sacc[2*ks + 1][3]);
#pragma unroll
            for (int j16 = 0; j16 < 4; j16++) {
                u32 bf[4];
                ldmx4(bf, addrB16(vbase, VSP, j16 * 16, ks * 16, lane));
                mma_fp(oacc[2*j16],     pf, bf);
                mma_fp(oacc[2*j16 + 1], pf, bf + 2);
            }
        }
    }

    // epilogue: write 2-term fp16 A-pattern Y
    int b = bh >> 3, h = bh & 7;
    int rr = lane >> 2, cq = (lane & 3) * 2;
#pragma unroll
    for (int h2 = 0; h2 < 2; h2++) {
        int srow = q0 + wm + rr + h2 * 8;
        int m = srow * B_SZ + b;
        float inv = 1.0f / li[h2];
#pragma unroll
        for (int j = 0; j < 8; j++) {
            int f = h * HD + j * 8 + cq;
            u32 w[2];
            packA2h(oacc[j][h2 * 2] * inv, oacc[j][h2 * 2 + 1] * inv, w);
            u32* d = (u32*)(g_Yb + (size_t)m * TRIP + 2 * f);
            d[0] = w[0]; d[1] = w[1];
        }
    }
}

// ---------------------------------------------------------------------------
extern "C" void kernel_launch(void* const* d_in, const int* in_sizes, int n_in,
                              void* d_out, int out_size) {
    const float* q  = (const float*)d_in[0];
    const float* k  = (const float*)d_in[1];
    const float* v  = (const float*)d_in[2];
    const float* Wq = (const float*)d_in[3];
    const float* bq = (const float*)d_in[4];
    const float* Wk = (const float*)d_in[5];
    const float* bk = (const float*)d_in[6];
    const float* Wv = (const float*)d_in[7];
    const float* bv = (const float*)d_in[8];
    const float* Wo = (const float*)d_in[9];
    const float* bo = (const float*)d_in[10];

    u16 *pIn, *pW, *pQ, *pK, *pV, *pY;
    cudaGetSymbolAddress((void**)&pIn, g_inb);
    cudaGetSymbolAddress((void**)&pW,  g_Wb);
    cudaGetSymbolAddress((void**)&pQ,  g_Qb);
    cudaGetSymbolAddress((void**)&pK,  g_Kb);
    cudaGetSymbolAddress((void**)&pV,  g_Vb);
    cudaGetSymbolAddress((void**)&pY,  g_Yb);

    cudaFuncSetAttribute(projqkv_kernel, cudaFuncAttributeMaxDynamicSharedMemorySize, PROJ_SMEM);
    cudaFuncSetAttribute(projo_kernel,   cudaFuncAttributeMaxDynamicSharedMemorySize, PROJ_SMEM);
    cudaFuncSetAttribute(flash_kernel,   cudaFuncAttributeMaxDynamicSharedMemorySize, FLASH_SMEM);

    rope_table_kernel<<<256, 256>>>();

    const int nIn8 = M_ROWS * F_DIM / 8;
    const int nW8  = F_DIM * F_DIM / 8;
    conv_in_kernel<<<dim3(nIn8 / 256, 3), 256>>>(q, k, v, pIn, nIn8);
    conv_w_kernel<<<dim3(nW8 / 256, 4), 256>>>(Wq, Wk, Wv, Wo, pW, nW8);

    dim3 pg(F_DIM / 256, M_ROWS / 128, 3);   // (2, 64, 3)
    projqkv_kernel<<<pg, 512, PROJ_SMEM>>>(pIn, pW, bq, bk, bv, pQ, pK, pV);

    flash_kernel<<<dim3(S_LEN / 256, NB), 512, FLASH_SMEM>>>();

    projo_kernel<<<dim3(F_DIM / 256, M_ROWS / 128), 512, PROJ_SMEM>>>(
        pY, pW + (size_t)3 * F_DIM * TRIP, bo, (float*)d_out);
}